// round 10
// baseline (speedup 1.0000x reference)
#include <cuda_runtime.h>
#include <cuda_fp16.h>
#include <cstdint>
#include <cstddef>

// ---------------- problem dims (fixed) ----------------
#define N_B    64
#define T_DIM  64
#define TM1    63
#define DX     16
#define DU     8
#define H_DIM  256
#define L_DIM  128
#define K_NETS 64
#define MX     (N_B * T_DIM)   // 4096
#define MU     (N_B * TM1)     // 4032
#define KP1    32
#define NGRP   16              // split-K net groups for phisum GEMM
#define KGRP   (K_NETS / NGRP * H_DIM)   // 1024

// ---------------- scratch (device globals) ----------------
__device__ __half g_xnhi[MX * KP1];
__device__ __half g_xnlo[MX * KP1];
__device__ __half g_unhi[MU * KP1];
__device__ __half g_unlo[MU * KP1];
__device__ float g_b1ex[K_NETS * H_DIM];
__device__ float g_b1eu[K_NETS * H_DIM];
__device__ __half g_w1xh[K_NETS * H_DIM * KP1];
__device__ __half g_w1xl[K_NETS * H_DIM * KP1];
__device__ __half g_w1uh[K_NETS * H_DIM * KP1];
__device__ __half g_w1ul[K_NETS * H_DIM * KP1];
__device__ __half g_h1[(size_t)K_NETS * MX * H_DIM];
__device__ __half g_h2[(size_t)K_NETS * MX * H_DIM];     // x: [m][net][d]; u: [net][m][d]
__device__ __half g_w2xt_hi[(size_t)K_NETS * H_DIM * H_DIM];
__device__ __half g_w2xt_lo[(size_t)K_NETS * H_DIM * H_DIM];
__device__ __half g_w3xt_hi[(size_t)K_NETS * L_DIM * H_DIM];  // x: cat [n][net][d]
__device__ __half g_w3xt_lo[(size_t)K_NETS * L_DIM * H_DIM];
__device__ __half g_w2ut_hi[(size_t)K_NETS * H_DIM * H_DIM];
__device__ __half g_w2ut_lo[(size_t)K_NETS * H_DIM * H_DIM];
__device__ __half g_w3ut_hi[(size_t)K_NETS * L_DIM * H_DIM];  // u: [net][n][d]
__device__ __half g_w3ut_lo[(size_t)K_NETS * L_DIM * H_DIM];
__device__ float g_psi[(size_t)MU * K_NETS * L_DIM];     // [bt][net][L]
__device__ float g_psi0[K_NETS * L_DIM];
__device__ float g_phi0[N_B * K_NETS * L_DIM];           // per-net phi at t=0: [b][net][L]
__device__ float g_phisum_part[NGRP * MX * L_DIM];
__device__ float g_phisum[MX * L_DIM];
__device__ float g_predsum2[2 * N_B * TM1 * L_DIM];

// ---------------- BN + fp16 hi/lo split ----------------
__global__ void bn_split_kernel(const float* __restrict__ x,
                                __half* __restrict__ Ahi, __half* __restrict__ Alo,
                                int M, int D) {
    int d = blockIdx.x;
    int tid = threadIdx.x;
    if (d >= D) {
        for (int m = tid; m < M; m += 256) {
            Ahi[(size_t)m * KP1 + d] = __float2half(0.f);
            Alo[(size_t)m * KP1 + d] = __float2half(0.f);
        }
        return;
    }
    __shared__ float r1[256], r2[256];
    float s = 0.f, s2 = 0.f;
    for (int m = tid; m < M; m += 256) {
        float v = x[(size_t)m * D + d];
        s += v; s2 += v * v;
    }
    r1[tid] = s; r2[tid] = s2;
    __syncthreads();
    for (int o = 128; o > 0; o >>= 1) {
        if (tid < o) { r1[tid] += r1[tid + o]; r2[tid] += r2[tid + o]; }
        __syncthreads();
    }
    float mu = r1[0] / M;
    float var = r2[0] / M - mu * mu;
    float rstd = rsqrtf(var + 1e-5f);
    for (int m = tid; m < M; m += 256) {
        float v = (x[(size_t)m * D + d] - mu) * rstd;
        __half h = __float2half(v);
        Ahi[(size_t)m * KP1 + d] = h;
        Alo[(size_t)m * KP1 + d] = __float2half(v - __half2float(h));
    }
}

// ---------------- fold BN affine into layer-1, transpose, split ----------------
__global__ void prep_w1_split_kernel(const float* __restrict__ g, const float* __restrict__ be,
                                     const float* __restrict__ W1, const float* __restrict__ b1,
                                     __half* __restrict__ Thi, __half* __restrict__ Tlo,
                                     float* __restrict__ beff, int D) {
    int k = blockIdx.x;
    int h = threadIdx.x;
    float bacc = b1[k * H_DIM + h];
    for (int d = 0; d < KP1; d++) {
        float v = 0.f;
        if (d < D) {
            float w = W1[((size_t)k * D + d) * H_DIM + h];
            v = g[k * D + d] * w;
            bacc += be[k * D + d] * w;
        }
        __half hi = __float2half(v);
        size_t o = ((size_t)k * H_DIM + h) * KP1 + d;
        Thi[o] = hi;
        Tlo[o] = __float2half(v - __half2float(hi));
    }
    beff[k * H_DIM + h] = bacc;
}

// ---------------- W2 + W3 transpose + split; W3 gets scale folded in ----------------
// cat3=1: W3 out [n][net][d] (concat layout for phisum GEMM); cat3=0: [net][n][d]
__global__ void transpose_split2_kernel(const float* __restrict__ W2,
                                        __half* __restrict__ T2h, __half* __restrict__ T2l,
                                        const float* __restrict__ W3,
                                        __half* __restrict__ T3h, __half* __restrict__ T3l,
                                        const float* __restrict__ scale3, int cat3) {
    __shared__ float tile[32][33];
    int k = blockIdx.y;
    int idx = blockIdx.x;
    if (idx < 64) {
        const float* W = W2 + (size_t)k * H_DIM * H_DIM;
        int kk0 = (idx >> 3) * 32, n0 = (idx & 7) * 32;
        for (int r = threadIdx.y; r < 32; r += 8)
            tile[r][threadIdx.x] = W[(size_t)(kk0 + r) * H_DIM + n0 + threadIdx.x];
        __syncthreads();
        for (int r = threadIdx.y; r < 32; r += 8) {
            int n = n0 + r, kk = kk0 + threadIdx.x;
            float v = tile[threadIdx.x][r];
            __half h = __float2half(v);
            size_t o = ((size_t)k * H_DIM + n) * H_DIM + kk;
            T2h[o] = h;
            T2l[o] = __float2half(v - __half2float(h));
        }
    } else {
        idx -= 64;
        const float* W = W3 + (size_t)k * H_DIM * L_DIM;
        int kk0 = (idx >> 2) * 32, n0 = (idx & 3) * 32;
        for (int r = threadIdx.y; r < 32; r += 8)
            tile[r][threadIdx.x] = W[(size_t)(kk0 + r) * L_DIM + n0 + threadIdx.x];
        __syncthreads();
        for (int r = threadIdx.y; r < 32; r += 8) {
            int n = n0 + r, kk = kk0 + threadIdx.x;
            float v = tile[threadIdx.x][r] * scale3[k * L_DIM + n];
            __half h = __float2half(v);
            size_t o = cat3 ? ((size_t)n * K_NETS + k) * H_DIM + kk
                            : ((size_t)k * L_DIM + n) * H_DIM + kk;
            T3h[o] = h;
            T3l[o] = __float2half(v - __half2float(h));
        }
    }
}

// ================= streaming HMMA batched GEMM, 256m x 128n, 512 threads =================
#define A_STRIDE 40
#define A_PLANE  (256 * A_STRIDE)     // halves
#define B_PLANE  (128 * A_STRIDE)     // halves

__device__ __forceinline__ void cp16(void* dst, const void* src, bool pred) {
    uint32_t d = (uint32_t)__cvta_generic_to_shared(dst);
    int n = pred ? 16 : 0;
    asm volatile("cp.async.cg.shared.global [%0], [%1], 16, %2;" :: "r"(d), "l"(src), "r"(n));
}
#define CP_COMMIT() asm volatile("cp.async.commit_group;")
#define CP_WAIT(N)  asm volatile("cp.async.wait_group %0;" :: "n"(N))

__device__ __forceinline__ void ldsm_x4(uint32_t* r, const void* p) {
    uint32_t a = (uint32_t)__cvta_generic_to_shared(p);
    asm volatile("ldmatrix.sync.aligned.m8n8.x4.shared.b16 {%0,%1,%2,%3}, [%4];"
                 : "=r"(r[0]), "=r"(r[1]), "=r"(r[2]), "=r"(r[3]) : "r"(a));
}
#define MMA16816(d, a, b0, b1) \
    asm volatile("mma.sync.aligned.m16n8k16.row.col.f32.f16.f16.f32 " \
                 "{%0,%1,%2,%3},{%4,%5,%6,%7},{%8,%9},{%0,%1,%2,%3};" \
                 : "+f"((d)[0]), "+f"((d)[1]), "+f"((d)[2]), "+f"((d)[3]) \
                 : "r"((a)[0]), "r"((a)[1]), "r"((a)[2]), "r"((a)[3]), \
                   "r"(b0), "r"(b1))

template <bool ASPLIT>
__global__ void __launch_bounds__(512, 2)
hmma_gemm_kernel(const __half* __restrict__ Ahi, const __half* __restrict__ Alo,
                 size_t strideA, int lda, int KdPad,
                 const __half* __restrict__ Bhi, const __half* __restrict__ Blo,
                 size_t strideB, int ldb,
                 const float* __restrict__ bias,
                 float* __restrict__ Cf, __half* __restrict__ Ch, size_t strideC,
                 int Mrows, int Nfull, int leaky, int tposeF) {
    extern __shared__ char smem[];
    constexpr int STAGE_H = (ASPLIT ? 2 : 1) * A_PLANE + 2 * B_PLANE;  // halves

    int tid = threadIdx.x;
    int lane = tid & 31, wid = tid >> 5;
    int wm = wid >> 1, wn = wid & 1;               // 8 x 2 warp grid
    int z = blockIdx.z;
    int n0 = blockIdx.y * 128;
    int m0 = blockIdx.x * 256;

    const __half* Ah = Ahi + strideA * z;
    const __half* Al = ASPLIT ? (Alo + strideA * z) : nullptr;
    const __half* Bh = Bhi + strideB * z + (size_t)n0 * ldb;
    const __half* Bl = Blo + strideB * z + (size_t)n0 * ldb;

    int rowA = tid >> 1;                 // 0..255
    int kk16 = (tid & 1) * 16;
    int soffA = rowA * A_STRIDE + kk16;
    int rowB = (tid & 255) >> 1;         // 0..127 (tid<256 loads B)
    int soffB = rowB * A_STRIDE + kk16;

    int nk = KdPad >> 5;

    auto load_stage = [&](int s, int c) {
        __half* base = reinterpret_cast<__half*>(smem) + s * STAGE_H;
        int gm = m0 + rowA;
        bool aOk = gm < Mrows;
        const __half* pa = Ah + (size_t)gm * lda + c * 32 + kk16;
        cp16(base + soffA,     pa,     aOk);
        cp16(base + soffA + 8, pa + 8, aOk);
        if (ASPLIT) {
            const __half* pl = Al + (size_t)gm * lda + c * 32 + kk16;
            cp16(base + A_PLANE + soffA,     pl,     aOk);
            cp16(base + A_PLANE + soffA + 8, pl + 8, aOk);
        }
        if (tid < 256) {
            __half* bb = base + (ASPLIT ? 2 : 1) * A_PLANE;
            const __half* pb = Bh + (size_t)rowB * ldb + c * 32 + kk16;
            cp16(bb + soffB,     pb,     true);
            cp16(bb + soffB + 8, pb + 8, true);
            const __half* pbl = Bl + (size_t)rowB * ldb + c * 32 + kk16;
            cp16(bb + B_PLANE + soffB,     pbl,     true);
            cp16(bb + B_PLANE + soffB + 8, pbl + 8, true);
        }
        CP_COMMIT();
    };

    float acc[2][8][4];
#pragma unroll
    for (int mi = 0; mi < 2; mi++)
#pragma unroll
        for (int ni = 0; ni < 8; ni++)
#pragma unroll
            for (int i = 0; i < 4; i++) acc[mi][ni][i] = 0.f;

    int aRow = wm * 32 + (lane & 15);
    int aCol = (lane >> 4) * 8;
    int bRow = wn * 64 + (lane >> 4) * 8 + (lane & 7);
    int bCol = ((lane >> 3) & 1) * 8;
    int g = lane >> 2, t = lane & 3;

    load_stage(0, 0);

    for (int c = 0; c < nk; c++) {
        int s = (nk == 1) ? 0 : (c & 1);
        if (c + 1 < nk) {
            load_stage(s ^ 1, c + 1);
            CP_WAIT(1);
        } else {
            CP_WAIT(0);
        }
        __syncthreads();

        const __half* base = reinterpret_cast<const __half*>(smem) + s * STAGE_H;
        const __half* pAh = base;
        const __half* pAl = base + A_PLANE;
        const __half* pBh = base + (ASPLIT ? 2 : 1) * A_PLANE;
        const __half* pBl = pBh + B_PLANE;

#pragma unroll
        for (int ks = 0; ks < 2; ks++) {
            uint32_t ah[2][4], al[2][4];
#pragma unroll
            for (int mi = 0; mi < 2; mi++) {
                ldsm_x4(ah[mi], pAh + (aRow + mi * 16) * A_STRIDE + ks * 16 + aCol);
                if (ASPLIT)
                    ldsm_x4(al[mi], pAl + (aRow + mi * 16) * A_STRIDE + ks * 16 + aCol);
            }
#pragma unroll
            for (int q = 0; q < 4; q++) {
                uint32_t rh[4], rl[4];
                ldsm_x4(rh, pBh + (bRow + q * 16) * A_STRIDE + ks * 16 + bCol);
                ldsm_x4(rl, pBl + (bRow + q * 16) * A_STRIDE + ks * 16 + bCol);
#pragma unroll
                for (int p = 0; p < 2; p++) {
                    int ni = 2 * q + p;
#pragma unroll
                    for (int mi = 0; mi < 2; mi++) {
                        MMA16816(acc[mi][ni], ah[mi], rh[2 * p], rh[2 * p + 1]);
                        MMA16816(acc[mi][ni], ah[mi], rl[2 * p], rl[2 * p + 1]);
                        if (ASPLIT)
                            MMA16816(acc[mi][ni], al[mi], rh[2 * p], rh[2 * p + 1]);
                    }
                }
            }
        }
        __syncthreads();
    }

    // ---- epilogue ----
#pragma unroll
    for (int mi = 0; mi < 2; mi++) {
#pragma unroll
        for (int ni = 0; ni < 8; ni++) {
            int col = n0 + wn * 64 + ni * 8 + 2 * t;
            float b0 = 0.f, b1v = 0.f;
            if (bias) {
                b0 = bias[(size_t)z * Nfull + col];
                b1v = bias[(size_t)z * Nfull + col + 1];
            }
#pragma unroll
            for (int h = 0; h < 2; h++) {
                int row = m0 + wm * 32 + mi * 16 + g + h * 8;
                if (row >= Mrows) continue;
                float v0 = acc[mi][ni][2 * h] + b0;
                float v1 = acc[mi][ni][2 * h + 1] + b1v;
                if (leaky) {
                    v0 = v0 > 0.f ? v0 : 0.01f * v0;
                    v1 = v1 > 0.f ? v1 : 0.01f * v1;
                }
                size_t o = tposeF
                    ? ((size_t)row * K_NETS + z) * Nfull + col
                    : strideC * z + (size_t)row * Nfull + col;
                if (Cf) {
                    *reinterpret_cast<float2*>(&Cf[o]) = make_float2(v0, v1);
                } else {
                    *reinterpret_cast<__half2*>(&Ch[o]) = __floats2half2_rn(v0, v1);
                }
            }
        }
    }
}

#define SMEM_T  ((2 * A_PLANE + 2 * B_PLANE) * 2)          // ASPLIT=true, 1 stage: 61440
#define SMEM_F  (2 * (A_PLANE + 2 * B_PLANE) * 2)          // ASPLIT=false, 2 stages: 81920

// ---------------- phi0: per-net phi at t=0, from h2x + scale-folded W3cat ----------------
#define W3P 260   // padded d-stride (halves); 130 mod 32 = 2 -> 2-way LDS conflict max
__global__ void phi0_kernel(const __half* __restrict__ h2x,
                            const __half* __restrict__ w3h, const __half* __restrict__ w3l,
                            float* __restrict__ phi0) {
    extern __shared__ __half wsm[];
    __half* wh = wsm;
    __half* wl = wsm + 128 * W3P;
    __shared__ float hrow[H_DIM];
    __shared__ float partial[256];
    int j = blockIdx.x, bg = blockIdx.y;
    int tid = threadIdx.x;
    // load W3cat rows for net j: [128 n][256 d], uint2 granularity
    for (int i = tid; i < 128 * (H_DIM / 4); i += 256) {
        int n = i >> 6, d4 = (i & 63) * 4;
        *reinterpret_cast<uint2*>(wh + n * W3P + d4) =
            *reinterpret_cast<const uint2*>(w3h + ((size_t)n * K_NETS + j) * H_DIM + d4);
        *reinterpret_cast<uint2*>(wl + n * W3P + d4) =
            *reinterpret_cast<const uint2*>(w3l + ((size_t)n * K_NETS + j) * H_DIM + d4);
    }
    __syncthreads();
    for (int bi = 0; bi < N_B / 4; bi++) {
        int b = bg * (N_B / 4) + bi;
        hrow[tid] = __half2float(h2x[((size_t)(b * T_DIM) * K_NETS + j) * H_DIM + tid]);
        __syncthreads();
        int n = tid & 127, hh = tid >> 7;
        const __half* whn = wh + n * W3P + hh * 128;
        const __half* wln = wl + n * W3P + hh * 128;
        const float* hr = hrow + hh * 128;
        float s = 0.f;
#pragma unroll 8
        for (int d = 0; d < 128; d++)
            s += hr[d] * (__half2float(whn[d]) + __half2float(wln[d]));
        partial[tid] = s;
        __syncthreads();
        if (tid < 128)
            phi0[((size_t)b * K_NETS + j) * L_DIM + tid] = partial[tid] + partial[tid + 128];
        __syncthreads();
    }
}

// ---------------- reduce split-K partials into phisum ----------------
__global__ void reduce16_kernel(const float* __restrict__ part, float* __restrict__ out) {
    int m = blockIdx.x;
    int l = threadIdx.x;
    float s = 0.f;
#pragma unroll
    for (int gp = 0; gp < NGRP; gp++)
        s += part[(size_t)gp * MX * L_DIM + (size_t)m * L_DIM + l];
    out[(size_t)m * L_DIM + l] = s;
}

// ---------------- psi(0) exact fp32 ----------------
__global__ void psi0_kernel(const float* __restrict__ b1eff, const float* __restrict__ W2,
                            const float* __restrict__ b2, const float* __restrict__ W3,
                            const float* __restrict__ scale, float* __restrict__ psi0) {
    int k = blockIdx.x;
    int t = threadIdx.x;
    __shared__ float h1[H_DIM], h2[H_DIM];
    float v = b1eff[k * H_DIM + t];
    h1[t] = v > 0.f ? v : 0.01f * v;
    __syncthreads();
    float a = b2[k * H_DIM + t];
    for (int d = 0; d < H_DIM; d++)
        a += h1[d] * W2[((size_t)k * H_DIM + d) * H_DIM + t];
    h2[t] = a > 0.f ? a : 0.01f * a;
    __syncthreads();
    if (t < L_DIM) {
        float s = 0.f;
        for (int d = 0; d < H_DIM; d++)
            s += h2[d] * W3[((size_t)k * H_DIM + d) * L_DIM + t];
        psi0[k * L_DIM + t] = s * scale[k * L_DIM + t];
    }
}

// ---------------- sequential Koopman scan: 2 blocks per batch ----------------
__global__ void __launch_bounds__(256)
scan_kernel(const float* __restrict__ phi0,  // [b][net][L]
            const float* __restrict__ psi,   // [bt][net][L]
            const float* __restrict__ psi0,
            const float* __restrict__ reL, const float* __restrict__ imL,
            float* __restrict__ predsum2) {
    int bid = blockIdx.x;
    int b = bid >> 1;
    int sel = bid & 1;
    int j0 = sel * 32;
    int tid = threadIdx.x;
    __shared__ float ps[32 * L_DIM];
    __shared__ float rsh[K_NETS], ish[K_NETS];
    if (tid < K_NETS) { rsh[tid] = reL[tid]; ish[tid] = imL[tid]; }

    float px[8], py[8], rj[8], ij[8], u0x[8], u0y[8];
    const float* phiB = phi0 + ((size_t)b * K_NETS + j0) * L_DIM;
    const float* psi0B = psi0 + (size_t)j0 * L_DIM;
#pragma unroll
    for (int q = 0; q < 8; q++) {
        int e = q * 256 + tid;
        float2 v = *reinterpret_cast<const float2*>(&phiB[e * 2]);
        px[q] = v.x; py[q] = v.y;
        float2 zz = *reinterpret_cast<const float2*>(&psi0B[e * 2]);
        u0x[q] = zz.x; u0y[q] = zz.y;
    }
    __syncthreads();
#pragma unroll
    for (int q = 0; q < 8; q++) {
        int j = j0 + ((q * 256 + tid) >> 6);
        rj[q] = rsh[j]; ij[q] = ish[j];
    }

    for (int t = 0; t < TM1; t++) {
        const float* psiT = psi + ((size_t)(b * TM1 + t) * K_NETS + j0) * L_DIM;
#pragma unroll
        for (int q = 0; q < 8; q++) {
            int e = q * 256 + tid;
            float2 u = *reinterpret_cast<const float2*>(&psiT[e * 2]);
            float vx = px[q] + u.x - u0x[q];
            float vy = py[q] + u.y - u0y[q];
            px[q] = vx * rj[q] - vy * ij[q];
            py[q] = vx * ij[q] + vy * rj[q];
            ps[e * 2]     = px[q];
            ps[e * 2 + 1] = py[q];
        }
        __syncthreads();
        if (tid < L_DIM) {
            float s = 0.f;
#pragma unroll 8
            for (int j = 0; j < 32; j++) s += ps[j * L_DIM + tid];
            predsum2[(((size_t)sel * N_B + b) * TM1 + t) * L_DIM + tid] = s;
        }
        __syncthreads();
    }
}

// ---------------- decode ----------------
__global__ void decode_kernel(const float* __restrict__ phisum,
                              const float* __restrict__ predsum2,
                              const float* __restrict__ C_W,
                              float* __restrict__ out) {
    __shared__ float Cs[DX * L_DIM];
    __shared__ float rowY[L_DIM], rowP[L_DIM];
    int bt = blockIdx.x;
    int b = bt / TM1, t = bt % TM1;
    int tid = threadIdx.x;
    for (int i = tid; i < DX * L_DIM; i += 256) Cs[i] = C_W[i];
    if (tid < L_DIM)
        rowY[tid] = phisum[((size_t)(b * T_DIM + t + 1)) * L_DIM + tid];
    else {
        int l = tid - L_DIM;
        rowP[l] = predsum2[(size_t)bt * L_DIM + l]
                + predsum2[((size_t)N_B * TM1 + bt) * L_DIM + l];
    }
    __syncthreads();
    if (tid < 2 * DX) {
        int sel = tid >> 4, d = tid & 15;
        const float* row = sel ? rowP : rowY;
        float s = 0.f;
        for (int l = 0; l < L_DIM; l++) s += row[l] * Cs[d * L_DIM + l];
        out[(size_t)sel * N_B * TM1 * DX + (size_t)bt * DX + d] = s;
    }
}

// ---------------- launcher ----------------
extern "C" void kernel_launch(void* const* d_in, const int* in_sizes, int n_in,
                              void* d_out, int out_size) {
    const float* xs      = (const float*)d_in[0];
    const float* us      = (const float*)d_in[1];
    const float* x_gamma = (const float*)d_in[2];
    const float* x_beta  = (const float*)d_in[3];
    const float* xW1     = (const float*)d_in[4];
    const float* xb1     = (const float*)d_in[5];
    const float* xW2     = (const float*)d_in[6];
    const float* xb2     = (const float*)d_in[7];
    const float* xW3     = (const float*)d_in[8];
    const float* x_scale = (const float*)d_in[9];
    const float* u_gamma = (const float*)d_in[10];
    const float* u_beta  = (const float*)d_in[11];
    const float* uW1     = (const float*)d_in[12];
    const float* ub1     = (const float*)d_in[13];
    const float* uW2     = (const float*)d_in[14];
    const float* ub2     = (const float*)d_in[15];
    const float* uW3     = (const float*)d_in[16];
    const float* u_scale = (const float*)d_in[17];
    const float* reL     = (const float*)d_in[18];
    const float* imL     = (const float*)d_in[19];
    const float* C_W     = (const float*)d_in[20];
    float* out = (float*)d_out;

    float *b1ex, *b1eu, *psi, *psi0, *phi0, *phisum_part, *phisum, *predsum2;
    __half *xnhi, *xnlo, *unhi, *unlo, *w1xh, *w1xl, *w1uh, *w1ul;
    __half *h1, *h2;
    __half *w2xh, *w2xl, *w3xh, *w3xl, *w2uh, *w2ul, *w3uh, *w3ul;
    cudaGetSymbolAddress((void**)&xnhi, g_xnhi);
    cudaGetSymbolAddress((void**)&xnlo, g_xnlo);
    cudaGetSymbolAddress((void**)&unhi, g_unhi);
    cudaGetSymbolAddress((void**)&unlo, g_unlo);
    cudaGetSymbolAddress((void**)&b1ex, g_b1ex);
    cudaGetSymbolAddress((void**)&b1eu, g_b1eu);
    cudaGetSymbolAddress((void**)&w1xh, g_w1xh);
    cudaGetSymbolAddress((void**)&w1xl, g_w1xl);
    cudaGetSymbolAddress((void**)&w1uh, g_w1uh);
    cudaGetSymbolAddress((void**)&w1ul, g_w1ul);
    cudaGetSymbolAddress((void**)&h1, g_h1);
    cudaGetSymbolAddress((void**)&h2, g_h2);
    cudaGetSymbolAddress((void**)&w2xh, g_w2xt_hi);
    cudaGetSymbolAddress((void**)&w2xl, g_w2xt_lo);
    cudaGetSymbolAddress((void**)&w3xh, g_w3xt_hi);
    cudaGetSymbolAddress((void**)&w3xl, g_w3xt_lo);
    cudaGetSymbolAddress((void**)&w2uh, g_w2ut_hi);
    cudaGetSymbolAddress((void**)&w2ul, g_w2ut_lo);
    cudaGetSymbolAddress((void**)&w3uh, g_w3ut_hi);
    cudaGetSymbolAddress((void**)&w3ul, g_w3ut_lo);
    cudaGetSymbolAddress((void**)&psi, g_psi);
    cudaGetSymbolAddress((void**)&psi0, g_psi0);
    cudaGetSymbolAddress((void**)&phi0, g_phi0);
    cudaGetSymbolAddress((void**)&phisum_part, g_phisum_part);
    cudaGetSymbolAddress((void**)&phisum, g_phisum);
    cudaGetSymbolAddress((void**)&predsum2, g_predsum2);

    cudaFuncSetAttribute((const void*)hmma_gemm_kernel<true>,
                         cudaFuncAttributeMaxDynamicSharedMemorySize, SMEM_T);
    cudaFuncSetAttribute((const void*)hmma_gemm_kernel<false>,
                         cudaFuncAttributeMaxDynamicSharedMemorySize, SMEM_F);
    cudaFuncSetAttribute((const void*)phi0_kernel,
                         cudaFuncAttributeMaxDynamicSharedMemorySize, 2 * 128 * W3P * 2);

    dim3 tb(32, 8);
    // ---- x path ----
    bn_split_kernel<<<KP1, 256>>>(xs, xnhi, xnlo, MX, DX);                          // 0
    prep_w1_split_kernel<<<K_NETS, H_DIM>>>(x_gamma, x_beta, xW1, xb1,
                                            w1xh, w1xl, b1ex, DX);                  // 1
    transpose_split2_kernel<<<dim3(96, K_NETS), tb>>>(
        xW2, w2xh, w2xl, xW3, w3xh, w3xl, x_scale, 1);                              // 2
    hmma_gemm_kernel<true><<<dim3(MX / 256, 2, K_NETS), 512, SMEM_T>>>(
        xnhi, xnlo, 0, KP1, KP1, w1xh, w1xl, (size_t)H_DIM * KP1, KP1,
        b1ex, nullptr, h1, (size_t)MX * H_DIM, MX, H_DIM, 1, 0);                    // 3: L1x
    bn_split_kernel<<<KP1, 256>>>(us, unhi, unlo, MU, DU);                          // 4
    hmma_gemm_kernel<false><<<dim3(MX / 256, 2, K_NETS), 512, SMEM_F>>>(
        h1, nullptr, (size_t)MX * H_DIM, H_DIM, H_DIM,
        w2xh, w2xl, (size_t)H_DIM * H_DIM, H_DIM,
        xb2, nullptr, h2, 0, MX, H_DIM, 1, 1);                                      // 5: L2x -> h2 [m][net][d]
    hmma_gemm_kernel<false><<<dim3(MX / 256, 1, NGRP), 512, SMEM_F>>>(
        h2, nullptr, (size_t)KGRP, K_NETS * H_DIM, KGRP,
        w3xh, w3xl, (size_t)KGRP, K_NETS * H_DIM,
        nullptr, phisum_part, nullptr, (size_t)MX * L_DIM, MX, L_DIM, 0, 0);        // 6: phisum split-K
    phi0_kernel<<<dim3(K_NETS, 4), 256, 2 * 128 * W3P * 2>>>(h2, w3xh, w3xl, phi0); // 7
    reduce16_kernel<<<MX, L_DIM>>>(phisum_part, phisum);                            // 8

    // ---- u path ----
    prep_w1_split_kernel<<<K_NETS, H_DIM>>>(u_gamma, u_beta, uW1, ub1,
                                            w1uh, w1ul, b1eu, DU);                  // 9
    transpose_split2_kernel<<<dim3(96, K_NETS), tb>>>(
        uW2, w2uh, w2ul, uW3, w3uh, w3ul, u_scale, 0);                              // 10
    hmma_gemm_kernel<true><<<dim3(16, 2, K_NETS), 512, SMEM_T>>>(
        unhi, unlo, 0, KP1, KP1, w1uh, w1ul, (size_t)H_DIM * KP1, KP1,
        b1eu, nullptr, h1, (size_t)MU * H_DIM, MU, H_DIM, 1, 0);                    // 11
    hmma_gemm_kernel<false><<<dim3(16, 2, K_NETS), 512, SMEM_F>>>(
        h1, nullptr, (size_t)MU * H_DIM, H_DIM, H_DIM,
        w2uh, w2ul, (size_t)H_DIM * H_DIM, H_DIM,
        ub2, nullptr, h2, (size_t)MU * H_DIM, MU, H_DIM, 1, 0);                     // 12
    hmma_gemm_kernel<false><<<dim3(16, 1, K_NETS), 512, SMEM_F>>>(
        h2, nullptr, (size_t)MU * H_DIM, H_DIM, H_DIM,
        w3uh, w3ul, (size_t)L_DIM * H_DIM, H_DIM,
        nullptr, psi, nullptr, 0, MU, L_DIM, 0, 1);                                 // 13: psi [bt][net][L]

    psi0_kernel<<<K_NETS, H_DIM>>>(b1eu, uW2, ub2, uW3, u_scale, psi0);             // 14
    scan_kernel<<<2 * N_B, 256>>>(phi0, psi, psi0, reL, imL, predsum2);             // 15
    decode_kernel<<<N_B * TM1, 256>>>(phisum, predsum2, C_W, out);                  // 16
}

// round 11
// speedup vs baseline: 1.5931x; 1.5931x over previous
#include <cuda_runtime.h>
#include <cuda_fp16.h>
#include <cstdint>
#include <cstddef>

// ---------------- problem dims (fixed) ----------------
#define N_B    64
#define T_DIM  64
#define TM1    63
#define DX     16
#define DU     8
#define H_DIM  256
#define L_DIM  128
#define K_NETS 64
#define MX     (N_B * T_DIM)   // 4096
#define MU     (N_B * TM1)     // 4032
#define KP1    32
#define NGRP   16              // split-K net groups for phisum GEMM
#define KGRP   (K_NETS / NGRP * H_DIM)   // 1024

// ---------------- scratch (device globals) ----------------
__device__ __half g_xnhi[MX * KP1];
__device__ __half g_xnlo[MX * KP1];
__device__ __half g_unhi[MU * KP1];
__device__ __half g_unlo[MU * KP1];
__device__ float g_b1ex[K_NETS * H_DIM];
__device__ float g_b1eu[K_NETS * H_DIM];
__device__ __half g_w1xh[K_NETS * H_DIM * KP1];
__device__ __half g_w1xl[K_NETS * H_DIM * KP1];
__device__ __half g_w1uh[K_NETS * H_DIM * KP1];
__device__ __half g_w1ul[K_NETS * H_DIM * KP1];
__device__ __half g_h1[(size_t)K_NETS * MX * H_DIM];
__device__ __half g_h2[(size_t)K_NETS * MX * H_DIM];     // x: [m][net][d]; u: [net][m][d]
__device__ __half g_w2xt_hi[(size_t)K_NETS * H_DIM * H_DIM];
__device__ __half g_w2xt_lo[(size_t)K_NETS * H_DIM * H_DIM];
__device__ __half g_w3xt_hi[(size_t)K_NETS * L_DIM * H_DIM];  // x: cat [n][net][d]
__device__ __half g_w3xt_lo[(size_t)K_NETS * L_DIM * H_DIM];
__device__ __half g_w2ut_hi[(size_t)K_NETS * H_DIM * H_DIM];
__device__ __half g_w2ut_lo[(size_t)K_NETS * H_DIM * H_DIM];
__device__ __half g_w3ut_hi[(size_t)K_NETS * L_DIM * H_DIM];  // u: [net][n][d]
__device__ __half g_w3ut_lo[(size_t)K_NETS * L_DIM * H_DIM];
__device__ float g_psi[(size_t)MU * K_NETS * L_DIM];     // [bt][net][L]
__device__ float g_psi0[K_NETS * L_DIM];
__device__ float g_phi0[N_B * K_NETS * L_DIM];           // per-net phi at t=0: [b][net][L]
__device__ float g_phisum_part[NGRP * MX * L_DIM];
__device__ float g_phisum[MX * L_DIM];
__device__ float g_predsum2[2 * N_B * TM1 * L_DIM];

// ---------------- BN + fp16 hi/lo split ----------------
__global__ void bn_split_kernel(const float* __restrict__ x,
                                __half* __restrict__ Ahi, __half* __restrict__ Alo,
                                int M, int D) {
    int d = blockIdx.x;
    int tid = threadIdx.x;
    if (d >= D) {
        for (int m = tid; m < M; m += 256) {
            Ahi[(size_t)m * KP1 + d] = __float2half(0.f);
            Alo[(size_t)m * KP1 + d] = __float2half(0.f);
        }
        return;
    }
    __shared__ float r1[256], r2[256];
    float s = 0.f, s2 = 0.f;
    for (int m = tid; m < M; m += 256) {
        float v = x[(size_t)m * D + d];
        s += v; s2 += v * v;
    }
    r1[tid] = s; r2[tid] = s2;
    __syncthreads();
    for (int o = 128; o > 0; o >>= 1) {
        if (tid < o) { r1[tid] += r1[tid + o]; r2[tid] += r2[tid + o]; }
        __syncthreads();
    }
    float mu = r1[0] / M;
    float var = r2[0] / M - mu * mu;
    float rstd = rsqrtf(var + 1e-5f);
    for (int m = tid; m < M; m += 256) {
        float v = (x[(size_t)m * D + d] - mu) * rstd;
        __half h = __float2half(v);
        Ahi[(size_t)m * KP1 + d] = h;
        Alo[(size_t)m * KP1 + d] = __float2half(v - __half2float(h));
    }
}

// ---------------- fold BN affine into layer-1, transpose, split ----------------
__global__ void prep_w1_split_kernel(const float* __restrict__ g, const float* __restrict__ be,
                                     const float* __restrict__ W1, const float* __restrict__ b1,
                                     __half* __restrict__ Thi, __half* __restrict__ Tlo,
                                     float* __restrict__ beff, int D) {
    int k = blockIdx.x;
    int h = threadIdx.x;
    float bacc = b1[k * H_DIM + h];
    for (int d = 0; d < KP1; d++) {
        float v = 0.f;
        if (d < D) {
            float w = W1[((size_t)k * D + d) * H_DIM + h];
            v = g[k * D + d] * w;
            bacc += be[k * D + d] * w;
        }
        __half hi = __float2half(v);
        size_t o = ((size_t)k * H_DIM + h) * KP1 + d;
        Thi[o] = hi;
        Tlo[o] = __float2half(v - __half2float(hi));
    }
    beff[k * H_DIM + h] = bacc;
}

// ---------------- W2 + W3 transpose + split; W3 gets scale folded in ----------------
// cat3=1: W3 out [n][net][d] (concat layout for phisum GEMM); cat3=0: [net][n][d]
__global__ void transpose_split2_kernel(const float* __restrict__ W2,
                                        __half* __restrict__ T2h, __half* __restrict__ T2l,
                                        const float* __restrict__ W3,
                                        __half* __restrict__ T3h, __half* __restrict__ T3l,
                                        const float* __restrict__ scale3, int cat3) {
    __shared__ float tile[32][33];
    int k = blockIdx.y;
    int idx = blockIdx.x;
    if (idx < 64) {
        const float* W = W2 + (size_t)k * H_DIM * H_DIM;
        int kk0 = (idx >> 3) * 32, n0 = (idx & 7) * 32;
        for (int r = threadIdx.y; r < 32; r += 8)
            tile[r][threadIdx.x] = W[(size_t)(kk0 + r) * H_DIM + n0 + threadIdx.x];
        __syncthreads();
        for (int r = threadIdx.y; r < 32; r += 8) {
            int n = n0 + r, kk = kk0 + threadIdx.x;
            float v = tile[threadIdx.x][r];
            __half h = __float2half(v);
            size_t o = ((size_t)k * H_DIM + n) * H_DIM + kk;
            T2h[o] = h;
            T2l[o] = __float2half(v - __half2float(h));
        }
    } else {
        idx -= 64;
        const float* W = W3 + (size_t)k * H_DIM * L_DIM;
        int kk0 = (idx >> 2) * 32, n0 = (idx & 3) * 32;
        for (int r = threadIdx.y; r < 32; r += 8)
            tile[r][threadIdx.x] = W[(size_t)(kk0 + r) * L_DIM + n0 + threadIdx.x];
        __syncthreads();
        for (int r = threadIdx.y; r < 32; r += 8) {
            int n = n0 + r, kk = kk0 + threadIdx.x;
            float v = tile[threadIdx.x][r] * scale3[k * L_DIM + n];
            __half h = __float2half(v);
            size_t o = cat3 ? ((size_t)n * K_NETS + k) * H_DIM + kk
                            : ((size_t)k * L_DIM + n) * H_DIM + kk;
            T3h[o] = h;
            T3l[o] = __float2half(v - __half2float(h));
        }
    }
}

// ================= streaming HMMA batched GEMM, 256m x 128n, 512 threads =================
#define A_STRIDE 40
#define A_PLANE  (256 * A_STRIDE)     // halves
#define B_PLANE  (128 * A_STRIDE)     // halves

__device__ __forceinline__ void cp16(void* dst, const void* src, bool pred) {
    uint32_t d = (uint32_t)__cvta_generic_to_shared(dst);
    int n = pred ? 16 : 0;
    asm volatile("cp.async.cg.shared.global [%0], [%1], 16, %2;" :: "r"(d), "l"(src), "r"(n));
}
#define CP_COMMIT() asm volatile("cp.async.commit_group;")
#define CP_WAIT(N)  asm volatile("cp.async.wait_group %0;" :: "n"(N))

__device__ __forceinline__ void ldsm_x4(uint32_t* r, const void* p) {
    uint32_t a = (uint32_t)__cvta_generic_to_shared(p);
    asm volatile("ldmatrix.sync.aligned.m8n8.x4.shared.b16 {%0,%1,%2,%3}, [%4];"
                 : "=r"(r[0]), "=r"(r[1]), "=r"(r[2]), "=r"(r[3]) : "r"(a));
}
#define MMA16816(d, a, b0, b1) \
    asm volatile("mma.sync.aligned.m16n8k16.row.col.f32.f16.f16.f32 " \
                 "{%0,%1,%2,%3},{%4,%5,%6,%7},{%8,%9},{%0,%1,%2,%3};" \
                 : "+f"((d)[0]), "+f"((d)[1]), "+f"((d)[2]), "+f"((d)[3]) \
                 : "r"((a)[0]), "r"((a)[1]), "r"((a)[2]), "r"((a)[3]), \
                   "r"(b0), "r"(b1))

template <bool ASPLIT>
__global__ void __launch_bounds__(512, 1)          // 1 CTA/SM: full 128 regs, no spills
hmma_gemm_kernel(const __half* __restrict__ Ahi, const __half* __restrict__ Alo,
                 size_t strideA, int lda, int KdPad,
                 const __half* __restrict__ Bhi, const __half* __restrict__ Blo,
                 size_t strideB, int ldb,
                 const float* __restrict__ bias,
                 float* __restrict__ Cf, __half* __restrict__ Ch, size_t strideC,
                 int Mrows, int Nfull, int leaky, int tposeF) {
    extern __shared__ char smem[];
    constexpr int STAGE_H = (ASPLIT ? 2 : 1) * A_PLANE + 2 * B_PLANE;  // halves

    int tid = threadIdx.x;
    int lane = tid & 31, wid = tid >> 5;
    int wm = wid >> 1, wn = wid & 1;               // 8 x 2 warp grid
    int z = blockIdx.z;
    int n0 = blockIdx.y * 128;
    int m0 = blockIdx.x * 256;

    const __half* Ah = Ahi + strideA * z;
    const __half* Al = ASPLIT ? (Alo + strideA * z) : nullptr;
    const __half* Bh = Bhi + strideB * z + (size_t)n0 * ldb;
    const __half* Bl = Blo + strideB * z + (size_t)n0 * ldb;

    int rowA = tid >> 1;                 // 0..255
    int kk16 = (tid & 1) * 16;
    int soffA = rowA * A_STRIDE + kk16;
    int rowB = (tid & 255) >> 1;         // 0..127 (tid<256 loads B)
    int soffB = rowB * A_STRIDE + kk16;

    int nk = KdPad >> 5;

    auto load_stage = [&](int s, int c) {
        __half* base = reinterpret_cast<__half*>(smem) + s * STAGE_H;
        int gm = m0 + rowA;
        bool aOk = gm < Mrows;
        const __half* pa = Ah + (size_t)gm * lda + c * 32 + kk16;
        cp16(base + soffA,     pa,     aOk);
        cp16(base + soffA + 8, pa + 8, aOk);
        if (ASPLIT) {
            const __half* pl = Al + (size_t)gm * lda + c * 32 + kk16;
            cp16(base + A_PLANE + soffA,     pl,     aOk);
            cp16(base + A_PLANE + soffA + 8, pl + 8, aOk);
        }
        if (tid < 256) {
            __half* bb = base + (ASPLIT ? 2 : 1) * A_PLANE;
            const __half* pb = Bh + (size_t)rowB * ldb + c * 32 + kk16;
            cp16(bb + soffB,     pb,     true);
            cp16(bb + soffB + 8, pb + 8, true);
            const __half* pbl = Bl + (size_t)rowB * ldb + c * 32 + kk16;
            cp16(bb + B_PLANE + soffB,     pbl,     true);
            cp16(bb + B_PLANE + soffB + 8, pbl + 8, true);
        }
        CP_COMMIT();
    };

    float acc[2][8][4];
#pragma unroll
    for (int mi = 0; mi < 2; mi++)
#pragma unroll
        for (int ni = 0; ni < 8; ni++)
#pragma unroll
            for (int i = 0; i < 4; i++) acc[mi][ni][i] = 0.f;

    int aRow = wm * 32 + (lane & 15);
    int aCol = (lane >> 4) * 8;
    int bRow = wn * 64 + (lane >> 4) * 8 + (lane & 7);
    int bCol = ((lane >> 3) & 1) * 8;
    int g = lane >> 2, t = lane & 3;

    load_stage(0, 0);

    for (int c = 0; c < nk; c++) {
        int s = (nk == 1) ? 0 : (c & 1);
        if (c + 1 < nk) {
            load_stage(s ^ 1, c + 1);
            CP_WAIT(1);
        } else {
            CP_WAIT(0);
        }
        __syncthreads();

        const __half* base = reinterpret_cast<const __half*>(smem) + s * STAGE_H;
        const __half* pAh = base;
        const __half* pAl = base + A_PLANE;
        const __half* pBh = base + (ASPLIT ? 2 : 1) * A_PLANE;
        const __half* pBl = pBh + B_PLANE;

#pragma unroll
        for (int ks = 0; ks < 2; ks++) {
            uint32_t ah[2][4], al[2][4];
#pragma unroll
            for (int mi = 0; mi < 2; mi++) {
                ldsm_x4(ah[mi], pAh + (aRow + mi * 16) * A_STRIDE + ks * 16 + aCol);
                if (ASPLIT)
                    ldsm_x4(al[mi], pAl + (aRow + mi * 16) * A_STRIDE + ks * 16 + aCol);
            }
#pragma unroll
            for (int q = 0; q < 4; q++) {
                uint32_t rh[4], rl[4];
                ldsm_x4(rh, pBh + (bRow + q * 16) * A_STRIDE + ks * 16 + bCol);
                ldsm_x4(rl, pBl + (bRow + q * 16) * A_STRIDE + ks * 16 + bCol);
#pragma unroll
                for (int p = 0; p < 2; p++) {
                    int ni = 2 * q + p;
#pragma unroll
                    for (int mi = 0; mi < 2; mi++) {
                        MMA16816(acc[mi][ni], ah[mi], rh[2 * p], rh[2 * p + 1]);
                        MMA16816(acc[mi][ni], ah[mi], rl[2 * p], rl[2 * p + 1]);
                        if (ASPLIT)
                            MMA16816(acc[mi][ni], al[mi], rh[2 * p], rh[2 * p + 1]);
                    }
                }
            }
        }
        __syncthreads();
    }

    // ---- epilogue ----
#pragma unroll
    for (int mi = 0; mi < 2; mi++) {
#pragma unroll
        for (int ni = 0; ni < 8; ni++) {
            int col = n0 + wn * 64 + ni * 8 + 2 * t;
            float b0 = 0.f, b1v = 0.f;
            if (bias) {
                b0 = bias[(size_t)z * Nfull + col];
                b1v = bias[(size_t)z * Nfull + col + 1];
            }
#pragma unroll
            for (int h = 0; h < 2; h++) {
                int row = m0 + wm * 32 + mi * 16 + g + h * 8;
                if (row >= Mrows) continue;
                float v0 = acc[mi][ni][2 * h] + b0;
                float v1 = acc[mi][ni][2 * h + 1] + b1v;
                if (leaky) {
                    v0 = v0 > 0.f ? v0 : 0.01f * v0;
                    v1 = v1 > 0.f ? v1 : 0.01f * v1;
                }
                size_t o = tposeF
                    ? ((size_t)row * K_NETS + z) * Nfull + col
                    : strideC * z + (size_t)row * Nfull + col;
                if (Cf) {
                    *reinterpret_cast<float2*>(&Cf[o]) = make_float2(v0, v1);
                } else {
                    *reinterpret_cast<__half2*>(&Ch[o]) = __floats2half2_rn(v0, v1);
                }
            }
        }
    }
}

#define SMEM_T  ((2 * A_PLANE + 2 * B_PLANE) * 2)          // ASPLIT=true, 1 stage: 61440
#define SMEM_F  (2 * (A_PLANE + 2 * B_PLANE) * 2)          // ASPLIT=false, 2 stages: 81920

// ---------------- phi0: per-net phi at t=0, from h2x + scale-folded W3cat ----------------
#define W3P 260   // padded d-stride (halves)
__global__ void phi0_kernel(const __half* __restrict__ h2x,
                            const __half* __restrict__ w3h, const __half* __restrict__ w3l,
                            float* __restrict__ phi0) {
    extern __shared__ __half wsm[];
    __half* wh = wsm;
    __half* wl = wsm + 128 * W3P;
    __shared__ float hrow[H_DIM];
    __shared__ float partial[256];
    int j = blockIdx.x, bg = blockIdx.y;
    int tid = threadIdx.x;
    for (int i = tid; i < 128 * (H_DIM / 4); i += 256) {
        int n = i >> 6, d4 = (i & 63) * 4;
        *reinterpret_cast<uint2*>(wh + n * W3P + d4) =
            *reinterpret_cast<const uint2*>(w3h + ((size_t)n * K_NETS + j) * H_DIM + d4);
        *reinterpret_cast<uint2*>(wl + n * W3P + d4) =
            *reinterpret_cast<const uint2*>(w3l + ((size_t)n * K_NETS + j) * H_DIM + d4);
    }
    __syncthreads();
    for (int bi = 0; bi < N_B / 4; bi++) {
        int b = bg * (N_B / 4) + bi;
        hrow[tid] = __half2float(h2x[((size_t)(b * T_DIM) * K_NETS + j) * H_DIM + tid]);
        __syncthreads();
        int n = tid & 127, hh = tid >> 7;
        const __half* whn = wh + n * W3P + hh * 128;
        const __half* wln = wl + n * W3P + hh * 128;
        const float* hr = hrow + hh * 128;
        float s = 0.f;
#pragma unroll 8
        for (int d = 0; d < 128; d++)
            s += hr[d] * (__half2float(whn[d]) + __half2float(wln[d]));
        partial[tid] = s;
        __syncthreads();
        if (tid < 128)
            phi0[((size_t)b * K_NETS + j) * L_DIM + tid] = partial[tid] + partial[tid + 128];
        __syncthreads();
    }
}

// ---------------- reduce split-K partials into phisum ----------------
__global__ void reduce16_kernel(const float* __restrict__ part, float* __restrict__ out) {
    int m = blockIdx.x;
    int l = threadIdx.x;
    float s = 0.f;
#pragma unroll
    for (int gp = 0; gp < NGRP; gp++)
        s += part[(size_t)gp * MX * L_DIM + (size_t)m * L_DIM + l];
    out[(size_t)m * L_DIM + l] = s;
}

// ---------------- psi(0) exact fp32 ----------------
__global__ void psi0_kernel(const float* __restrict__ b1eff, const float* __restrict__ W2,
                            const float* __restrict__ b2, const float* __restrict__ W3,
                            const float* __restrict__ scale, float* __restrict__ psi0) {
    int k = blockIdx.x;
    int t = threadIdx.x;
    __shared__ float h1[H_DIM], h2[H_DIM];
    float v = b1eff[k * H_DIM + t];
    h1[t] = v > 0.f ? v : 0.01f * v;
    __syncthreads();
    float a = b2[k * H_DIM + t];
    for (int d = 0; d < H_DIM; d++)
        a += h1[d] * W2[((size_t)k * H_DIM + d) * H_DIM + t];
    h2[t] = a > 0.f ? a : 0.01f * a;
    __syncthreads();
    if (t < L_DIM) {
        float s = 0.f;
        for (int d = 0; d < H_DIM; d++)
            s += h2[d] * W3[((size_t)k * H_DIM + d) * L_DIM + t];
        psi0[k * L_DIM + t] = s * scale[k * L_DIM + t];
    }
}

// ---------------- sequential Koopman scan: 2 blocks per batch ----------------
__global__ void __launch_bounds__(256)
scan_kernel(const float* __restrict__ phi0,  // [b][net][L]
            const float* __restrict__ psi,   // [bt][net][L]
            const float* __restrict__ psi0,
            const float* __restrict__ reL, const float* __restrict__ imL,
            float* __restrict__ predsum2) {
    int bid = blockIdx.x;
    int b = bid >> 1;
    int sel = bid & 1;
    int j0 = sel * 32;
    int tid = threadIdx.x;
    __shared__ float ps[32 * L_DIM];
    __shared__ float rsh[K_NETS], ish[K_NETS];
    if (tid < K_NETS) { rsh[tid] = reL[tid]; ish[tid] = imL[tid]; }

    float px[8], py[8], rj[8], ij[8], u0x[8], u0y[8];
    const float* phiB = phi0 + ((size_t)b * K_NETS + j0) * L_DIM;
    const float* psi0B = psi0 + (size_t)j0 * L_DIM;
#pragma unroll
    for (int q = 0; q < 8; q++) {
        int e = q * 256 + tid;
        float2 v = *reinterpret_cast<const float2*>(&phiB[e * 2]);
        px[q] = v.x; py[q] = v.y;
        float2 zz = *reinterpret_cast<const float2*>(&psi0B[e * 2]);
        u0x[q] = zz.x; u0y[q] = zz.y;
    }
    __syncthreads();
#pragma unroll
    for (int q = 0; q < 8; q++) {
        int j = j0 + ((q * 256 + tid) >> 6);
        rj[q] = rsh[j]; ij[q] = ish[j];
    }

    for (int t = 0; t < TM1; t++) {
        const float* psiT = psi + ((size_t)(b * TM1 + t) * K_NETS + j0) * L_DIM;
#pragma unroll
        for (int q = 0; q < 8; q++) {
            int e = q * 256 + tid;
            float2 u = *reinterpret_cast<const float2*>(&psiT[e * 2]);
            float vx = px[q] + u.x - u0x[q];
            float vy = py[q] + u.y - u0y[q];
            px[q] = vx * rj[q] - vy * ij[q];
            py[q] = vx * ij[q] + vy * rj[q];
            ps[e * 2]     = px[q];
            ps[e * 2 + 1] = py[q];
        }
        __syncthreads();
        if (tid < L_DIM) {
            float s = 0.f;
#pragma unroll 8
            for (int j = 0; j < 32; j++) s += ps[j * L_DIM + tid];
            predsum2[(((size_t)sel * N_B + b) * TM1 + t) * L_DIM + tid] = s;
        }
        __syncthreads();
    }
}

// ---------------- decode ----------------
__global__ void decode_kernel(const float* __restrict__ phisum,
                              const float* __restrict__ predsum2,
                              const float* __restrict__ C_W,
                              float* __restrict__ out) {
    __shared__ float Cs[DX * L_DIM];
    __shared__ float rowY[L_DIM], rowP[L_DIM];
    int bt = blockIdx.x;
    int b = bt / TM1, t = bt % TM1;
    int tid = threadIdx.x;
    for (int i = tid; i < DX * L_DIM; i += 256) Cs[i] = C_W[i];
    if (tid < L_DIM)
        rowY[tid] = phisum[((size_t)(b * T_DIM + t + 1)) * L_DIM + tid];
    else {
        int l = tid - L_DIM;
        rowP[l] = predsum2[(size_t)bt * L_DIM + l]
                + predsum2[((size_t)N_B * TM1 + bt) * L_DIM + l];
    }
    __syncthreads();
    if (tid < 2 * DX) {
        int sel = tid >> 4, d = tid & 15;
        const float* row = sel ? rowP : rowY;
        float s = 0.f;
        for (int l = 0; l < L_DIM; l++) s += row[l] * Cs[d * L_DIM + l];
        out[(size_t)sel * N_B * TM1 * DX + (size_t)bt * DX + d] = s;
    }
}

// ---------------- launcher ----------------
extern "C" void kernel_launch(void* const* d_in, const int* in_sizes, int n_in,
                              void* d_out, int out_size) {
    const float* xs      = (const float*)d_in[0];
    const float* us      = (const float*)d_in[1];
    const float* x_gamma = (const float*)d_in[2];
    const float* x_beta  = (const float*)d_in[3];
    const float* xW1     = (const float*)d_in[4];
    const float* xb1     = (const float*)d_in[5];
    const float* xW2     = (const float*)d_in[6];
    const float* xb2     = (const float*)d_in[7];
    const float* xW3     = (const float*)d_in[8];
    const float* x_scale = (const float*)d_in[9];
    const float* u_gamma = (const float*)d_in[10];
    const float* u_beta  = (const float*)d_in[11];
    const float* uW1     = (const float*)d_in[12];
    const float* ub1     = (const float*)d_in[13];
    const float* uW2     = (const float*)d_in[14];
    const float* ub2     = (const float*)d_in[15];
    const float* uW3     = (const float*)d_in[16];
    const float* u_scale = (const float*)d_in[17];
    const float* reL     = (const float*)d_in[18];
    const float* imL     = (const float*)d_in[19];
    const float* C_W     = (const float*)d_in[20];
    float* out = (float*)d_out;

    float *b1ex, *b1eu, *psi, *psi0, *phi0, *phisum_part, *phisum, *predsum2;
    __half *xnhi, *xnlo, *unhi, *unlo, *w1xh, *w1xl, *w1uh, *w1ul;
    __half *h1, *h2;
    __half *w2xh, *w2xl, *w3xh, *w3xl, *w2uh, *w2ul, *w3uh, *w3ul;
    cudaGetSymbolAddress((void**)&xnhi, g_xnhi);
    cudaGetSymbolAddress((void**)&xnlo, g_xnlo);
    cudaGetSymbolAddress((void**)&unhi, g_unhi);
    cudaGetSymbolAddress((void**)&unlo, g_unlo);
    cudaGetSymbolAddress((void**)&b1ex, g_b1ex);
    cudaGetSymbolAddress((void**)&b1eu, g_b1eu);
    cudaGetSymbolAddress((void**)&w1xh, g_w1xh);
    cudaGetSymbolAddress((void**)&w1xl, g_w1xl);
    cudaGetSymbolAddress((void**)&w1uh, g_w1uh);
    cudaGetSymbolAddress((void**)&w1ul, g_w1ul);
    cudaGetSymbolAddress((void**)&h1, g_h1);
    cudaGetSymbolAddress((void**)&h2, g_h2);
    cudaGetSymbolAddress((void**)&w2xh, g_w2xt_hi);
    cudaGetSymbolAddress((void**)&w2xl, g_w2xt_lo);
    cudaGetSymbolAddress((void**)&w3xh, g_w3xt_hi);
    cudaGetSymbolAddress((void**)&w3xl, g_w3xt_lo);
    cudaGetSymbolAddress((void**)&w2uh, g_w2ut_hi);
    cudaGetSymbolAddress((void**)&w2ul, g_w2ut_lo);
    cudaGetSymbolAddress((void**)&w3uh, g_w3ut_hi);
    cudaGetSymbolAddress((void**)&w3ul, g_w3ut_lo);
    cudaGetSymbolAddress((void**)&psi, g_psi);
    cudaGetSymbolAddress((void**)&psi0, g_psi0);
    cudaGetSymbolAddress((void**)&phi0, g_phi0);
    cudaGetSymbolAddress((void**)&phisum_part, g_phisum_part);
    cudaGetSymbolAddress((void**)&phisum, g_phisum);
    cudaGetSymbolAddress((void**)&predsum2, g_predsum2);

    cudaFuncSetAttribute((const void*)hmma_gemm_kernel<true>,
                         cudaFuncAttributeMaxDynamicSharedMemorySize, SMEM_T);
    cudaFuncSetAttribute((const void*)hmma_gemm_kernel<false>,
                         cudaFuncAttributeMaxDynamicSharedMemorySize, SMEM_F);
    cudaFuncSetAttribute((const void*)phi0_kernel,
                         cudaFuncAttributeMaxDynamicSharedMemorySize, 2 * 128 * W3P * 2);

    dim3 tb(32, 8);
    // ---- x path ----
    bn_split_kernel<<<KP1, 256>>>(xs, xnhi, xnlo, MX, DX);                          // 0
    prep_w1_split_kernel<<<K_NETS, H_DIM>>>(x_gamma, x_beta, xW1, xb1,
                                            w1xh, w1xl, b1ex, DX);                  // 1
    transpose_split2_kernel<<<dim3(96, K_NETS), tb>>>(
        xW2, w2xh, w2xl, xW3, w3xh, w3xl, x_scale, 1);                              // 2
    hmma_gemm_kernel<true><<<dim3(MX / 256, 2, K_NETS), 512, SMEM_T>>>(
        xnhi, xnlo, 0, KP1, KP1, w1xh, w1xl, (size_t)H_DIM * KP1, KP1,
        b1ex, nullptr, h1, (size_t)MX * H_DIM, MX, H_DIM, 1, 0);                    // 3: L1x
    bn_split_kernel<<<KP1, 256>>>(us, unhi, unlo, MU, DU);                          // 4
    hmma_gemm_kernel<false><<<dim3(MX / 256, 2, K_NETS), 512, SMEM_F>>>(
        h1, nullptr, (size_t)MX * H_DIM, H_DIM, H_DIM,
        w2xh, w2xl, (size_t)H_DIM * H_DIM, H_DIM,
        xb2, nullptr, h2, 0, MX, H_DIM, 1, 1);                                      // 5: L2x -> h2 [m][net][d]
    hmma_gemm_kernel<false><<<dim3(MX / 256, 1, NGRP), 512, SMEM_F>>>(
        h2, nullptr, (size_t)KGRP, K_NETS * H_DIM, KGRP,
        w3xh, w3xl, (size_t)KGRP, K_NETS * H_DIM,
        nullptr, phisum_part, nullptr, (size_t)MX * L_DIM, MX, L_DIM, 0, 0);        // 6: phisum split-K
    phi0_kernel<<<dim3(K_NETS, 4), 256, 2 * 128 * W3P * 2>>>(h2, w3xh, w3xl, phi0); // 7
    reduce16_kernel<<<MX, L_DIM>>>(phisum_part, phisum);                            // 8

    // ---- u path ----
    prep_w1_split_kernel<<<K_NETS, H_DIM>>>(u_gamma, u_beta, uW1, ub1,
                                            w1uh, w1ul, b1eu, DU);                  // 9
    transpose_split2_kernel<<<dim3(96, K_NETS), tb>>>(
        uW2, w2uh, w2ul, uW3, w3uh, w3ul, u_scale, 0);                              // 10
    hmma_gemm_kernel<true><<<dim3(16, 2, K_NETS), 512, SMEM_T>>>(
        unhi, unlo, 0, KP1, KP1, w1uh, w1ul, (size_t)H_DIM * KP1, KP1,
        b1eu, nullptr, h1, (size_t)MU * H_DIM, MU, H_DIM, 1, 0);                    // 11
    hmma_gemm_kernel<false><<<dim3(16, 2, K_NETS), 512, SMEM_F>>>(
        h1, nullptr, (size_t)MU * H_DIM, H_DIM, H_DIM,
        w2uh, w2ul, (size_t)H_DIM * H_DIM, H_DIM,
        ub2, nullptr, h2, (size_t)MU * H_DIM, MU, H_DIM, 1, 0);                     // 12
    hmma_gemm_kernel<false><<<dim3(16, 1, K_NETS), 512, SMEM_F>>>(
        h2, nullptr, (size_t)MU * H_DIM, H_DIM, H_DIM,
        w3uh, w3ul, (size_t)L_DIM * H_DIM, H_DIM,
        nullptr, psi, nullptr, 0, MU, L_DIM, 0, 1);                                 // 13: psi [bt][net][L]

    psi0_kernel<<<K_NETS, H_DIM>>>(b1eu, uW2, ub2, uW3, u_scale, psi0);             // 14
    scan_kernel<<<2 * N_B, 256>>>(phi0, psi, psi0, reL, imL, predsum2);             // 15
    decode_kernel<<<N_B * TM1, 256>>>(phisum, predsum2, C_W, out);                  // 16
}

// round 12
// speedup vs baseline: 1.6989x; 1.0664x over previous
#include <cuda_runtime.h>
#include <cuda_fp16.h>
#include <cstdint>
#include <cstddef>

// ---------------- problem dims (fixed) ----------------
#define N_B    64
#define T_DIM  64
#define TM1    63
#define DX     16
#define DU     8
#define H_DIM  256
#define L_DIM  128
#define K_NETS 64
#define MX     (N_B * T_DIM)   // 4096
#define MU     (N_B * TM1)     // 4032
#define KP1    32
#define NGRP   16              // split-K net groups for phisum GEMM
#define KGRP   (K_NETS / NGRP * H_DIM)   // 1024
#define KCAT   (K_NETS * H_DIM)          // 16384

// ---------------- scratch (device globals) ----------------
__device__ __half g_xnhi[MX * KP1];
__device__ __half g_xnlo[MX * KP1];
__device__ __half g_unhi[MU * KP1];
__device__ __half g_unlo[MU * KP1];
__device__ float g_b1ex[K_NETS * H_DIM];
__device__ float g_b1eu[K_NETS * H_DIM];
__device__ __half g_w1xh[K_NETS * H_DIM * KP1];
__device__ __half g_w1xl[K_NETS * H_DIM * KP1];
__device__ __half g_w1uh[K_NETS * H_DIM * KP1];
__device__ __half g_w1ul[K_NETS * H_DIM * KP1];
__device__ __half g_h1[(size_t)K_NETS * MX * H_DIM];
__device__ __half g_h2[(size_t)K_NETS * MX * H_DIM];     // x: [m][net*d] concat; u: [net][m][d]
__device__ __half g_w2xt_hi[(size_t)K_NETS * H_DIM * H_DIM];
__device__ __half g_w2xt_lo[(size_t)K_NETS * H_DIM * H_DIM];
__device__ __half g_w3xt_hi[(size_t)K_NETS * L_DIM * H_DIM];  // x: cat [n][net*d], scale folded
__device__ __half g_w3xt_lo[(size_t)K_NETS * L_DIM * H_DIM];
__device__ __half g_w2ut_hi[(size_t)K_NETS * H_DIM * H_DIM];
__device__ __half g_w2ut_lo[(size_t)K_NETS * H_DIM * H_DIM];
__device__ __half g_w3ut_hi[(size_t)K_NETS * L_DIM * H_DIM];  // u: [net][n][d], scale folded
__device__ __half g_w3ut_lo[(size_t)K_NETS * L_DIM * H_DIM];
__device__ float g_psi[(size_t)MU * K_NETS * L_DIM];     // [bt][net][L]
__device__ float g_psi0[K_NETS * L_DIM];
__device__ float g_phi0[N_B * K_NETS * L_DIM];           // per-net phi at t=0: [b][net][L]
__device__ float g_phisum_part[NGRP * MX * L_DIM];
__device__ float g_phisum[MX * L_DIM];
__device__ float g_predsum2[2 * N_B * TM1 * L_DIM];

// ---------------- BN + fp16 hi/lo split ----------------
__global__ void bn_split_kernel(const float* __restrict__ x,
                                __half* __restrict__ Ahi, __half* __restrict__ Alo,
                                int M, int D) {
    int d = blockIdx.x;
    int tid = threadIdx.x;
    if (d >= D) {
        for (int m = tid; m < M; m += 256) {
            Ahi[(size_t)m * KP1 + d] = __float2half(0.f);
            Alo[(size_t)m * KP1 + d] = __float2half(0.f);
        }
        return;
    }
    __shared__ float r1[256], r2[256];
    float s = 0.f, s2 = 0.f;
    for (int m = tid; m < M; m += 256) {
        float v = x[(size_t)m * D + d];
        s += v; s2 += v * v;
    }
    r1[tid] = s; r2[tid] = s2;
    __syncthreads();
    for (int o = 128; o > 0; o >>= 1) {
        if (tid < o) { r1[tid] += r1[tid + o]; r2[tid] += r2[tid + o]; }
        __syncthreads();
    }
    float mu = r1[0] / M;
    float var = r2[0] / M - mu * mu;
    float rstd = rsqrtf(var + 1e-5f);
    for (int m = tid; m < M; m += 256) {
        float v = (x[(size_t)m * D + d] - mu) * rstd;
        __half h = __float2half(v);
        Ahi[(size_t)m * KP1 + d] = h;
        Alo[(size_t)m * KP1 + d] = __float2half(v - __half2float(h));
    }
}

// ---------------- fold BN affine into layer-1, transpose, split ----------------
__global__ void prep_w1_split_kernel(const float* __restrict__ g, const float* __restrict__ be,
                                     const float* __restrict__ W1, const float* __restrict__ b1,
                                     __half* __restrict__ Thi, __half* __restrict__ Tlo,
                                     float* __restrict__ beff, int D) {
    int k = blockIdx.x;
    int h = threadIdx.x;
    float bacc = b1[k * H_DIM + h];
    for (int d = 0; d < KP1; d++) {
        float v = 0.f;
        if (d < D) {
            float w = W1[((size_t)k * D + d) * H_DIM + h];
            v = g[k * D + d] * w;
            bacc += be[k * D + d] * w;
        }
        __half hi = __float2half(v);
        size_t o = ((size_t)k * H_DIM + h) * KP1 + d;
        Thi[o] = hi;
        Tlo[o] = __float2half(v - __half2float(hi));
    }
    beff[k * H_DIM + h] = bacc;
}

// ---------------- W2 + W3 transpose + split; W3 gets scale folded in ----------------
// cat3=1: W3 out [n][net*d] (concat for phisum GEMM); cat3=0: [net][n][d]
__global__ void transpose_split2_kernel(const float* __restrict__ W2,
                                        __half* __restrict__ T2h, __half* __restrict__ T2l,
                                        const float* __restrict__ W3,
                                        __half* __restrict__ T3h, __half* __restrict__ T3l,
                                        const float* __restrict__ scale3, int cat3) {
    __shared__ float tile[32][33];
    int k = blockIdx.y;
    int idx = blockIdx.x;
    if (idx < 64) {
        const float* W = W2 + (size_t)k * H_DIM * H_DIM;
        int kk0 = (idx >> 3) * 32, n0 = (idx & 7) * 32;
        for (int r = threadIdx.y; r < 32; r += 8)
            tile[r][threadIdx.x] = W[(size_t)(kk0 + r) * H_DIM + n0 + threadIdx.x];
        __syncthreads();
        for (int r = threadIdx.y; r < 32; r += 8) {
            int n = n0 + r, kk = kk0 + threadIdx.x;
            float v = tile[threadIdx.x][r];
            __half h = __float2half(v);
            size_t o = ((size_t)k * H_DIM + n) * H_DIM + kk;
            T2h[o] = h;
            T2l[o] = __float2half(v - __half2float(h));
        }
    } else {
        idx -= 64;
        const float* W = W3 + (size_t)k * H_DIM * L_DIM;
        int kk0 = (idx >> 2) * 32, n0 = (idx & 3) * 32;
        for (int r = threadIdx.y; r < 32; r += 8)
            tile[r][threadIdx.x] = W[(size_t)(kk0 + r) * L_DIM + n0 + threadIdx.x];
        __syncthreads();
        for (int r = threadIdx.y; r < 32; r += 8) {
            int n = n0 + r, kk = kk0 + threadIdx.x;
            float v = tile[threadIdx.x][r] * scale3[k * L_DIM + n];
            __half h = __float2half(v);
            size_t o = cat3 ? ((size_t)n * K_NETS + k) * H_DIM + kk
                            : ((size_t)k * L_DIM + n) * H_DIM + kk;
            T3h[o] = h;
            T3l[o] = __float2half(v - __half2float(h));
        }
    }
}

// ================= R8-geometry HMMA GEMM (128m x 128n, 256 thr, 2 CTA/SM) =================
// generalized addressing: A[z] = Ahi + strideA*z, row stride lda (same for Alo);
// B[z] = Bhi + strideB*z + n0*ldb, row stride ldb (same for Blo).
#define SM_STRIDE 40
#define PLANE_BYTES (128 * SM_STRIDE * 2)     // 10240

__device__ __forceinline__ void cp16(void* dst, const void* src, bool pred) {
    uint32_t d = (uint32_t)__cvta_generic_to_shared(dst);
    int n = pred ? 16 : 0;
    asm volatile("cp.async.cg.shared.global [%0], [%1], 16, %2;" :: "r"(d), "l"(src), "r"(n));
}
#define CP_COMMIT() asm volatile("cp.async.commit_group;")
#define CP_WAIT(N)  asm volatile("cp.async.wait_group %0;" :: "n"(N))

__device__ __forceinline__ void ldsm_x4(uint32_t* r, const void* p) {
    uint32_t a = (uint32_t)__cvta_generic_to_shared(p);
    asm volatile("ldmatrix.sync.aligned.m8n8.x4.shared.b16 {%0,%1,%2,%3}, [%4];"
                 : "=r"(r[0]), "=r"(r[1]), "=r"(r[2]), "=r"(r[3]) : "r"(a));
}
#define MMA16816(d, a, b0, b1) \
    asm volatile("mma.sync.aligned.m16n8k16.row.col.f32.f16.f16.f32 " \
                 "{%0,%1,%2,%3},{%4,%5,%6,%7},{%8,%9},{%0,%1,%2,%3};" \
                 : "+f"((d)[0]), "+f"((d)[1]), "+f"((d)[2]), "+f"((d)[3]) \
                 : "r"((a)[0]), "r"((a)[1]), "r"((a)[2]), "r"((a)[3]), \
                   "r"(b0), "r"(b1))

template <bool ASPLIT>
__global__ void __launch_bounds__(256, 2)
hmma_gemm_kernel(const __half* __restrict__ Ahi, const __half* __restrict__ Alo,
                 size_t strideA, int lda, int KdPad,
                 const __half* __restrict__ Bhi, const __half* __restrict__ Blo,
                 size_t strideB, int ldb,
                 const float* __restrict__ bias,
                 float* __restrict__ Cf, __half* __restrict__ Ch, size_t strideC,
                 int Mrows, int Nfull, int leaky, int tposeF) {
    extern __shared__ char smem[];
    constexpr int NPL = ASPLIT ? 4 : 3;   // planes: Ah [Al] Bh Bl

    int tid = threadIdx.x;
    int lane = tid & 31, wid = tid >> 5;
    int wm = wid >> 1, wn = wid & 1;
    int z = blockIdx.z;
    int m0 = blockIdx.x * 128, n0 = blockIdx.y * 128;

    const __half* Ah = Ahi + strideA * z;
    const __half* Al = ASPLIT ? (Alo + strideA * z) : nullptr;
    const __half* Bh = Bhi + strideB * z + (size_t)n0 * ldb;
    const __half* Bl = Blo + strideB * z + (size_t)n0 * ldb;

    auto plane = [&](int p, int s) -> __half* {
        return reinterpret_cast<__half*>(smem + (p * 2 + s) * PLANE_BYTES);
    };

    int rowL = tid >> 1;
    int kkL = (tid & 1) * 16;
    bool aOk = (m0 + rowL) < Mrows;
    const __half* gA_h = Ah + (size_t)(m0 + rowL) * lda + kkL;
    const __half* gA_l = ASPLIT ? (Al + (size_t)(m0 + rowL) * lda + kkL) : nullptr;
    const __half* gB_h = Bh + (size_t)rowL * ldb + kkL;
    const __half* gB_l = Bl + (size_t)rowL * ldb + kkL;
    int soff = rowL * SM_STRIDE + kkL;

    int nk = KdPad >> 5;

    auto load_stage = [&](int s, int c) {
        int k0 = c << 5;
        cp16(plane(0, s) + soff,     gA_h + k0,     aOk);
        cp16(plane(0, s) + soff + 8, gA_h + k0 + 8, aOk);
        if (ASPLIT) {
            cp16(plane(1, s) + soff,     gA_l + k0,     aOk);
            cp16(plane(1, s) + soff + 8, gA_l + k0 + 8, aOk);
        }
        cp16(plane(NPL - 2, s) + soff,     gB_h + k0,     true);
        cp16(plane(NPL - 2, s) + soff + 8, gB_h + k0 + 8, true);
        cp16(plane(NPL - 1, s) + soff,     gB_l + k0,     true);
        cp16(plane(NPL - 1, s) + soff + 8, gB_l + k0 + 8, true);
        CP_COMMIT();
    };

    float acc[2][8][4];
#pragma unroll
    for (int mi = 0; mi < 2; mi++)
#pragma unroll
        for (int ni = 0; ni < 8; ni++)
#pragma unroll
            for (int i = 0; i < 4; i++) acc[mi][ni][i] = 0.f;

    int aRow = wm * 32 + (lane & 15);
    int aCol = (lane >> 4) * 8;
    int bRow = wn * 64 + (lane >> 4) * 8 + (lane & 7);
    int bCol = ((lane >> 3) & 1) * 8;
    int g = lane >> 2, t = lane & 3;

    load_stage(0, 0);

    for (int c = 0; c < nk; c++) {
        int s = c & 1;
        if (c + 1 < nk) {
            load_stage(s ^ 1, c + 1);
            CP_WAIT(1);
        } else {
            CP_WAIT(0);
        }
        __syncthreads();

        const __half* pAh = plane(0, s);
        const __half* pAl = plane(1, s);
        const __half* pBh = plane(NPL - 2, s);
        const __half* pBl = plane(NPL - 1, s);

#pragma unroll
        for (int ks = 0; ks < 2; ks++) {
            uint32_t ah[2][4], al[2][4];
#pragma unroll
            for (int mi = 0; mi < 2; mi++) {
                ldsm_x4(ah[mi], pAh + (aRow + mi * 16) * SM_STRIDE + ks * 16 + aCol);
                if (ASPLIT)
                    ldsm_x4(al[mi], pAl + (aRow + mi * 16) * SM_STRIDE + ks * 16 + aCol);
            }
#pragma unroll
            for (int q = 0; q < 4; q++) {
                uint32_t rh[4], rl[4];
                ldsm_x4(rh, pBh + (bRow + q * 16) * SM_STRIDE + ks * 16 + bCol);
                ldsm_x4(rl, pBl + (bRow + q * 16) * SM_STRIDE + ks * 16 + bCol);
#pragma unroll
                for (int p = 0; p < 2; p++) {
                    int ni = 2 * q + p;
#pragma unroll
                    for (int mi = 0; mi < 2; mi++) {
                        MMA16816(acc[mi][ni], ah[mi], rh[2 * p], rh[2 * p + 1]);
                        MMA16816(acc[mi][ni], ah[mi], rl[2 * p], rl[2 * p + 1]);
                        if (ASPLIT)
                            MMA16816(acc[mi][ni], al[mi], rh[2 * p], rh[2 * p + 1]);
                    }
                }
            }
        }
        __syncthreads();
    }

    // ---- epilogue ----
#pragma unroll
    for (int mi = 0; mi < 2; mi++) {
#pragma unroll
        for (int ni = 0; ni < 8; ni++) {
            int col = n0 + wn * 64 + ni * 8 + 2 * t;
            float b0 = 0.f, b1v = 0.f;
            if (bias) {
                b0 = bias[(size_t)z * Nfull + col];
                b1v = bias[(size_t)z * Nfull + col + 1];
            }
#pragma unroll
            for (int h = 0; h < 2; h++) {
                int row = m0 + wm * 32 + mi * 16 + g + h * 8;
                if (row >= Mrows) continue;
                float v0 = acc[mi][ni][2 * h] + b0;
                float v1 = acc[mi][ni][2 * h + 1] + b1v;
                if (leaky) {
                    v0 = v0 > 0.f ? v0 : 0.01f * v0;
                    v1 = v1 > 0.f ? v1 : 0.01f * v1;
                }
                size_t o = tposeF
                    ? ((size_t)row * K_NETS + z) * Nfull + col
                    : strideC * z + (size_t)row * Nfull + col;
                if (Cf) {
                    *reinterpret_cast<float2*>(&Cf[o]) = make_float2(v0, v1);
                } else {
                    *reinterpret_cast<__half2*>(&Ch[o]) = __floats2half2_rn(v0, v1);
                }
            }
        }
    }
}

#define SMEM_T (8 * PLANE_BYTES)   // ASPLIT=true:  4 planes x 2 stages = 81920
#define SMEM_F (6 * PLANE_BYTES)   // ASPLIT=false: 3 planes x 2 stages = 61440

// ---------------- phi0: per-net phi at t=0 ----------------
#define W3P 260
__global__ void phi0_kernel(const __half* __restrict__ h2x,
                            const __half* __restrict__ w3h, const __half* __restrict__ w3l,
                            float* __restrict__ phi0) {
    extern __shared__ __half wsm[];
    __half* wh = wsm;
    __half* wl = wsm + 128 * W3P;
    __shared__ float hrow[H_DIM];
    __shared__ float partial[256];
    int j = blockIdx.x, bg = blockIdx.y;
    int tid = threadIdx.x;
    for (int i = tid; i < 128 * (H_DIM / 4); i += 256) {
        int n = i >> 6, d4 = (i & 63) * 4;
        *reinterpret_cast<uint2*>(wh + n * W3P + d4) =
            *reinterpret_cast<const uint2*>(w3h + ((size_t)n * K_NETS + j) * H_DIM + d4);
        *reinterpret_cast<uint2*>(wl + n * W3P + d4) =
            *reinterpret_cast<const uint2*>(w3l + ((size_t)n * K_NETS + j) * H_DIM + d4);
    }
    __syncthreads();
    for (int bi = 0; bi < N_B / 4; bi++) {
        int b = bg * (N_B / 4) + bi;
        hrow[tid] = __half2float(h2x[((size_t)(b * T_DIM) * K_NETS + j) * H_DIM + tid]);
        __syncthreads();
        int n = tid & 127, hh = tid >> 7;
        const __half* whn = wh + n * W3P + hh * 128;
        const __half* wln = wl + n * W3P + hh * 128;
        const float* hr = hrow + hh * 128;
        float s = 0.f;
#pragma unroll 8
        for (int d = 0; d < 128; d++)
            s += hr[d] * (__half2float(whn[d]) + __half2float(wln[d]));
        partial[tid] = s;
        __syncthreads();
        if (tid < 128)
            phi0[((size_t)b * K_NETS + j) * L_DIM + tid] = partial[tid] + partial[tid + 128];
        __syncthreads();
    }
}

// ---------------- reduce split-K partials ----------------
__global__ void reduce16_kernel(const float* __restrict__ part, float* __restrict__ out) {
    int m = blockIdx.x;
    int l = threadIdx.x;
    float s = 0.f;
#pragma unroll
    for (int gp = 0; gp < NGRP; gp++)
        s += part[(size_t)gp * MX * L_DIM + (size_t)m * L_DIM + l];
    out[(size_t)m * L_DIM + l] = s;
}

// ---------------- psi(0) exact fp32 ----------------
__global__ void psi0_kernel(const float* __restrict__ b1eff, const float* __restrict__ W2,
                            const float* __restrict__ b2, const float* __restrict__ W3,
                            const float* __restrict__ scale, float* __restrict__ psi0) {
    int k = blockIdx.x;
    int t = threadIdx.x;
    __shared__ float h1[H_DIM], h2[H_DIM];
    float v = b1eff[k * H_DIM + t];
    h1[t] = v > 0.f ? v : 0.01f * v;
    __syncthreads();
    float a = b2[k * H_DIM + t];
    for (int d = 0; d < H_DIM; d++)
        a += h1[d] * W2[((size_t)k * H_DIM + d) * H_DIM + t];
    h2[t] = a > 0.f ? a : 0.01f * a;
    __syncthreads();
    if (t < L_DIM) {
        float s = 0.f;
        for (int d = 0; d < H_DIM; d++)
            s += h2[d] * W3[((size_t)k * H_DIM + d) * L_DIM + t];
        psi0[k * L_DIM + t] = s * scale[k * L_DIM + t];
    }
}

// ---------------- scan: 2 blocks per batch ----------------
__global__ void __launch_bounds__(256)
scan_kernel(const float* __restrict__ phi0,
            const float* __restrict__ psi,
            const float* __restrict__ psi0,
            const float* __restrict__ reL, const float* __restrict__ imL,
            float* __restrict__ predsum2) {
    int bid = blockIdx.x;
    int b = bid >> 1;
    int sel = bid & 1;
    int j0 = sel * 32;
    int tid = threadIdx.x;
    __shared__ float ps[32 * L_DIM];
    __shared__ float rsh[K_NETS], ish[K_NETS];
    if (tid < K_NETS) { rsh[tid] = reL[tid]; ish[tid] = imL[tid]; }

    float px[8], py[8], rj[8], ij[8], u0x[8], u0y[8];
    const float* phiB = phi0 + ((size_t)b * K_NETS + j0) * L_DIM;
    const float* psi0B = psi0 + (size_t)j0 * L_DIM;
#pragma unroll
    for (int q = 0; q < 8; q++) {
        int e = q * 256 + tid;
        float2 v = *reinterpret_cast<const float2*>(&phiB[e * 2]);
        px[q] = v.x; py[q] = v.y;
        float2 zz = *reinterpret_cast<const float2*>(&psi0B[e * 2]);
        u0x[q] = zz.x; u0y[q] = zz.y;
    }
    __syncthreads();
#pragma unroll
    for (int q = 0; q < 8; q++) {
        int j = j0 + ((q * 256 + tid) >> 6);
        rj[q] = rsh[j]; ij[q] = ish[j];
    }

    for (int t = 0; t < TM1; t++) {
        const float* psiT = psi + ((size_t)(b * TM1 + t) * K_NETS + j0) * L_DIM;
#pragma unroll
        for (int q = 0; q < 8; q++) {
            int e = q * 256 + tid;
            float2 u = *reinterpret_cast<const float2*>(&psiT[e * 2]);
            float vx = px[q] + u.x - u0x[q];
            float vy = py[q] + u.y - u0y[q];
            px[q] = vx * rj[q] - vy * ij[q];
            py[q] = vx * ij[q] + vy * rj[q];
            ps[e * 2]     = px[q];
            ps[e * 2 + 1] = py[q];
        }
        __syncthreads();
        if (tid < L_DIM) {
            float s = 0.f;
#pragma unroll 8
            for (int j = 0; j < 32; j++) s += ps[j * L_DIM + tid];
            predsum2[(((size_t)sel * N_B + b) * TM1 + t) * L_DIM + tid] = s;
        }
        __syncthreads();
    }
}

// ---------------- decode ----------------
__global__ void decode_kernel(const float* __restrict__ phisum,
                              const float* __restrict__ predsum2,
                              const float* __restrict__ C_W,
                              float* __restrict__ out) {
    __shared__ float Cs[DX * L_DIM];
    __shared__ float rowY[L_DIM], rowP[L_DIM];
    int bt = blockIdx.x;
    int b = bt / TM1, t = bt % TM1;
    int tid = threadIdx.x;
    for (int i = tid; i < DX * L_DIM; i += 256) Cs[i] = C_W[i];
    if (tid < L_DIM)
        rowY[tid] = phisum[((size_t)(b * T_DIM + t + 1)) * L_DIM + tid];
    else {
        int l = tid - L_DIM;
        rowP[l] = predsum2[(size_t)bt * L_DIM + l]
                + predsum2[((size_t)N_B * TM1 + bt) * L_DIM + l];
    }
    __syncthreads();
    if (tid < 2 * DX) {
        int sel = tid >> 4, d = tid & 15;
        const float* row = sel ? rowP : rowY;
        float s = 0.f;
        for (int l = 0; l < L_DIM; l++) s += row[l] * Cs[d * L_DIM + l];
        out[(size_t)sel * N_B * TM1 * DX + (size_t)bt * DX + d] = s;
    }
}

// ---------------- launcher ----------------
extern "C" void kernel_launch(void* const* d_in, const int* in_sizes, int n_in,
                              void* d_out, int out_size) {
    const float* xs      = (const float*)d_in[0];
    const float* us      = (const float*)d_in[1];
    const float* x_gamma = (const float*)d_in[2];
    const float* x_beta  = (const float*)d_in[3];
    const float* xW1     = (const float*)d_in[4];
    const float* xb1     = (const float*)d_in[5];
    const float* xW2     = (const float*)d_in[6];
    const float* xb2     = (const float*)d_in[7];
    const float* xW3     = (const float*)d_in[8];
    const float* x_scale = (const float*)d_in[9];
    const float* u_gamma = (const float*)d_in[10];
    const float* u_beta  = (const float*)d_in[11];
    const float* uW1     = (const float*)d_in[12];
    const float* ub1     = (const float*)d_in[13];
    const float* uW2     = (const float*)d_in[14];
    const float* ub2     = (const float*)d_in[15];
    const float* uW3     = (const float*)d_in[16];
    const float* u_scale = (const float*)d_in[17];
    const float* reL     = (const float*)d_in[18];
    const float* imL     = (const float*)d_in[19];
    const float* C_W     = (const float*)d_in[20];
    float* out = (float*)d_out;

    float *b1ex, *b1eu, *psi, *psi0, *phi0, *phisum_part, *phisum, *predsum2;
    __half *xnhi, *xnlo, *unhi, *unlo, *w1xh, *w1xl, *w1uh, *w1ul;
    __half *h1, *h2;
    __half *w2xh, *w2xl, *w3xh, *w3xl, *w2uh, *w2ul, *w3uh, *w3ul;
    cudaGetSymbolAddress((void**)&xnhi, g_xnhi);
    cudaGetSymbolAddress((void**)&xnlo, g_xnlo);
    cudaGetSymbolAddress((void**)&unhi, g_unhi);
    cudaGetSymbolAddress((void**)&unlo, g_unlo);
    cudaGetSymbolAddress((void**)&b1ex, g_b1ex);
    cudaGetSymbolAddress((void**)&b1eu, g_b1eu);
    cudaGetSymbolAddress((void**)&w1xh, g_w1xh);
    cudaGetSymbolAddress((void**)&w1xl, g_w1xl);
    cudaGetSymbolAddress((void**)&w1uh, g_w1uh);
    cudaGetSymbolAddress((void**)&w1ul, g_w1ul);
    cudaGetSymbolAddress((void**)&h1, g_h1);
    cudaGetSymbolAddress((void**)&h2, g_h2);
    cudaGetSymbolAddress((void**)&w2xh, g_w2xt_hi);
    cudaGetSymbolAddress((void**)&w2xl, g_w2xt_lo);
    cudaGetSymbolAddress((void**)&w3xh, g_w3xt_hi);
    cudaGetSymbolAddress((void**)&w3xl, g_w3xt_lo);
    cudaGetSymbolAddress((void**)&w2uh, g_w2ut_hi);
    cudaGetSymbolAddress((void**)&w2ul, g_w2ut_lo);
    cudaGetSymbolAddress((void**)&w3uh, g_w3ut_hi);
    cudaGetSymbolAddress((void**)&w3ul, g_w3ut_lo);
    cudaGetSymbolAddress((void**)&psi, g_psi);
    cudaGetSymbolAddress((void**)&psi0, g_psi0);
    cudaGetSymbolAddress((void**)&phi0, g_phi0);
    cudaGetSymbolAddress((void**)&phisum_part, g_phisum_part);
    cudaGetSymbolAddress((void**)&phisum, g_phisum);
    cudaGetSymbolAddress((void**)&predsum2, g_predsum2);

    cudaFuncSetAttribute((const void*)hmma_gemm_kernel<true>,
                         cudaFuncAttributeMaxDynamicSharedMemorySize, SMEM_T);
    cudaFuncSetAttribute((const void*)hmma_gemm_kernel<false>,
                         cudaFuncAttributeMaxDynamicSharedMemorySize, SMEM_F);
    cudaFuncSetAttribute((const void*)phi0_kernel,
                         cudaFuncAttributeMaxDynamicSharedMemorySize, 2 * 128 * W3P * 2);

    dim3 tb(32, 8);
    // ---- x path ----
    bn_split_kernel<<<KP1, 256>>>(xs, xnhi, xnlo, MX, DX);                          // 0
    prep_w1_split_kernel<<<K_NETS, H_DIM>>>(x_gamma, x_beta, xW1, xb1,
                                            w1xh, w1xl, b1ex, DX);                  // 1
    transpose_split2_kernel<<<dim3(96, K_NETS), tb>>>(
        xW2, w2xh, w2xl, xW3, w3xh, w3xl, x_scale, 1);                              // 2
    // L1x: h1[net][m][d]
    hmma_gemm_kernel<true><<<dim3(MX / 128, 2, K_NETS), 256, SMEM_T>>>(
        xnhi, xnlo, 0, KP1, KP1, w1xh, w1xl, (size_t)H_DIM * KP1, KP1,
        b1ex, nullptr, h1, (size_t)MX * H_DIM, MX, H_DIM, 1, 0);                    // 3
    bn_split_kernel<<<KP1, 256>>>(us, unhi, unlo, MU, DU);                          // 4
    // L2x: h2 concat [m][net*d]
    hmma_gemm_kernel<false><<<dim3(MX / 128, 2, K_NETS), 256, SMEM_F>>>(
        h1, nullptr, (size_t)MX * H_DIM, H_DIM, H_DIM,
        w2xh, w2xl, (size_t)H_DIM * H_DIM, H_DIM,
        xb2, nullptr, h2, 0, MX, H_DIM, 1, 1);                                      // 5
    // phisum split-K concat GEMM
    hmma_gemm_kernel<false><<<dim3(MX / 128, 1, NGRP), 256, SMEM_F>>>(
        h2, nullptr, (size_t)KGRP, KCAT, KGRP,
        w3xh, w3xl, (size_t)KGRP, KCAT,
        nullptr, phisum_part, nullptr, (size_t)MX * L_DIM, MX, L_DIM, 0, 0);        // 6
    phi0_kernel<<<dim3(K_NETS, 4), 256, 2 * 128 * W3P * 2>>>(h2, w3xh, w3xl, phi0); // 7
    reduce16_kernel<<<MX, L_DIM>>>(phisum_part, phisum);                            // 8

    // ---- u path ----
    prep_w1_split_kernel<<<K_NETS, H_DIM>>>(u_gamma, u_beta, uW1, ub1,
                                            w1uh, w1ul, b1eu, DU);                  // 9
    transpose_split2_kernel<<<dim3(96, K_NETS), tb>>>(
        uW2, w2uh, w2ul, uW3, w3uh, w3ul, u_scale, 0);                              // 10
    hmma_gemm_kernel<true><<<dim3(32, 2, K_NETS), 256, SMEM_T>>>(
        unhi, unlo, 0, KP1, KP1, w1uh, w1ul, (size_t)H_DIM * KP1, KP1,
        b1eu, nullptr, h1, (size_t)MU * H_DIM, MU, H_DIM, 1, 0);                    // 11
    hmma_gemm_kernel<false><<<dim3(32, 2, K_NETS), 256, SMEM_F>>>(
        h1, nullptr, (size_t)MU * H_DIM, H_DIM, H_DIM,
        w2uh, w2ul, (size_t)H_DIM * H_DIM, H_DIM,
        ub2, nullptr, h2, (size_t)MU * H_DIM, MU, H_DIM, 1, 0);                     // 12
    hmma_gemm_kernel<false><<<dim3(32, 1, K_NETS), 256, SMEM_F>>>(
        h2, nullptr, (size_t)MU * H_DIM, H_DIM, H_DIM,
        w3uh, w3ul, (size_t)L_DIM * H_DIM, H_DIM,
        nullptr, psi, nullptr, 0, MU, L_DIM, 0, 1);                                 // 13: psi [bt][net][L]

    psi0_kernel<<<K_NETS, H_DIM>>>(b1eu, uW2, ub2, uW3, u_scale, psi0);             // 14
    scan_kernel<<<2 * N_B, 256>>>(phi0, psi, psi0, reL, imL, predsum2);             // 15
    decode_kernel<<<N_B * TM1, 256>>>(phisum, predsum2, C_W, out);                  // 16
}

// round 13
// speedup vs baseline: 1.7784x; 1.0468x over previous
#include <cuda_runtime.h>
#include <cuda_fp16.h>
#include <cstdint>
#include <cstddef>

// ---------------- problem dims (fixed) ----------------
#define N_B    64
#define T_DIM  64
#define TM1    63
#define DX     16
#define DU     8
#define H_DIM  256
#define L_DIM  128
#define K_NETS 64
#define MX     (N_B * T_DIM)   // 4096
#define MU     (N_B * TM1)     // 4032
#define KP1    32

// ---------------- scratch (device globals) ----------------
__device__ __half g_xnhi[MX * KP1];
__device__ __half g_xnlo[MX * KP1];
__device__ __half g_unhi[MU * KP1];
__device__ __half g_unlo[MU * KP1];
__device__ float g_b1ex[K_NETS * H_DIM];
__device__ float g_b1eu[K_NETS * H_DIM];
__device__ __half g_w1xh[K_NETS * H_DIM * KP1];
__device__ __half g_w1xl[K_NETS * H_DIM * KP1];
__device__ __half g_w1uh[K_NETS * H_DIM * KP1];
__device__ __half g_w1ul[K_NETS * H_DIM * KP1];
__device__ __half g_h1[(size_t)K_NETS * MX * H_DIM];
__device__ __half g_h2[(size_t)K_NETS * MX * H_DIM];
__device__ __half g_w2xt_hi[(size_t)K_NETS * H_DIM * H_DIM];
__device__ __half g_w2xt_lo[(size_t)K_NETS * H_DIM * H_DIM];
__device__ __half g_w3xt_hi[(size_t)K_NETS * L_DIM * H_DIM];  // [net][n][d], scale folded
__device__ __half g_w3xt_lo[(size_t)K_NETS * L_DIM * H_DIM];
__device__ __half g_w2ut_hi[(size_t)K_NETS * H_DIM * H_DIM];
__device__ __half g_w2ut_lo[(size_t)K_NETS * H_DIM * H_DIM];
__device__ __half g_w3ut_hi[(size_t)K_NETS * L_DIM * H_DIM];  // [net][n][d], scale folded
__device__ __half g_w3ut_lo[(size_t)K_NETS * L_DIM * H_DIM];
__device__ float g_phi[(size_t)MX * K_NETS * L_DIM];      // [m][net][L]
__device__ float g_psi[(size_t)MU * K_NETS * L_DIM];      // [bt][net][L]
__device__ float g_psi0[K_NETS * L_DIM];
__device__ float g_phisum[MX * L_DIM];
__device__ float g_predsum2[2 * N_B * TM1 * L_DIM];

// ---------------- BN + fp16 hi/lo split ----------------
__global__ void bn_split_kernel(const float* __restrict__ x,
                                __half* __restrict__ Ahi, __half* __restrict__ Alo,
                                int M, int D) {
    int d = blockIdx.x;
    int tid = threadIdx.x;
    if (d >= D) {
        for (int m = tid; m < M; m += 256) {
            Ahi[(size_t)m * KP1 + d] = __float2half(0.f);
            Alo[(size_t)m * KP1 + d] = __float2half(0.f);
        }
        return;
    }
    __shared__ float r1[256], r2[256];
    float s = 0.f, s2 = 0.f;
    for (int m = tid; m < M; m += 256) {
        float v = x[(size_t)m * D + d];
        s += v; s2 += v * v;
    }
    r1[tid] = s; r2[tid] = s2;
    __syncthreads();
    for (int o = 128; o > 0; o >>= 1) {
        if (tid < o) { r1[tid] += r1[tid + o]; r2[tid] += r2[tid + o]; }
        __syncthreads();
    }
    float mu = r1[0] / M;
    float var = r2[0] / M - mu * mu;
    float rstd = rsqrtf(var + 1e-5f);
    for (int m = tid; m < M; m += 256) {
        float v = (x[(size_t)m * D + d] - mu) * rstd;
        __half h = __float2half(v);
        Ahi[(size_t)m * KP1 + d] = h;
        Alo[(size_t)m * KP1 + d] = __float2half(v - __half2float(h));
    }
}

// ---------------- fold BN affine into layer-1, transpose, split ----------------
__global__ void prep_w1_split_kernel(const float* __restrict__ g, const float* __restrict__ be,
                                     const float* __restrict__ W1, const float* __restrict__ b1,
                                     __half* __restrict__ Thi, __half* __restrict__ Tlo,
                                     float* __restrict__ beff, int D) {
    int k = blockIdx.x;
    int h = threadIdx.x;
    float bacc = b1[k * H_DIM + h];
    for (int d = 0; d < KP1; d++) {
        float v = 0.f;
        if (d < D) {
            float w = W1[((size_t)k * D + d) * H_DIM + h];
            v = g[k * D + d] * w;
            bacc += be[k * D + d] * w;
        }
        __half hi = __float2half(v);
        size_t o = ((size_t)k * H_DIM + h) * KP1 + d;
        Thi[o] = hi;
        Tlo[o] = __float2half(v - __half2float(hi));
    }
    beff[k * H_DIM + h] = bacc;
}

// ---------------- W2 + W3 transpose + split; W3 scale folded, [net][n][d] ----------------
__global__ void transpose_split2_kernel(const float* __restrict__ W2,
                                        __half* __restrict__ T2h, __half* __restrict__ T2l,
                                        const float* __restrict__ W3,
                                        __half* __restrict__ T3h, __half* __restrict__ T3l,
                                        const float* __restrict__ scale3) {
    __shared__ float tile[32][33];
    int k = blockIdx.y;
    int idx = blockIdx.x;
    if (idx < 64) {
        const float* W = W2 + (size_t)k * H_DIM * H_DIM;
        int kk0 = (idx >> 3) * 32, n0 = (idx & 7) * 32;
        for (int r = threadIdx.y; r < 32; r += 8)
            tile[r][threadIdx.x] = W[(size_t)(kk0 + r) * H_DIM + n0 + threadIdx.x];
        __syncthreads();
        for (int r = threadIdx.y; r < 32; r += 8) {
            int n = n0 + r, kk = kk0 + threadIdx.x;
            float v = tile[threadIdx.x][r];
            __half h = __float2half(v);
            size_t o = ((size_t)k * H_DIM + n) * H_DIM + kk;
            T2h[o] = h;
            T2l[o] = __float2half(v - __half2float(h));
        }
    } else {
        idx -= 64;
        const float* W = W3 + (size_t)k * H_DIM * L_DIM;
        int kk0 = (idx >> 2) * 32, n0 = (idx & 3) * 32;
        for (int r = threadIdx.y; r < 32; r += 8)
            tile[r][threadIdx.x] = W[(size_t)(kk0 + r) * L_DIM + n0 + threadIdx.x];
        __syncthreads();
        for (int r = threadIdx.y; r < 32; r += 8) {
            int n = n0 + r, kk = kk0 + threadIdx.x;
            float v = tile[threadIdx.x][r] * scale3[k * L_DIM + n];
            __half h = __float2half(v);
            size_t o = ((size_t)k * L_DIM + n) * H_DIM + kk;
            T3h[o] = h;
            T3l[o] = __float2half(v - __half2float(h));
        }
    }
}

// ================= R8-geometry HMMA GEMM, templated BK =================
__device__ __forceinline__ void cp16(void* dst, const void* src, bool pred) {
    uint32_t d = (uint32_t)__cvta_generic_to_shared(dst);
    int n = pred ? 16 : 0;
    asm volatile("cp.async.cg.shared.global [%0], [%1], 16, %2;" :: "r"(d), "l"(src), "r"(n));
}
#define CP_COMMIT() asm volatile("cp.async.commit_group;")
#define CP_WAIT(N)  asm volatile("cp.async.wait_group %0;" :: "n"(N))

__device__ __forceinline__ void ldsm_x4(uint32_t* r, const void* p) {
    uint32_t a = (uint32_t)__cvta_generic_to_shared(p);
    asm volatile("ldmatrix.sync.aligned.m8n8.x4.shared.b16 {%0,%1,%2,%3}, [%4];"
                 : "=r"(r[0]), "=r"(r[1]), "=r"(r[2]), "=r"(r[3]) : "r"(a));
}
#define MMA16816(d, a, b0, b1) \
    asm volatile("mma.sync.aligned.m16n8k16.row.col.f32.f16.f16.f32 " \
                 "{%0,%1,%2,%3},{%4,%5,%6,%7},{%8,%9},{%0,%1,%2,%3};" \
                 : "+f"((d)[0]), "+f"((d)[1]), "+f"((d)[2]), "+f"((d)[3]) \
                 : "r"((a)[0]), "r"((a)[1]), "r"((a)[2]), "r"((a)[3]), \
                   "r"(b0), "r"(b1))

template <bool ASPLIT, int BK>
__global__ void __launch_bounds__(256, 2)
hmma_gemm_kernel(const __half* __restrict__ Ahi, const __half* __restrict__ Alo,
                 size_t strideA, int lda, int KdPad,
                 const __half* __restrict__ Bhi, const __half* __restrict__ Blo,
                 size_t strideB, int ldb,
                 const float* __restrict__ bias,
                 float* __restrict__ Cf, __half* __restrict__ Ch, size_t strideC,
                 int Mrows, int Nfull, int leaky, int tposeF) {
    extern __shared__ char smem[];
    constexpr int NPL = ASPLIT ? 4 : 3;               // planes: Ah [Al] Bh Bl
    constexpr int STR = BK + 8;                       // halves
    constexpr int PLANE_H = 128 * STR;                // halves per plane

    int tid = threadIdx.x;
    int lane = tid & 31, wid = tid >> 5;
    int wm = wid >> 1, wn = wid & 1;
    int z = blockIdx.z;
    int m0 = blockIdx.x * 128, n0 = blockIdx.y * 128;

    const __half* Ah = Ahi + strideA * z;
    const __half* Al = ASPLIT ? (Alo + strideA * z) : nullptr;
    const __half* Bh = Bhi + strideB * z + (size_t)n0 * ldb;
    const __half* Bl = Blo + strideB * z + (size_t)n0 * ldb;

    auto plane = [&](int p, int s) -> __half* {
        return reinterpret_cast<__half*>(smem) + (p * 2 + s) * PLANE_H;
    };

    int rowL = tid >> 1;
    int kkL = (tid & 1) * 16;
    bool aOk = (m0 + rowL) < Mrows;
    const __half* gA_h = Ah + (size_t)(m0 + rowL) * lda + kkL;
    const __half* gA_l = ASPLIT ? (Al + (size_t)(m0 + rowL) * lda + kkL) : nullptr;
    const __half* gB_h = Bh + (size_t)rowL * ldb + kkL;
    const __half* gB_l = Bl + (size_t)rowL * ldb + kkL;
    int soff = rowL * STR + kkL;

    int nk = KdPad / BK;

    auto load_stage = [&](int s, int c) {
#pragma unroll
        for (int seg = 0; seg < BK / 32; seg++) {
            int k0 = c * BK + seg * 32;
            int so = soff + seg * 32;
            cp16(plane(0, s) + so,     gA_h + k0,     aOk);
            cp16(plane(0, s) + so + 8, gA_h + k0 + 8, aOk);
            if (ASPLIT) {
                cp16(plane(1, s) + so,     gA_l + k0,     aOk);
                cp16(plane(1, s) + so + 8, gA_l + k0 + 8, aOk);
            }
            cp16(plane(NPL - 2, s) + so,     gB_h + k0,     true);
            cp16(plane(NPL - 2, s) + so + 8, gB_h + k0 + 8, true);
            cp16(plane(NPL - 1, s) + so,     gB_l + k0,     true);
            cp16(plane(NPL - 1, s) + so + 8, gB_l + k0 + 8, true);
        }
        CP_COMMIT();
    };

    float acc[2][8][4];
#pragma unroll
    for (int mi = 0; mi < 2; mi++)
#pragma unroll
        for (int ni = 0; ni < 8; ni++)
#pragma unroll
            for (int i = 0; i < 4; i++) acc[mi][ni][i] = 0.f;

    int aRow = wm * 32 + (lane & 15);
    int aCol = (lane >> 4) * 8;
    int bRow = wn * 64 + (lane >> 4) * 8 + (lane & 7);
    int bCol = ((lane >> 3) & 1) * 8;
    int g = lane >> 2, t = lane & 3;

    load_stage(0, 0);

    for (int c = 0; c < nk; c++) {
        int s = c & 1;
        if (c + 1 < nk) {
            load_stage(s ^ 1, c + 1);
            CP_WAIT(1);
        } else {
            CP_WAIT(0);
        }
        __syncthreads();

        const __half* pAh = plane(0, s);
        const __half* pAl = plane(1, s);
        const __half* pBh = plane(NPL - 2, s);
        const __half* pBl = plane(NPL - 1, s);

#pragma unroll
        for (int ks = 0; ks < BK / 16; ks++) {
            uint32_t ah[2][4], al[2][4];
#pragma unroll
            for (int mi = 0; mi < 2; mi++) {
                ldsm_x4(ah[mi], pAh + (aRow + mi * 16) * STR + ks * 16 + aCol);
                if (ASPLIT)
                    ldsm_x4(al[mi], pAl + (aRow + mi * 16) * STR + ks * 16 + aCol);
            }
#pragma unroll
            for (int q = 0; q < 4; q++) {
                uint32_t rh[4], rl[4];
                ldsm_x4(rh, pBh + (bRow + q * 16) * STR + ks * 16 + bCol);
                ldsm_x4(rl, pBl + (bRow + q * 16) * STR + ks * 16 + bCol);
#pragma unroll
                for (int p = 0; p < 2; p++) {
                    int ni = 2 * q + p;
#pragma unroll
                    for (int mi = 0; mi < 2; mi++) {
                        MMA16816(acc[mi][ni], ah[mi], rh[2 * p], rh[2 * p + 1]);
                        MMA16816(acc[mi][ni], ah[mi], rl[2 * p], rl[2 * p + 1]);
                        if (ASPLIT)
                            MMA16816(acc[mi][ni], al[mi], rh[2 * p], rh[2 * p + 1]);
                    }
                }
            }
        }
        __syncthreads();
    }

    // ---- epilogue ----
#pragma unroll
    for (int mi = 0; mi < 2; mi++) {
#pragma unroll
        for (int ni = 0; ni < 8; ni++) {
            int col = n0 + wn * 64 + ni * 8 + 2 * t;
            float b0 = 0.f, b1v = 0.f;
            if (bias) {
                b0 = bias[(size_t)z * Nfull + col];
                b1v = bias[(size_t)z * Nfull + col + 1];
            }
#pragma unroll
            for (int h = 0; h < 2; h++) {
                int row = m0 + wm * 32 + mi * 16 + g + h * 8;
                if (row >= Mrows) continue;
                float v0 = acc[mi][ni][2 * h] + b0;
                float v1 = acc[mi][ni][2 * h + 1] + b1v;
                if (leaky) {
                    v0 = v0 > 0.f ? v0 : 0.01f * v0;
                    v1 = v1 > 0.f ? v1 : 0.01f * v1;
                }
                size_t o = tposeF
                    ? ((size_t)row * K_NETS + z) * Nfull + col
                    : strideC * z + (size_t)row * Nfull + col;
                if (Cf) {
                    *reinterpret_cast<float2*>(&Cf[o]) = make_float2(v0, v1);
                } else {
                    *reinterpret_cast<__half2*>(&Ch[o]) = __floats2half2_rn(v0, v1);
                }
            }
        }
    }
}

#define SMEM_T (4 * 2 * 128 * (32 + 8) * 2)   // ASPLIT=true,  BK=32: 81920
#define SMEM_F (3 * 2 * 128 * (64 + 8) * 2)   // ASPLIT=false, BK=64: 110592

// ---------------- sum over net axis (phi [m][net][L]) ----------------
__global__ void sum_nets_kernel(const float* __restrict__ phi, float* __restrict__ out, int M) {
    int m = blockIdx.x;
    int l = threadIdx.x;
    const float* base = phi + (size_t)m * K_NETS * L_DIM + l;
    float s = 0.f;
#pragma unroll 8
    for (int j = 0; j < K_NETS; j++) s += base[j * L_DIM];
    out[(size_t)m * L_DIM + l] = s;
}

// ---------------- psi(0) exact fp32 ----------------
__global__ void psi0_kernel(const float* __restrict__ b1eff, const float* __restrict__ W2,
                            const float* __restrict__ b2, const float* __restrict__ W3,
                            const float* __restrict__ scale, float* __restrict__ psi0) {
    int k = blockIdx.x;
    int t = threadIdx.x;
    __shared__ float h1[H_DIM], h2[H_DIM];
    float v = b1eff[k * H_DIM + t];
    h1[t] = v > 0.f ? v : 0.01f * v;
    __syncthreads();
    float a = b2[k * H_DIM + t];
    for (int d = 0; d < H_DIM; d++)
        a += h1[d] * W2[((size_t)k * H_DIM + d) * H_DIM + t];
    h2[t] = a > 0.f ? a : 0.01f * a;
    __syncthreads();
    if (t < L_DIM) {
        float s = 0.f;
        for (int d = 0; d < H_DIM; d++)
            s += h2[d] * W3[((size_t)k * H_DIM + d) * L_DIM + t];
        psi0[k * L_DIM + t] = s * scale[k * L_DIM + t];
    }
}

// ---------------- scan: 2 blocks per batch ----------------
__global__ void __launch_bounds__(256)
scan_kernel(const float* __restrict__ phi,   // [m][net][L]
            const float* __restrict__ psi,   // [bt][net][L]
            const float* __restrict__ psi0,
            const float* __restrict__ reL, const float* __restrict__ imL,
            float* __restrict__ predsum2) {
    int bid = blockIdx.x;
    int b = bid >> 1;
    int sel = bid & 1;
    int j0 = sel * 32;
    int tid = threadIdx.x;
    __shared__ float ps[32 * L_DIM];
    __shared__ float rsh[K_NETS], ish[K_NETS];
    if (tid < K_NETS) { rsh[tid] = reL[tid]; ish[tid] = imL[tid]; }

    float px[8], py[8], rj[8], ij[8], u0x[8], u0y[8];
    const float* phiB = phi + ((size_t)(b * T_DIM) * K_NETS + j0) * L_DIM;
    const float* psi0B = psi0 + (size_t)j0 * L_DIM;
#pragma unroll
    for (int q = 0; q < 8; q++) {
        int e = q * 256 + tid;
        float2 v = *reinterpret_cast<const float2*>(&phiB[e * 2]);
        px[q] = v.x; py[q] = v.y;
        float2 zz = *reinterpret_cast<const float2*>(&psi0B[e * 2]);
        u0x[q] = zz.x; u0y[q] = zz.y;
    }
    __syncthreads();
#pragma unroll
    for (int q = 0; q < 8; q++) {
        int j = j0 + ((q * 256 + tid) >> 6);
        rj[q] = rsh[j]; ij[q] = ish[j];
    }

    for (int t = 0; t < TM1; t++) {
        const float* psiT = psi + ((size_t)(b * TM1 + t) * K_NETS + j0) * L_DIM;
#pragma unroll
        for (int q = 0; q < 8; q++) {
            int e = q * 256 + tid;
            float2 u = *reinterpret_cast<const float2*>(&psiT[e * 2]);
            float vx = px[q] + u.x - u0x[q];
            float vy = py[q] + u.y - u0y[q];
            px[q] = vx * rj[q] - vy * ij[q];
            py[q] = vx * ij[q] + vy * rj[q];
            ps[e * 2]     = px[q];
            ps[e * 2 + 1] = py[q];
        }
        __syncthreads();
        if (tid < L_DIM) {
            float s = 0.f;
#pragma unroll 8
            for (int j = 0; j < 32; j++) s += ps[j * L_DIM + tid];
            predsum2[(((size_t)sel * N_B + b) * TM1 + t) * L_DIM + tid] = s;
        }
        __syncthreads();
    }
}

// ---------------- decode ----------------
__global__ void decode_kernel(const float* __restrict__ phisum,
                              const float* __restrict__ predsum2,
                              const float* __restrict__ C_W,
                              float* __restrict__ out) {
    __shared__ float Cs[DX * L_DIM];
    __shared__ float rowY[L_DIM], rowP[L_DIM];
    int bt = blockIdx.x;
    int b = bt / TM1, t = bt % TM1;
    int tid = threadIdx.x;
    for (int i = tid; i < DX * L_DIM; i += 256) Cs[i] = C_W[i];
    if (tid < L_DIM)
        rowY[tid] = phisum[((size_t)(b * T_DIM + t + 1)) * L_DIM + tid];
    else {
        int l = tid - L_DIM;
        rowP[l] = predsum2[(size_t)bt * L_DIM + l]
                + predsum2[((size_t)N_B * TM1 + bt) * L_DIM + l];
    }
    __syncthreads();
    if (tid < 2 * DX) {
        int sel = tid >> 4, d = tid & 15;
        const float* row = sel ? rowP : rowY;
        float s = 0.f;
        for (int l = 0; l < L_DIM; l++) s += row[l] * Cs[d * L_DIM + l];
        out[(size_t)sel * N_B * TM1 * DX + (size_t)bt * DX + d] = s;
    }
}

// ---------------- launcher ----------------
extern "C" void kernel_launch(void* const* d_in, const int* in_sizes, int n_in,
                              void* d_out, int out_size) {
    const float* xs      = (const float*)d_in[0];
    const float* us      = (const float*)d_in[1];
    const float* x_gamma = (const float*)d_in[2];
    const float* x_beta  = (const float*)d_in[3];
    const float* xW1     = (const float*)d_in[4];
    const float* xb1     = (const float*)d_in[5];
    const float* xW2     = (const float*)d_in[6];
    const float* xb2     = (const float*)d_in[7];
    const float* xW3     = (const float*)d_in[8];
    const float* x_scale = (const float*)d_in[9];
    const float* u_gamma = (const float*)d_in[10];
    const float* u_beta  = (const float*)d_in[11];
    const float* uW1     = (const float*)d_in[12];
    const float* ub1     = (const float*)d_in[13];
    const float* uW2     = (const float*)d_in[14];
    const float* ub2     = (const float*)d_in[15];
    const float* uW3     = (const float*)d_in[16];
    const float* u_scale = (const float*)d_in[17];
    const float* reL     = (const float*)d_in[18];
    const float* imL     = (const float*)d_in[19];
    const float* C_W     = (const float*)d_in[20];
    float* out = (float*)d_out;

    float *b1ex, *b1eu, *phi, *psi, *psi0, *phisum, *predsum2;
    __half *xnhi, *xnlo, *unhi, *unlo, *w1xh, *w1xl, *w1uh, *w1ul;
    __half *h1, *h2;
    __half *w2xh, *w2xl, *w3xh, *w3xl, *w2uh, *w2ul, *w3uh, *w3ul;
    cudaGetSymbolAddress((void**)&xnhi, g_xnhi);
    cudaGetSymbolAddress((void**)&xnlo, g_xnlo);
    cudaGetSymbolAddress((void**)&unhi, g_unhi);
    cudaGetSymbolAddress((void**)&unlo, g_unlo);
    cudaGetSymbolAddress((void**)&b1ex, g_b1ex);
    cudaGetSymbolAddress((void**)&b1eu, g_b1eu);
    cudaGetSymbolAddress((void**)&w1xh, g_w1xh);
    cudaGetSymbolAddress((void**)&w1xl, g_w1xl);
    cudaGetSymbolAddress((void**)&w1uh, g_w1uh);
    cudaGetSymbolAddress((void**)&w1ul, g_w1ul);
    cudaGetSymbolAddress((void**)&h1, g_h1);
    cudaGetSymbolAddress((void**)&h2, g_h2);
    cudaGetSymbolAddress((void**)&w2xh, g_w2xt_hi);
    cudaGetSymbolAddress((void**)&w2xl, g_w2xt_lo);
    cudaGetSymbolAddress((void**)&w3xh, g_w3xt_hi);
    cudaGetSymbolAddress((void**)&w3xl, g_w3xt_lo);
    cudaGetSymbolAddress((void**)&w2uh, g_w2ut_hi);
    cudaGetSymbolAddress((void**)&w2ul, g_w2ut_lo);
    cudaGetSymbolAddress((void**)&w3uh, g_w3ut_hi);
    cudaGetSymbolAddress((void**)&w3ul, g_w3ut_lo);
    cudaGetSymbolAddress((void**)&phi, g_phi);
    cudaGetSymbolAddress((void**)&psi, g_psi);
    cudaGetSymbolAddress((void**)&psi0, g_psi0);
    cudaGetSymbolAddress((void**)&phisum, g_phisum);
    cudaGetSymbolAddress((void**)&predsum2, g_predsum2);

    cudaFuncSetAttribute((const void*)hmma_gemm_kernel<true, 32>,
                         cudaFuncAttributeMaxDynamicSharedMemorySize, SMEM_T);
    cudaFuncSetAttribute((const void*)hmma_gemm_kernel<false, 64>,
                         cudaFuncAttributeMaxDynamicSharedMemorySize, SMEM_F);

    dim3 tb(32, 8);
    // ---- x path ----
    bn_split_kernel<<<KP1, 256>>>(xs, xnhi, xnlo, MX, DX);                          // 0
    prep_w1_split_kernel<<<K_NETS, H_DIM>>>(x_gamma, x_beta, xW1, xb1,
                                            w1xh, w1xl, b1ex, DX);                  // 1
    transpose_split2_kernel<<<dim3(96, K_NETS), tb>>>(
        xW2, w2xh, w2xl, xW3, w3xh, w3xl, x_scale);                                 // 2
    hmma_gemm_kernel<true, 32><<<dim3(MX / 128, 2, K_NETS), 256, SMEM_T>>>(
        xnhi, xnlo, 0, KP1, KP1, w1xh, w1xl, (size_t)H_DIM * KP1, KP1,
        b1ex, nullptr, h1, (size_t)MX * H_DIM, MX, H_DIM, 1, 0);                    // 3: L1x
    bn_split_kernel<<<KP1, 256>>>(us, unhi, unlo, MU, DU);                          // 4
    hmma_gemm_kernel<false, 64><<<dim3(MX / 128, 2, K_NETS), 256, SMEM_F>>>(
        h1, nullptr, (size_t)MX * H_DIM, H_DIM, H_DIM,
        w2xh, w2xl, (size_t)H_DIM * H_DIM, H_DIM,
        xb2, nullptr, h2, (size_t)MX * H_DIM, MX, H_DIM, 1, 0);                     // 5: L2x
    hmma_gemm_kernel<false, 64><<<dim3(MX / 128, 1, K_NETS), 256, SMEM_F>>>(
        h2, nullptr, (size_t)MX * H_DIM, H_DIM, H_DIM,
        w3xh, w3xl, (size_t)L_DIM * H_DIM, H_DIM,
        nullptr, phi, nullptr, 0, MX, L_DIM, 0, 1);                                 // 6: L3x -> [m][net][L]
    sum_nets_kernel<<<MX, L_DIM>>>(phi, phisum, MX);                                // 7

    // ---- u path ----
    prep_w1_split_kernel<<<K_NETS, H_DIM>>>(u_gamma, u_beta, uW1, ub1,
                                            w1uh, w1ul, b1eu, DU);                  // 8
    transpose_split2_kernel<<<dim3(96, K_NETS), tb>>>(
        uW2, w2uh, w2ul, uW3, w3uh, w3ul, u_scale);                                 // 9
    hmma_gemm_kernel<true, 32><<<dim3(32, 2, K_NETS), 256, SMEM_T>>>(
        unhi, unlo, 0, KP1, KP1, w1uh, w1ul, (size_t)H_DIM * KP1, KP1,
        b1eu, nullptr, h1, (size_t)MU * H_DIM, MU, H_DIM, 1, 0);                    // 10
    hmma_gemm_kernel<false, 64><<<dim3(32, 2, K_NETS), 256, SMEM_F>>>(
        h1, nullptr, (size_t)MU * H_DIM, H_DIM, H_DIM,
        w2uh, w2ul, (size_t)H_DIM * H_DIM, H_DIM,
        ub2, nullptr, h2, (size_t)MU * H_DIM, MU, H_DIM, 1, 0);                     // 11
    hmma_gemm_kernel<false, 64><<<dim3(32, 1, K_NETS), 256, SMEM_F>>>(
        h2, nullptr, (size_t)MU * H_DIM, H_DIM, H_DIM,
        w3uh, w3ul, (size_t)L_DIM * H_DIM, H_DIM,
        nullptr, psi, nullptr, 0, MU, L_DIM, 0, 1);                                 // 12: psi [bt][net][L]

    psi0_kernel<<<K_NETS, H_DIM>>>(b1eu, uW2, ub2, uW3, u_scale, psi0);             // 13
    scan_kernel<<<2 * N_B, 256>>>(phi, psi, psi0, reL, imL, predsum2);              // 14
    decode_kernel<<<N_B * TM1, 256>>>(phisum, predsum2, C_W, out);                  // 15
}

// round 14
// speedup vs baseline: 1.8764x; 1.0551x over previous
#include <cuda_runtime.h>
#include <cuda_fp16.h>
#include <cstdint>
#include <cstddef>

// ---------------- problem dims (fixed) ----------------
#define N_B    64
#define T_DIM  64
#define TM1    63
#define DX     16
#define DU     8
#define H_DIM  256
#define L_DIM  128
#define K_NETS 64
#define MX     (N_B * T_DIM)   // 4096
#define MU     (N_B * TM1)     // 4032
#define KP1    32
#define L1_MT  4               // m-tiles per L1 block

// ---------------- scratch (device globals) ----------------
__device__ __half g_xnhi[MX * KP1];
__device__ __half g_xnlo[MX * KP1];
__device__ __half g_unhi[MU * KP1];
__device__ __half g_unlo[MU * KP1];
__device__ float g_b1ex[K_NETS * H_DIM];
__device__ float g_b1eu[K_NETS * H_DIM];
__device__ __half g_w1xh[K_NETS * H_DIM * KP1];
__device__ __half g_w1xl[K_NETS * H_DIM * KP1];
__device__ __half g_w1uh[K_NETS * H_DIM * KP1];
__device__ __half g_w1ul[K_NETS * H_DIM * KP1];
__device__ __half g_h1[(size_t)K_NETS * MX * H_DIM];
__device__ __half g_h2[(size_t)K_NETS * MX * H_DIM];
__device__ __half g_w2xt_hi[(size_t)K_NETS * H_DIM * H_DIM];
__device__ __half g_w2xt_lo[(size_t)K_NETS * H_DIM * H_DIM];
__device__ __half g_w3xt_hi[(size_t)K_NETS * L_DIM * H_DIM];  // [net][n][d], scale folded
__device__ __half g_w3xt_lo[(size_t)K_NETS * L_DIM * H_DIM];
__device__ __half g_w2ut_hi[(size_t)K_NETS * H_DIM * H_DIM];
__device__ __half g_w2ut_lo[(size_t)K_NETS * H_DIM * H_DIM];
__device__ __half g_w3ut_hi[(size_t)K_NETS * L_DIM * H_DIM];
__device__ __half g_w3ut_lo[(size_t)K_NETS * L_DIM * H_DIM];
__device__ __half g_phi_h[(size_t)MX * K_NETS * L_DIM];   // fp16 [m][net][L]
__device__ float g_psi[(size_t)MU * K_NETS * L_DIM];      // [bt][net][L]
__device__ float g_psi0[K_NETS * L_DIM];
__device__ float g_phisum[MX * L_DIM];
__device__ float g_predsum2[2 * N_B * TM1 * L_DIM];

// ---------------- BN + fp16 hi/lo split ----------------
__global__ void bn_split_kernel(const float* __restrict__ x,
                                __half* __restrict__ Ahi, __half* __restrict__ Alo,
                                int M, int D) {
    int d = blockIdx.x;
    int tid = threadIdx.x;
    if (d >= D) {
        for (int m = tid; m < M; m += 256) {
            Ahi[(size_t)m * KP1 + d] = __float2half(0.f);
            Alo[(size_t)m * KP1 + d] = __float2half(0.f);
        }
        return;
    }
    __shared__ float r1[256], r2[256];
    float s = 0.f, s2 = 0.f;
    for (int m = tid; m < M; m += 256) {
        float v = x[(size_t)m * D + d];
        s += v; s2 += v * v;
    }
    r1[tid] = s; r2[tid] = s2;
    __syncthreads();
    for (int o = 128; o > 0; o >>= 1) {
        if (tid < o) { r1[tid] += r1[tid + o]; r2[tid] += r2[tid + o]; }
        __syncthreads();
    }
    float mu = r1[0] / M;
    float var = r2[0] / M - mu * mu;
    float rstd = rsqrtf(var + 1e-5f);
    for (int m = tid; m < M; m += 256) {
        float v = (x[(size_t)m * D + d] - mu) * rstd;
        __half h = __float2half(v);
        Ahi[(size_t)m * KP1 + d] = h;
        Alo[(size_t)m * KP1 + d] = __float2half(v - __half2float(h));
    }
}

// ---------------- fold BN affine into layer-1, transpose, split ----------------
__global__ void prep_w1_split_kernel(const float* __restrict__ g, const float* __restrict__ be,
                                     const float* __restrict__ W1, const float* __restrict__ b1,
                                     __half* __restrict__ Thi, __half* __restrict__ Tlo,
                                     float* __restrict__ beff, int D) {
    int k = blockIdx.x;
    int h = threadIdx.x;
    float bacc = b1[k * H_DIM + h];
    for (int d = 0; d < KP1; d++) {
        float v = 0.f;
        if (d < D) {
            float w = W1[((size_t)k * D + d) * H_DIM + h];
            v = g[k * D + d] * w;
            bacc += be[k * D + d] * w;
        }
        __half hi = __float2half(v);
        size_t o = ((size_t)k * H_DIM + h) * KP1 + d;
        Thi[o] = hi;
        Tlo[o] = __float2half(v - __half2float(hi));
    }
    beff[k * H_DIM + h] = bacc;
}

// ---------------- W2 + W3 transpose + split; W3 scale folded ----------------
__global__ void transpose_split2_kernel(const float* __restrict__ W2,
                                        __half* __restrict__ T2h, __half* __restrict__ T2l,
                                        const float* __restrict__ W3,
                                        __half* __restrict__ T3h, __half* __restrict__ T3l,
                                        const float* __restrict__ scale3) {
    __shared__ float tile[32][33];
    int k = blockIdx.y;
    int idx = blockIdx.x;
    if (idx < 64) {
        const float* W = W2 + (size_t)k * H_DIM * H_DIM;
        int kk0 = (idx >> 3) * 32, n0 = (idx & 7) * 32;
        for (int r = threadIdx.y; r < 32; r += 8)
            tile[r][threadIdx.x] = W[(size_t)(kk0 + r) * H_DIM + n0 + threadIdx.x];
        __syncthreads();
        for (int r = threadIdx.y; r < 32; r += 8) {
            int n = n0 + r, kk = kk0 + threadIdx.x;
            float v = tile[threadIdx.x][r];
            __half h = __float2half(v);
            size_t o = ((size_t)k * H_DIM + n) * H_DIM + kk;
            T2h[o] = h;
            T2l[o] = __float2half(v - __half2float(h));
        }
    } else {
        idx -= 64;
        const float* W = W3 + (size_t)k * H_DIM * L_DIM;
        int kk0 = (idx >> 2) * 32, n0 = (idx & 3) * 32;
        for (int r = threadIdx.y; r < 32; r += 8)
            tile[r][threadIdx.x] = W[(size_t)(kk0 + r) * L_DIM + n0 + threadIdx.x];
        __syncthreads();
        for (int r = threadIdx.y; r < 32; r += 8) {
            int n = n0 + r, kk = kk0 + threadIdx.x;
            float v = tile[threadIdx.x][r] * scale3[k * L_DIM + n];
            __half h = __float2half(v);
            size_t o = ((size_t)k * L_DIM + n) * H_DIM + kk;
            T3h[o] = h;
            T3l[o] = __float2half(v - __half2float(h));
        }
    }
}

// ================= common GEMM helpers =================
__device__ __forceinline__ void cp16(void* dst, const void* src, bool pred) {
    uint32_t d = (uint32_t)__cvta_generic_to_shared(dst);
    int n = pred ? 16 : 0;
    asm volatile("cp.async.cg.shared.global [%0], [%1], 16, %2;" :: "r"(d), "l"(src), "r"(n));
}
#define CP_COMMIT() asm volatile("cp.async.commit_group;")
#define CP_WAIT(N)  asm volatile("cp.async.wait_group %0;" :: "n"(N))

__device__ __forceinline__ void ldsm_x4(uint32_t* r, const void* p) {
    uint32_t a = (uint32_t)__cvta_generic_to_shared(p);
    asm volatile("ldmatrix.sync.aligned.m8n8.x4.shared.b16 {%0,%1,%2,%3}, [%4];"
                 : "=r"(r[0]), "=r"(r[1]), "=r"(r[2]), "=r"(r[3]) : "r"(a));
}
#define MMA16816(d, a, b0, b1) \
    asm volatile("mma.sync.aligned.m16n8k16.row.col.f32.f16.f16.f32 " \
                 "{%0,%1,%2,%3},{%4,%5,%6,%7},{%8,%9},{%0,%1,%2,%3};" \
                 : "+f"((d)[0]), "+f"((d)[1]), "+f"((d)[2]), "+f"((d)[3]) \
                 : "r"((a)[0]), "r"((a)[1]), "r"((a)[2]), "r"((a)[3]), \
                   "r"(b0), "r"(b1))

// ================= L1 kernel: B-resident, 4 m-tiles per block, 3-term split =================
// A shared across nets (xn/un); B = W1 per net, K=32.
#define L1_STR 40
#define L1_PLH (128 * L1_STR)     // halves per plane
// smem layout (planes of L1_PLH halves): [0]=Bh [1]=Bl [2]=A0h [3]=A0l [4]=A1h [5]=A1l
#define SMEM_L1 (6 * L1_PLH * 2)  // 61440

__global__ void __launch_bounds__(256, 2)
hmma_l1_kernel(const __half* __restrict__ Ahi, const __half* __restrict__ Alo,
               const __half* __restrict__ Bhi, const __half* __restrict__ Blo,
               const float* __restrict__ bias,
               __half* __restrict__ Ch, size_t strideC, int Mrows) {
    extern __shared__ char smem[];
    auto plane = [&](int p) -> __half* {
        return reinterpret_cast<__half*>(smem) + p * L1_PLH;
    };
    int tid = threadIdx.x;
    int lane = tid & 31, wid = tid >> 5;
    int wm = wid >> 1, wn = wid & 1;
    int z = blockIdx.z;
    int n0 = blockIdx.y * 128;
    int mg = blockIdx.x;

    const __half* Bh = Bhi + ((size_t)z * H_DIM + n0) * KP1;
    const __half* Bl = Blo + ((size_t)z * H_DIM + n0) * KP1;

    int rowL = tid >> 1;
    int kkL = (tid & 1) * 16;
    int soff = rowL * L1_STR + kkL;

    // B resident load (group 0)
    cp16(plane(0) + soff,     Bh + (size_t)rowL * KP1 + kkL, true);
    cp16(plane(0) + soff + 8, Bh + (size_t)rowL * KP1 + kkL + 8, true);
    cp16(plane(1) + soff,     Bl + (size_t)rowL * KP1 + kkL, true);
    cp16(plane(1) + soff + 8, Bl + (size_t)rowL * KP1 + kkL + 8, true);
    CP_COMMIT();

    auto load_A = [&](int s, int mt) {
        int gm = (mg * L1_MT + mt) * 128 + rowL;
        bool aOk = gm < Mrows;
        const __half* pa = Ahi + (size_t)gm * KP1 + kkL;
        const __half* pl = Alo + (size_t)gm * KP1 + kkL;
        cp16(plane(2 + s * 2) + soff,     pa,     aOk);
        cp16(plane(2 + s * 2) + soff + 8, pa + 8, aOk);
        cp16(plane(3 + s * 2) + soff,     pl,     aOk);
        cp16(plane(3 + s * 2) + soff + 8, pl + 8, aOk);
        CP_COMMIT();
    };
    load_A(0, 0);

    int aRow = wm * 32 + (lane & 15);
    int aCol = (lane >> 4) * 8;
    int bRow = wn * 64 + (lane >> 4) * 8 + (lane & 7);
    int bCol = ((lane >> 3) & 1) * 8;
    int g = lane >> 2, t = lane & 3;

    for (int mt = 0; mt < L1_MT; mt++) {
        int s = mt & 1;
        if (mt + 1 < L1_MT) {
            load_A(s ^ 1, mt + 1);
            CP_WAIT(1);
        } else {
            CP_WAIT(0);
        }
        __syncthreads();

        float acc[2][8][4];
#pragma unroll
        for (int mi = 0; mi < 2; mi++)
#pragma unroll
            for (int ni = 0; ni < 8; ni++)
#pragma unroll
                for (int i = 0; i < 4; i++) acc[mi][ni][i] = 0.f;

        const __half* pAh = plane(2 + s * 2);
        const __half* pAl = plane(3 + s * 2);
        const __half* pBh = plane(0);
        const __half* pBl = plane(1);

#pragma unroll
        for (int ks = 0; ks < 2; ks++) {
            uint32_t ah[2][4], al[2][4];
#pragma unroll
            for (int mi = 0; mi < 2; mi++) {
                ldsm_x4(ah[mi], pAh + (aRow + mi * 16) * L1_STR + ks * 16 + aCol);
                ldsm_x4(al[mi], pAl + (aRow + mi * 16) * L1_STR + ks * 16 + aCol);
            }
#pragma unroll
            for (int q = 0; q < 4; q++) {
                uint32_t rh[4], rl[4];
                ldsm_x4(rh, pBh + (bRow + q * 16) * L1_STR + ks * 16 + bCol);
                ldsm_x4(rl, pBl + (bRow + q * 16) * L1_STR + ks * 16 + bCol);
#pragma unroll
                for (int p = 0; p < 2; p++) {
                    int ni = 2 * q + p;
#pragma unroll
                    for (int mi = 0; mi < 2; mi++) {
                        MMA16816(acc[mi][ni], ah[mi], rh[2 * p], rh[2 * p + 1]);
                        MMA16816(acc[mi][ni], ah[mi], rl[2 * p], rl[2 * p + 1]);
                        MMA16816(acc[mi][ni], al[mi], rh[2 * p], rh[2 * p + 1]);
                    }
                }
            }
        }

        // epilogue: leaky + fp16 store to h1 [net][m][d]
        int mbase = (mg * L1_MT + mt) * 128;
#pragma unroll
        for (int mi = 0; mi < 2; mi++) {
#pragma unroll
            for (int ni = 0; ni < 8; ni++) {
                int col = n0 + wn * 64 + ni * 8 + 2 * t;
                float b0 = bias[(size_t)z * H_DIM + col];
                float b1v = bias[(size_t)z * H_DIM + col + 1];
#pragma unroll
                for (int h = 0; h < 2; h++) {
                    int row = mbase + wm * 32 + mi * 16 + g + h * 8;
                    if (row >= Mrows) continue;
                    float v0 = acc[mi][ni][2 * h] + b0;
                    float v1 = acc[mi][ni][2 * h + 1] + b1v;
                    v0 = v0 > 0.f ? v0 : 0.01f * v0;
                    v1 = v1 > 0.f ? v1 : 0.01f * v1;
                    size_t o = strideC * z + (size_t)row * H_DIM + col;
                    *reinterpret_cast<__half2*>(&Ch[o]) = __floats2half2_rn(v0, v1);
                }
            }
        }
        __syncthreads();
    }
}

// ================= BK=64 streaming kernel for K=256 layers =================
template <int BK>
__global__ void __launch_bounds__(256, 2)
hmma_gemm_kernel(const __half* __restrict__ A, size_t strideA, int lda, int KdPad,
                 const __half* __restrict__ Bhi, const __half* __restrict__ Blo,
                 size_t strideB, int ldb,
                 const float* __restrict__ bias,
                 float* __restrict__ Cf, __half* __restrict__ Ch, size_t strideC,
                 int Mrows, int Nfull, int leaky, int tposeF) {
    extern __shared__ char smem[];
    constexpr int STR = BK + 8;
    constexpr int PLANE_H = 128 * STR;

    int tid = threadIdx.x;
    int lane = tid & 31, wid = tid >> 5;
    int wm = wid >> 1, wn = wid & 1;
    int z = blockIdx.z;
    int m0 = blockIdx.x * 128, n0 = blockIdx.y * 128;

    const __half* Ab = A + strideA * z;
    const __half* Bh = Bhi + strideB * z + (size_t)n0 * ldb;
    const __half* Bl = Blo + strideB * z + (size_t)n0 * ldb;

    auto plane = [&](int p, int s) -> __half* {
        return reinterpret_cast<__half*>(smem) + (p * 2 + s) * PLANE_H;
    };

    int rowL = tid >> 1;
    int kkL = (tid & 1) * 16;
    bool aOk = (m0 + rowL) < Mrows;
    const __half* gA = Ab + (size_t)(m0 + rowL) * lda + kkL;
    const __half* gB_h = Bh + (size_t)rowL * ldb + kkL;
    const __half* gB_l = Bl + (size_t)rowL * ldb + kkL;
    int soff = rowL * STR + kkL;

    int nk = KdPad / BK;

    auto load_stage = [&](int s, int c) {
#pragma unroll
        for (int seg = 0; seg < BK / 32; seg++) {
            int k0 = c * BK + seg * 32;
            int so = soff + seg * 32;
            cp16(plane(0, s) + so,     gA + k0,     aOk);
            cp16(plane(0, s) + so + 8, gA + k0 + 8, aOk);
            cp16(plane(1, s) + so,     gB_h + k0,     true);
            cp16(plane(1, s) + so + 8, gB_h + k0 + 8, true);
            cp16(plane(2, s) + so,     gB_l + k0,     true);
            cp16(plane(2, s) + so + 8, gB_l + k0 + 8, true);
        }
        CP_COMMIT();
    };

    float acc[2][8][4];
#pragma unroll
    for (int mi = 0; mi < 2; mi++)
#pragma unroll
        for (int ni = 0; ni < 8; ni++)
#pragma unroll
            for (int i = 0; i < 4; i++) acc[mi][ni][i] = 0.f;

    int aRow = wm * 32 + (lane & 15);
    int aCol = (lane >> 4) * 8;
    int bRow = wn * 64 + (lane >> 4) * 8 + (lane & 7);
    int bCol = ((lane >> 3) & 1) * 8;
    int g = lane >> 2, t = lane & 3;

    load_stage(0, 0);

    for (int c = 0; c < nk; c++) {
        int s = c & 1;
        if (c + 1 < nk) {
            load_stage(s ^ 1, c + 1);
            CP_WAIT(1);
        } else {
            CP_WAIT(0);
        }
        __syncthreads();

        const __half* pA = plane(0, s);
        const __half* pBh = plane(1, s);
        const __half* pBl = plane(2, s);

#pragma unroll
        for (int ks = 0; ks < BK / 16; ks++) {
            uint32_t ah[2][4];
#pragma unroll
            for (int mi = 0; mi < 2; mi++)
                ldsm_x4(ah[mi], pA + (aRow + mi * 16) * STR + ks * 16 + aCol);
#pragma unroll
            for (int q = 0; q < 4; q++) {
                uint32_t rh[4], rl[4];
                ldsm_x4(rh, pBh + (bRow + q * 16) * STR + ks * 16 + bCol);
                ldsm_x4(rl, pBl + (bRow + q * 16) * STR + ks * 16 + bCol);
#pragma unroll
                for (int p = 0; p < 2; p++) {
                    int ni = 2 * q + p;
#pragma unroll
                    for (int mi = 0; mi < 2; mi++) {
                        MMA16816(acc[mi][ni], ah[mi], rh[2 * p], rh[2 * p + 1]);
                        MMA16816(acc[mi][ni], ah[mi], rl[2 * p], rl[2 * p + 1]);
                    }
                }
            }
        }
        __syncthreads();
    }

    // ---- epilogue ----
#pragma unroll
    for (int mi = 0; mi < 2; mi++) {
#pragma unroll
        for (int ni = 0; ni < 8; ni++) {
            int col = n0 + wn * 64 + ni * 8 + 2 * t;
            float b0 = 0.f, b1v = 0.f;
            if (bias) {
                b0 = bias[(size_t)z * Nfull + col];
                b1v = bias[(size_t)z * Nfull + col + 1];
            }
#pragma unroll
            for (int h = 0; h < 2; h++) {
                int row = m0 + wm * 32 + mi * 16 + g + h * 8;
                if (row >= Mrows) continue;
                float v0 = acc[mi][ni][2 * h] + b0;
                float v1 = acc[mi][ni][2 * h + 1] + b1v;
                if (leaky) {
                    v0 = v0 > 0.f ? v0 : 0.01f * v0;
                    v1 = v1 > 0.f ? v1 : 0.01f * v1;
                }
                size_t o = tposeF
                    ? ((size_t)row * K_NETS + z) * Nfull + col
                    : strideC * z + (size_t)row * Nfull + col;
                if (Cf) {
                    *reinterpret_cast<float2*>(&Cf[o]) = make_float2(v0, v1);
                } else {
                    *reinterpret_cast<__half2*>(&Ch[o]) = __floats2half2_rn(v0, v1);
                }
            }
        }
    }
}

#define SMEM_F (3 * 2 * 128 * (64 + 8) * 2)   // BK=64: 110592

// ---------------- sum over net axis (phi fp16 [m][net][L]) ----------------
__global__ void sum_nets_kernel(const __half2* __restrict__ phi2, float* __restrict__ out) {
    int m = blockIdx.x;
    int t = threadIdx.x;   // 64: half2 lanes
    const __half2* base = phi2 + (size_t)m * K_NETS * 64 + t;
    float sx = 0.f, sy = 0.f;
#pragma unroll 8
    for (int j = 0; j < K_NETS; j++) {
        float2 v = __half22float2(base[j * 64]);
        sx += v.x; sy += v.y;
    }
    *reinterpret_cast<float2*>(&out[(size_t)m * L_DIM + 2 * t]) = make_float2(sx, sy);
}

// ---------------- psi(0) exact fp32 ----------------
__global__ void psi0_kernel(const float* __restrict__ b1eff, const float* __restrict__ W2,
                            const float* __restrict__ b2, const float* __restrict__ W3,
                            const float* __restrict__ scale, float* __restrict__ psi0) {
    int k = blockIdx.x;
    int t = threadIdx.x;
    __shared__ float h1[H_DIM], h2[H_DIM];
    float v = b1eff[k * H_DIM + t];
    h1[t] = v > 0.f ? v : 0.01f * v;
    __syncthreads();
    float a = b2[k * H_DIM + t];
    for (int d = 0; d < H_DIM; d++)
        a += h1[d] * W2[((size_t)k * H_DIM + d) * H_DIM + t];
    h2[t] = a > 0.f ? a : 0.01f * a;
    __syncthreads();
    if (t < L_DIM) {
        float s = 0.f;
        for (int d = 0; d < H_DIM; d++)
            s += h2[d] * W3[((size_t)k * H_DIM + d) * L_DIM + t];
        psi0[k * L_DIM + t] = s * scale[k * L_DIM + t];
    }
}

// ---------------- scan: 2 blocks per batch; phi fp16, psi fp32 ----------------
__global__ void __launch_bounds__(256)
scan_kernel(const __half2* __restrict__ phi2,  // [m][net][64 half2]
            const float* __restrict__ psi,     // [bt][net][L]
            const float* __restrict__ psi0,
            const float* __restrict__ reL, const float* __restrict__ imL,
            float* __restrict__ predsum2) {
    int bid = blockIdx.x;
    int b = bid >> 1;
    int sel = bid & 1;
    int j0 = sel * 32;
    int tid = threadIdx.x;
    __shared__ float ps[32 * L_DIM];
    __shared__ float rsh[K_NETS], ish[K_NETS];
    if (tid < K_NETS) { rsh[tid] = reL[tid]; ish[tid] = imL[tid]; }

    float px[8], py[8], rj[8], ij[8], u0x[8], u0y[8];
    const __half2* phiB = phi2 + ((size_t)(b * T_DIM) * K_NETS + j0) * 64;
    const float* psi0B = psi0 + (size_t)j0 * L_DIM;
#pragma unroll
    for (int q = 0; q < 8; q++) {
        int e = q * 256 + tid;
        float2 v = __half22float2(phiB[e]);
        px[q] = v.x; py[q] = v.y;
        float2 zz = *reinterpret_cast<const float2*>(&psi0B[e * 2]);
        u0x[q] = zz.x; u0y[q] = zz.y;
    }
    __syncthreads();
#pragma unroll
    for (int q = 0; q < 8; q++) {
        int j = j0 + ((q * 256 + tid) >> 6);
        rj[q] = rsh[j]; ij[q] = ish[j];
    }

    for (int t = 0; t < TM1; t++) {
        const float* psiT = psi + ((size_t)(b * TM1 + t) * K_NETS + j0) * L_DIM;
#pragma unroll
        for (int q = 0; q < 8; q++) {
            int e = q * 256 + tid;
            float2 u = *reinterpret_cast<const float2*>(&psiT[e * 2]);
            float vx = px[q] + u.x - u0x[q];
            float vy = py[q] + u.y - u0y[q];
            px[q] = vx * rj[q] - vy * ij[q];
            py[q] = vx * ij[q] + vy * rj[q];
            ps[e * 2]     = px[q];
            ps[e * 2 + 1] = py[q];
        }
        __syncthreads();
        if (tid < L_DIM) {
            float s = 0.f;
#pragma unroll 8
            for (int j = 0; j < 32; j++) s += ps[j * L_DIM + tid];
            predsum2[(((size_t)sel * N_B + b) * TM1 + t) * L_DIM + tid] = s;
        }
        __syncthreads();
    }
}

// ---------------- decode ----------------
__global__ void decode_kernel(const float* __restrict__ phisum,
                              const float* __restrict__ predsum2,
                              const float* __restrict__ C_W,
                              float* __restrict__ out) {
    __shared__ float Cs[DX * L_DIM];
    __shared__ float rowY[L_DIM], rowP[L_DIM];
    int bt = blockIdx.x;
    int b = bt / TM1, t = bt % TM1;
    int tid = threadIdx.x;
    for (int i = tid; i < DX * L_DIM; i += 256) Cs[i] = C_W[i];
    if (tid < L_DIM)
        rowY[tid] = phisum[((size_t)(b * T_DIM + t + 1)) * L_DIM + tid];
    else {
        int l = tid - L_DIM;
        rowP[l] = predsum2[(size_t)bt * L_DIM + l]
                + predsum2[((size_t)N_B * TM1 + bt) * L_DIM + l];
    }
    __syncthreads();
    if (tid < 2 * DX) {
        int sel = tid >> 4, d = tid & 15;
        const float* row = sel ? rowP : rowY;
        float s = 0.f;
        for (int l = 0; l < L_DIM; l++) s += row[l] * Cs[d * L_DIM + l];
        out[(size_t)sel * N_B * TM1 * DX + (size_t)bt * DX + d] = s;
    }
}

// ---------------- launcher ----------------
extern "C" void kernel_launch(void* const* d_in, const int* in_sizes, int n_in,
                              void* d_out, int out_size) {
    const float* xs      = (const float*)d_in[0];
    const float* us      = (const float*)d_in[1];
    const float* x_gamma = (const float*)d_in[2];
    const float* x_beta  = (const float*)d_in[3];
    const float* xW1     = (const float*)d_in[4];
    const float* xb1     = (const float*)d_in[5];
    const float* xW2     = (const float*)d_in[6];
    const float* xb2     = (const float*)d_in[7];
    const float* xW3     = (const float*)d_in[8];
    const float* x_scale = (const float*)d_in[9];
    const float* u_gamma = (const float*)d_in[10];
    const float* u_beta  = (const float*)d_in[11];
    const float* uW1     = (const float*)d_in[12];
    const float* ub1     = (const float*)d_in[13];
    const float* uW2     = (const float*)d_in[14];
    const float* ub2     = (const float*)d_in[15];
    const float* uW3     = (const float*)d_in[16];
    const float* u_scale = (const float*)d_in[17];
    const float* reL     = (const float*)d_in[18];
    const float* imL     = (const float*)d_in[19];
    const float* C_W     = (const float*)d_in[20];
    float* out = (float*)d_out;

    float *b1ex, *b1eu, *psi, *psi0, *phisum, *predsum2;
    __half *xnhi, *xnlo, *unhi, *unlo, *w1xh, *w1xl, *w1uh, *w1ul;
    __half *h1, *h2, *phi_h;
    __half *w2xh, *w2xl, *w3xh, *w3xl, *w2uh, *w2ul, *w3uh, *w3ul;
    cudaGetSymbolAddress((void**)&xnhi, g_xnhi);
    cudaGetSymbolAddress((void**)&xnlo, g_xnlo);
    cudaGetSymbolAddress((void**)&unhi, g_unhi);
    cudaGetSymbolAddress((void**)&unlo, g_unlo);
    cudaGetSymbolAddress((void**)&b1ex, g_b1ex);
    cudaGetSymbolAddress((void**)&b1eu, g_b1eu);
    cudaGetSymbolAddress((void**)&w1xh, g_w1xh);
    cudaGetSymbolAddress((void**)&w1xl, g_w1xl);
    cudaGetSymbolAddress((void**)&w1uh, g_w1uh);
    cudaGetSymbolAddress((void**)&w1ul, g_w1ul);
    cudaGetSymbolAddress((void**)&h1, g_h1);
    cudaGetSymbolAddress((void**)&h2, g_h2);
    cudaGetSymbolAddress((void**)&phi_h, g_phi_h);
    cudaGetSymbolAddress((void**)&w2xh, g_w2xt_hi);
    cudaGetSymbolAddress((void**)&w2xl, g_w2xt_lo);
    cudaGetSymbolAddress((void**)&w3xh, g_w3xt_hi);
    cudaGetSymbolAddress((void**)&w3xl, g_w3xt_lo);
    cudaGetSymbolAddress((void**)&w2uh, g_w2ut_hi);
    cudaGetSymbolAddress((void**)&w2ul, g_w2ut_lo);
    cudaGetSymbolAddress((void**)&w3uh, g_w3ut_hi);
    cudaGetSymbolAddress((void**)&w3ul, g_w3ut_lo);
    cudaGetSymbolAddress((void**)&psi, g_psi);
    cudaGetSymbolAddress((void**)&psi0, g_psi0);
    cudaGetSymbolAddress((void**)&phisum, g_phisum);
    cudaGetSymbolAddress((void**)&predsum2, g_predsum2);

    cudaFuncSetAttribute((const void*)hmma_l1_kernel,
                         cudaFuncAttributeMaxDynamicSharedMemorySize, SMEM_L1);
    cudaFuncSetAttribute((const void*)hmma_gemm_kernel<64>,
                         cudaFuncAttributeMaxDynamicSharedMemorySize, SMEM_F);

    dim3 tb(32, 8);
    // ---- x path ----
    bn_split_kernel<<<KP1, 256>>>(xs, xnhi, xnlo, MX, DX);                          // 0
    prep_w1_split_kernel<<<K_NETS, H_DIM>>>(x_gamma, x_beta, xW1, xb1,
                                            w1xh, w1xl, b1ex, DX);                  // 1
    transpose_split2_kernel<<<dim3(96, K_NETS), tb>>>(
        xW2, w2xh, w2xl, xW3, w3xh, w3xl, x_scale);                                 // 2
    hmma_l1_kernel<<<dim3(MX / 128 / L1_MT, 2, K_NETS), 256, SMEM_L1>>>(
        xnhi, xnlo, w1xh, w1xl, b1ex, h1, (size_t)MX * H_DIM, MX);                  // 3: L1x
    bn_split_kernel<<<KP1, 256>>>(us, unhi, unlo, MU, DU);                          // 4
    hmma_gemm_kernel<64><<<dim3(MX / 128, 2, K_NETS), 256, SMEM_F>>>(
        h1, (size_t)MX * H_DIM, H_DIM, H_DIM,
        w2xh, w2xl, (size_t)H_DIM * H_DIM, H_DIM,
        xb2, nullptr, h2, (size_t)MX * H_DIM, MX, H_DIM, 1, 0);                     // 5: L2x
    hmma_gemm_kernel<64><<<dim3(MX / 128, 1, K_NETS), 256, SMEM_F>>>(
        h2, (size_t)MX * H_DIM, H_DIM, H_DIM,
        w3xh, w3xl, (size_t)L_DIM * H_DIM, H_DIM,
        nullptr, nullptr, phi_h, 0, MX, L_DIM, 0, 1);                               // 6: L3x -> fp16 [m][net][L]
    sum_nets_kernel<<<MX, 64>>>(reinterpret_cast<const __half2*>(phi_h), phisum);   // 7

    // ---- u path ----
    prep_w1_split_kernel<<<K_NETS, H_DIM>>>(u_gamma, u_beta, uW1, ub1,
                                            w1uh, w1ul, b1eu, DU);                  // 8
    transpose_split2_kernel<<<dim3(96, K_NETS), tb>>>(
        uW2, w2uh, w2ul, uW3, w3uh, w3ul, u_scale);                                 // 9
    hmma_l1_kernel<<<dim3(8, 2, K_NETS), 256, SMEM_L1>>>(
        unhi, unlo, w1uh, w1ul, b1eu, h1, (size_t)MU * H_DIM, MU);                  // 10: L1u (32 m-tiles / 4)
    hmma_gemm_kernel<64><<<dim3(32, 2, K_NETS), 256, SMEM_F>>>(
        h1, (size_t)MU * H_DIM, H_DIM, H_DIM,
        w2uh, w2ul, (size_t)H_DIM * H_DIM, H_DIM,
        ub2, nullptr, h2, (size_t)MU * H_DIM, MU, H_DIM, 1, 0);                     // 11
    hmma_gemm_kernel<64><<<dim3(32, 1, K_NETS), 256, SMEM_F>>>(
        h2, (size_t)MU * H_DIM, H_DIM, H_DIM,
        w3uh, w3ul, (size_t)L_DIM * H_DIM, H_DIM,
        nullptr, psi, nullptr, 0, MU, L_DIM, 0, 1);                                 // 12: psi fp32 [bt][net][L]

    psi0_kernel<<<K_NETS, H_DIM>>>(b1eu, uW2, ub2, uW3, u_scale, psi0);             // 13
    scan_kernel<<<2 * N_B, 256>>>(reinterpret_cast<const __half2*>(phi_h),
                                  psi, psi0, reL, imL, predsum2);                   // 14
    decode_kernel<<<N_B * TM1, 256>>>(phisum, predsum2, C_W, out);                  // 15
}

// round 15
// speedup vs baseline: 2.3261x; 1.2396x over previous
#include <cuda_runtime.h>
#include <cuda_fp16.h>
#include <cstdint>
#include <cstddef>

// ---------------- problem dims (fixed) ----------------
#define N_B    64
#define T_DIM  64
#define TM1    63
#define DX     16
#define DU     8
#define H_DIM  256
#define L_DIM  128
#define K_NETS 64
#define MX     (N_B * T_DIM)   // 4096
#define MU     (N_B * TM1)     // 4032
#define KP1    32
#define L1_MT  4               // m-tiles per L1 block

// ---------------- scratch (device globals) ----------------
__device__ __half g_xnhi[MX * KP1];
__device__ __half g_xnlo[MX * KP1];
__device__ __half g_unhi[MU * KP1];
__device__ __half g_unlo[MU * KP1];
__device__ float g_b1ex[K_NETS * H_DIM];
__device__ float g_b1eu[K_NETS * H_DIM];
__device__ __half g_w1xh[K_NETS * H_DIM * KP1];
__device__ __half g_w1xl[K_NETS * H_DIM * KP1];
__device__ __half g_w1uh[K_NETS * H_DIM * KP1];
__device__ __half g_w1ul[K_NETS * H_DIM * KP1];
__device__ __half g_h1[(size_t)K_NETS * MX * H_DIM];
__device__ __half g_h2[(size_t)K_NETS * MX * H_DIM];
__device__ __half g_w2xt[(size_t)K_NETS * H_DIM * H_DIM];   // [net][n][d] fp16 hi only
__device__ __half g_w3xt[(size_t)K_NETS * L_DIM * H_DIM];   // [net][n][d], scale folded
__device__ __half g_w2ut[(size_t)K_NETS * H_DIM * H_DIM];
__device__ __half g_w3ut[(size_t)K_NETS * L_DIM * H_DIM];
__device__ __half g_phi_h[(size_t)MX * K_NETS * L_DIM];   // fp16 [m][net][L]
__device__ float g_psi[(size_t)MU * K_NETS * L_DIM];      // [bt][net][L]
__device__ float g_psi0[K_NETS * L_DIM];
__device__ float g_phisum[MX * L_DIM];
__device__ float g_predsum2[2 * N_B * TM1 * L_DIM];

// ---------------- BN + fp16 hi/lo split ----------------
__global__ void bn_split_kernel(const float* __restrict__ x,
                                __half* __restrict__ Ahi, __half* __restrict__ Alo,
                                int M, int D) {
    int d = blockIdx.x;
    int tid = threadIdx.x;
    if (d >= D) {
        for (int m = tid; m < M; m += 256) {
            Ahi[(size_t)m * KP1 + d] = __float2half(0.f);
            Alo[(size_t)m * KP1 + d] = __float2half(0.f);
        }
        return;
    }
    __shared__ float r1[256], r2[256];
    float s = 0.f, s2 = 0.f;
    for (int m = tid; m < M; m += 256) {
        float v = x[(size_t)m * D + d];
        s += v; s2 += v * v;
    }
    r1[tid] = s; r2[tid] = s2;
    __syncthreads();
    for (int o = 128; o > 0; o >>= 1) {
        if (tid < o) { r1[tid] += r1[tid + o]; r2[tid] += r2[tid + o]; }
        __syncthreads();
    }
    float mu = r1[0] / M;
    float var = r2[0] / M - mu * mu;
    float rstd = rsqrtf(var + 1e-5f);
    for (int m = tid; m < M; m += 256) {
        float v = (x[(size_t)m * D + d] - mu) * rstd;
        __half h = __float2half(v);
        Ahi[(size_t)m * KP1 + d] = h;
        Alo[(size_t)m * KP1 + d] = __float2half(v - __half2float(h));
    }
}

// ---------------- fold BN affine into layer-1, transpose, split ----------------
__global__ void prep_w1_split_kernel(const float* __restrict__ g, const float* __restrict__ be,
                                     const float* __restrict__ W1, const float* __restrict__ b1,
                                     __half* __restrict__ Thi, __half* __restrict__ Tlo,
                                     float* __restrict__ beff, int D) {
    int k = blockIdx.x;
    int h = threadIdx.x;
    float bacc = b1[k * H_DIM + h];
    for (int d = 0; d < KP1; d++) {
        float v = 0.f;
        if (d < D) {
            float w = W1[((size_t)k * D + d) * H_DIM + h];
            v = g[k * D + d] * w;
            bacc += be[k * D + d] * w;
        }
        __half hi = __float2half(v);
        size_t o = ((size_t)k * H_DIM + h) * KP1 + d;
        Thi[o] = hi;
        Tlo[o] = __float2half(v - __half2float(hi));
    }
    beff[k * H_DIM + h] = bacc;
}

// ---------------- W2 + W3 transpose (single fp16 plane); W3 scale folded ----------------
__global__ void transpose_split2_kernel(const float* __restrict__ W2,
                                        __half* __restrict__ T2,
                                        const float* __restrict__ W3,
                                        __half* __restrict__ T3,
                                        const float* __restrict__ scale3) {
    __shared__ float tile[32][33];
    int k = blockIdx.y;
    int idx = blockIdx.x;
    if (idx < 64) {
        const float* W = W2 + (size_t)k * H_DIM * H_DIM;
        int kk0 = (idx >> 3) * 32, n0 = (idx & 7) * 32;
        for (int r = threadIdx.y; r < 32; r += 8)
            tile[r][threadIdx.x] = W[(size_t)(kk0 + r) * H_DIM + n0 + threadIdx.x];
        __syncthreads();
        for (int r = threadIdx.y; r < 32; r += 8) {
            int n = n0 + r, kk = kk0 + threadIdx.x;
            T2[((size_t)k * H_DIM + n) * H_DIM + kk] = __float2half(tile[threadIdx.x][r]);
        }
    } else {
        idx -= 64;
        const float* W = W3 + (size_t)k * H_DIM * L_DIM;
        int kk0 = (idx >> 2) * 32, n0 = (idx & 3) * 32;
        for (int r = threadIdx.y; r < 32; r += 8)
            tile[r][threadIdx.x] = W[(size_t)(kk0 + r) * L_DIM + n0 + threadIdx.x];
        __syncthreads();
        for (int r = threadIdx.y; r < 32; r += 8) {
            int n = n0 + r, kk = kk0 + threadIdx.x;
            float v = tile[threadIdx.x][r] * scale3[k * L_DIM + n];
            T3[((size_t)k * L_DIM + n) * H_DIM + kk] = __float2half(v);
        }
    }
}

// ================= common GEMM helpers =================
__device__ __forceinline__ void cp16(void* dst, const void* src, bool pred) {
    uint32_t d = (uint32_t)__cvta_generic_to_shared(dst);
    int n = pred ? 16 : 0;
    asm volatile("cp.async.cg.shared.global [%0], [%1], 16, %2;" :: "r"(d), "l"(src), "r"(n));
}
#define CP_COMMIT() asm volatile("cp.async.commit_group;")
#define CP_WAIT(N)  asm volatile("cp.async.wait_group %0;" :: "n"(N))

__device__ __forceinline__ void ldsm_x4(uint32_t* r, const void* p) {
    uint32_t a = (uint32_t)__cvta_generic_to_shared(p);
    asm volatile("ldmatrix.sync.aligned.m8n8.x4.shared.b16 {%0,%1,%2,%3}, [%4];"
                 : "=r"(r[0]), "=r"(r[1]), "=r"(r[2]), "=r"(r[3]) : "r"(a));
}
#define MMA16816(d, a, b0, b1) \
    asm volatile("mma.sync.aligned.m16n8k16.row.col.f32.f16.f16.f32 " \
                 "{%0,%1,%2,%3},{%4,%5,%6,%7},{%8,%9},{%0,%1,%2,%3};" \
                 : "+f"((d)[0]), "+f"((d)[1]), "+f"((d)[2]), "+f"((d)[3]) \
                 : "r"((a)[0]), "r"((a)[1]), "r"((a)[2]), "r"((a)[3]), \
                   "r"(b0), "r"(b1))

// ================= L1 kernel: B-resident, 4 m-tiles per block, 3-term split =================
#define L1_STR 40
#define L1_PLH (128 * L1_STR)
#define SMEM_L1 (6 * L1_PLH * 2)  // 61440

__global__ void __launch_bounds__(256, 2)
hmma_l1_kernel(const __half* __restrict__ Ahi, const __half* __restrict__ Alo,
               const __half* __restrict__ Bhi, const __half* __restrict__ Blo,
               const float* __restrict__ bias,
               __half* __restrict__ Ch, size_t strideC, int Mrows) {
    extern __shared__ char smem[];
    auto plane = [&](int p) -> __half* {
        return reinterpret_cast<__half*>(smem) + p * L1_PLH;
    };
    int tid = threadIdx.x;
    int lane = tid & 31, wid = tid >> 5;
    int wm = wid >> 1, wn = wid & 1;
    int z = blockIdx.z;
    int n0 = blockIdx.y * 128;
    int mg = blockIdx.x;

    const __half* Bh = Bhi + ((size_t)z * H_DIM + n0) * KP1;
    const __half* Bl = Blo + ((size_t)z * H_DIM + n0) * KP1;

    int rowL = tid >> 1;
    int kkL = (tid & 1) * 16;
    int soff = rowL * L1_STR + kkL;

    cp16(plane(0) + soff,     Bh + (size_t)rowL * KP1 + kkL, true);
    cp16(plane(0) + soff + 8, Bh + (size_t)rowL * KP1 + kkL + 8, true);
    cp16(plane(1) + soff,     Bl + (size_t)rowL * KP1 + kkL, true);
    cp16(plane(1) + soff + 8, Bl + (size_t)rowL * KP1 + kkL + 8, true);
    CP_COMMIT();

    auto load_A = [&](int s, int mt) {
        int gm = (mg * L1_MT + mt) * 128 + rowL;
        bool aOk = gm < Mrows;
        const __half* pa = Ahi + (size_t)gm * KP1 + kkL;
        const __half* pl = Alo + (size_t)gm * KP1 + kkL;
        cp16(plane(2 + s * 2) + soff,     pa,     aOk);
        cp16(plane(2 + s * 2) + soff + 8, pa + 8, aOk);
        cp16(plane(3 + s * 2) + soff,     pl,     aOk);
        cp16(plane(3 + s * 2) + soff + 8, pl + 8, aOk);
        CP_COMMIT();
    };
    load_A(0, 0);

    int aRow = wm * 32 + (lane & 15);
    int aCol = (lane >> 4) * 8;
    int bRow = wn * 64 + (lane >> 4) * 8 + (lane & 7);
    int bCol = ((lane >> 3) & 1) * 8;
    int g = lane >> 2, t = lane & 3;

    for (int mt = 0; mt < L1_MT; mt++) {
        int s = mt & 1;
        if (mt + 1 < L1_MT) {
            load_A(s ^ 1, mt + 1);
            CP_WAIT(1);
        } else {
            CP_WAIT(0);
        }
        __syncthreads();

        float acc[2][8][4];
#pragma unroll
        for (int mi = 0; mi < 2; mi++)
#pragma unroll
            for (int ni = 0; ni < 8; ni++)
#pragma unroll
                for (int i = 0; i < 4; i++) acc[mi][ni][i] = 0.f;

        const __half* pAh = plane(2 + s * 2);
        const __half* pAl = plane(3 + s * 2);
        const __half* pBh = plane(0);
        const __half* pBl = plane(1);

#pragma unroll
        for (int ks = 0; ks < 2; ks++) {
            uint32_t ah[2][4], al[2][4];
#pragma unroll
            for (int mi = 0; mi < 2; mi++) {
                ldsm_x4(ah[mi], pAh + (aRow + mi * 16) * L1_STR + ks * 16 + aCol);
                ldsm_x4(al[mi], pAl + (aRow + mi * 16) * L1_STR + ks * 16 + aCol);
            }
#pragma unroll
            for (int q = 0; q < 4; q++) {
                uint32_t rh[4], rl[4];
                ldsm_x4(rh, pBh + (bRow + q * 16) * L1_STR + ks * 16 + bCol);
                ldsm_x4(rl, pBl + (bRow + q * 16) * L1_STR + ks * 16 + bCol);
#pragma unroll
                for (int p = 0; p < 2; p++) {
                    int ni = 2 * q + p;
#pragma unroll
                    for (int mi = 0; mi < 2; mi++) {
                        MMA16816(acc[mi][ni], ah[mi], rh[2 * p], rh[2 * p + 1]);
                        MMA16816(acc[mi][ni], ah[mi], rl[2 * p], rl[2 * p + 1]);
                        MMA16816(acc[mi][ni], al[mi], rh[2 * p], rh[2 * p + 1]);
                    }
                }
            }
        }

        int mbase = (mg * L1_MT + mt) * 128;
#pragma unroll
        for (int mi = 0; mi < 2; mi++) {
#pragma unroll
            for (int ni = 0; ni < 8; ni++) {
                int col = n0 + wn * 64 + ni * 8 + 2 * t;
                float b0 = bias[(size_t)z * H_DIM + col];
                float b1v = bias[(size_t)z * H_DIM + col + 1];
#pragma unroll
                for (int h = 0; h < 2; h++) {
                    int row = mbase + wm * 32 + mi * 16 + g + h * 8;
                    if (row >= Mrows) continue;
                    float v0 = acc[mi][ni][2 * h] + b0;
                    float v1 = acc[mi][ni][2 * h + 1] + b1v;
                    v0 = v0 > 0.f ? v0 : 0.01f * v0;
                    v1 = v1 > 0.f ? v1 : 0.01f * v1;
                    size_t o = strideC * z + (size_t)row * H_DIM + col;
                    *reinterpret_cast<__half2*>(&Ch[o]) = __floats2half2_rn(v0, v1);
                }
            }
        }
        __syncthreads();
    }
}

// ================= BK=64 streaming kernel, single-plane B =================
template <int BK>
__global__ void __launch_bounds__(256, 2)
hmma_gemm_kernel(const __half* __restrict__ A, size_t strideA, int lda, int KdPad,
                 const __half* __restrict__ B, size_t strideB, int ldb,
                 const float* __restrict__ bias,
                 float* __restrict__ Cf, __half* __restrict__ Ch, size_t strideC,
                 int Mrows, int Nfull, int leaky, int tposeF) {
    extern __shared__ char smem[];
    constexpr int STR = BK + 8;
    constexpr int PLANE_H = 128 * STR;

    int tid = threadIdx.x;
    int lane = tid & 31, wid = tid >> 5;
    int wm = wid >> 1, wn = wid & 1;
    int z = blockIdx.z;
    int m0 = blockIdx.x * 128, n0 = blockIdx.y * 128;

    const __half* Ab = A + strideA * z;
    const __half* Bb = B + strideB * z + (size_t)n0 * ldb;

    auto plane = [&](int p, int s) -> __half* {
        return reinterpret_cast<__half*>(smem) + (p * 2 + s) * PLANE_H;
    };

    int rowL = tid >> 1;
    int kkL = (tid & 1) * 16;
    bool aOk = (m0 + rowL) < Mrows;
    const __half* gA = Ab + (size_t)(m0 + rowL) * lda + kkL;
    const __half* gB = Bb + (size_t)rowL * ldb + kkL;
    int soff = rowL * STR + kkL;

    int nk = KdPad / BK;

    auto load_stage = [&](int s, int c) {
#pragma unroll
        for (int seg = 0; seg < BK / 32; seg++) {
            int k0 = c * BK + seg * 32;
            int so = soff + seg * 32;
            cp16(plane(0, s) + so,     gA + k0,     aOk);
            cp16(plane(0, s) + so + 8, gA + k0 + 8, aOk);
            cp16(plane(1, s) + so,     gB + k0,     true);
            cp16(plane(1, s) + so + 8, gB + k0 + 8, true);
        }
        CP_COMMIT();
    };

    float acc[2][8][4];
#pragma unroll
    for (int mi = 0; mi < 2; mi++)
#pragma unroll
        for (int ni = 0; ni < 8; ni++)
#pragma unroll
            for (int i = 0; i < 4; i++) acc[mi][ni][i] = 0.f;

    int aRow = wm * 32 + (lane & 15);
    int aCol = (lane >> 4) * 8;
    int bRow = wn * 64 + (lane >> 4) * 8 + (lane & 7);
    int bCol = ((lane >> 3) & 1) * 8;
    int g = lane >> 2, t = lane & 3;

    load_stage(0, 0);

    for (int c = 0; c < nk; c++) {
        int s = c & 1;
        if (c + 1 < nk) {
            load_stage(s ^ 1, c + 1);
            CP_WAIT(1);
        } else {
            CP_WAIT(0);
        }
        __syncthreads();

        const __half* pA = plane(0, s);
        const __half* pB = plane(1, s);

#pragma unroll
        for (int ks = 0; ks < BK / 16; ks++) {
            uint32_t ah[2][4];
#pragma unroll
            for (int mi = 0; mi < 2; mi++)
                ldsm_x4(ah[mi], pA + (aRow + mi * 16) * STR + ks * 16 + aCol);
#pragma unroll
            for (int q = 0; q < 4; q++) {
                uint32_t rh[4];
                ldsm_x4(rh, pB + (bRow + q * 16) * STR + ks * 16 + bCol);
#pragma unroll
                for (int p = 0; p < 2; p++) {
                    int ni = 2 * q + p;
#pragma unroll
                    for (int mi = 0; mi < 2; mi++)
                        MMA16816(acc[mi][ni], ah[mi], rh[2 * p], rh[2 * p + 1]);
                }
            }
        }
        __syncthreads();
    }

    // ---- epilogue ----
#pragma unroll
    for (int mi = 0; mi < 2; mi++) {
#pragma unroll
        for (int ni = 0; ni < 8; ni++) {
            int col = n0 + wn * 64 + ni * 8 + 2 * t;
            float b0 = 0.f, b1v = 0.f;
            if (bias) {
                b0 = bias[(size_t)z * Nfull + col];
                b1v = bias[(size_t)z * Nfull + col + 1];
            }
#pragma unroll
            for (int h = 0; h < 2; h++) {
                int row = m0 + wm * 32 + mi * 16 + g + h * 8;
                if (row >= Mrows) continue;
                float v0 = acc[mi][ni][2 * h] + b0;
                float v1 = acc[mi][ni][2 * h + 1] + b1v;
                if (leaky) {
                    v0 = v0 > 0.f ? v0 : 0.01f * v0;
                    v1 = v1 > 0.f ? v1 : 0.01f * v1;
                }
                size_t o = tposeF
                    ? ((size_t)row * K_NETS + z) * Nfull + col
                    : strideC * z + (size_t)row * Nfull + col;
                if (Cf) {
                    *reinterpret_cast<float2*>(&Cf[o]) = make_float2(v0, v1);
                } else {
                    *reinterpret_cast<__half2*>(&Ch[o]) = __floats2half2_rn(v0, v1);
                }
            }
        }
    }
}

#define SMEM_F (2 * 2 * 128 * (64 + 8) * 2)   // BK=64, 2 planes: 73728

// ---------------- sum over net axis (phi fp16) ----------------
__global__ void sum_nets_kernel(const __half2* __restrict__ phi2, float* __restrict__ out) {
    int m = blockIdx.x;
    int t = threadIdx.x;   // 64 half2 lanes
    const __half2* base = phi2 + (size_t)m * K_NETS * 64 + t;
    float sx = 0.f, sy = 0.f;
#pragma unroll 8
    for (int j = 0; j < K_NETS; j++) {
        float2 v = __half22float2(base[j * 64]);
        sx += v.x; sy += v.y;
    }
    *reinterpret_cast<float2*>(&out[(size_t)m * L_DIM + 2 * t]) = make_float2(sx, sy);
}

// ---------------- psi(0): mirrors the GEMM numerics (fp16 weights+activations) ----------------
__global__ void psi0_kernel(const float* __restrict__ b1eff,
                            const __half* __restrict__ w2t,   // [net][n][d]
                            const float* __restrict__ b2,
                            const __half* __restrict__ w3t,   // [net][n][d], scale folded
                            float* __restrict__ psi0) {
    int k = blockIdx.x;
    int t = threadIdx.x;
    __shared__ float h1[H_DIM], h2[H_DIM];
    float v = b1eff[k * H_DIM + t];
    v = v > 0.f ? v : 0.01f * v;
    h1[t] = __half2float(__float2half(v));     // mirror fp16 h1 rounding
    __syncthreads();
    float a = b2[k * H_DIM + t];
    const __half* w2row = w2t + ((size_t)k * H_DIM + t) * H_DIM;
    for (int d = 0; d < H_DIM; d++)
        a += h1[d] * __half2float(w2row[d]);
    a = a > 0.f ? a : 0.01f * a;
    h2[t] = __half2float(__float2half(a));     // mirror fp16 h2 rounding
    __syncthreads();
    if (t < L_DIM) {
        float s = 0.f;
        const __half* w3row = w3t + ((size_t)k * L_DIM + t) * H_DIM;
        for (int d = 0; d < H_DIM; d++)
            s += h2[d] * __half2float(w3row[d]);
        psi0[k * L_DIM + t] = s;               // scale already folded into w3t
    }
}

// ---------------- scan: 2 blocks per batch; phi fp16, psi fp32 ----------------
__global__ void __launch_bounds__(256)
scan_kernel(const __half2* __restrict__ phi2,
            const float* __restrict__ psi,
            const float* __restrict__ psi0,
            const float* __restrict__ reL, const float* __restrict__ imL,
            float* __restrict__ predsum2) {
    int bid = blockIdx.x;
    int b = bid >> 1;
    int sel = bid & 1;
    int j0 = sel * 32;
    int tid = threadIdx.x;
    __shared__ float ps[32 * L_DIM];
    __shared__ float rsh[K_NETS], ish[K_NETS];
    if (tid < K_NETS) { rsh[tid] = reL[tid]; ish[tid] = imL[tid]; }

    float px[8], py[8], rj[8], ij[8], u0x[8], u0y[8];
    const __half2* phiB = phi2 + ((size_t)(b * T_DIM) * K_NETS + j0) * 64;
    const float* psi0B = psi0 + (size_t)j0 * L_DIM;
#pragma unroll
    for (int q = 0; q < 8; q++) {
        int e = q * 256 + tid;
        float2 v = __half22float2(phiB[e]);
        px[q] = v.x; py[q] = v.y;
        float2 zz = *reinterpret_cast<const float2*>(&psi0B[e * 2]);
        u0x[q] = zz.x; u0y[q] = zz.y;
    }
    __syncthreads();
#pragma unroll
    for (int q = 0; q < 8; q++) {
        int j = j0 + ((q * 256 + tid) >> 6);
        rj[q] = rsh[j]; ij[q] = ish[j];
    }

    for (int t = 0; t < TM1; t++) {
        const float* psiT = psi + ((size_t)(b * TM1 + t) * K_NETS + j0) * L_DIM;
#pragma unroll
        for (int q = 0; q < 8; q++) {
            int e = q * 256 + tid;
            float2 u = *reinterpret_cast<const float2*>(&psiT[e * 2]);
            float vx = px[q] + u.x - u0x[q];
            float vy = py[q] + u.y - u0y[q];
            px[q] = vx * rj[q] - vy * ij[q];
            py[q] = vx * ij[q] + vy * rj[q];
            ps[e * 2]     = px[q];
            ps[e * 2 + 1] = py[q];
        }
        __syncthreads();
        if (tid < L_DIM) {
            float s = 0.f;
#pragma unroll 8
            for (int j = 0; j < 32; j++) s += ps[j * L_DIM + tid];
            predsum2[(((size_t)sel * N_B + b) * TM1 + t) * L_DIM + tid] = s;
        }
        __syncthreads();
    }
}

// ---------------- decode ----------------
__global__ void decode_kernel(const float* __restrict__ phisum,
                              const float* __restrict__ predsum2,
                              const float* __restrict__ C_W,
                              float* __restrict__ out) {
    __shared__ float Cs[DX * L_DIM];
    __shared__ float rowY[L_DIM], rowP[L_DIM];
    int bt = blockIdx.x;
    int b = bt / TM1, t = bt % TM1;
    int tid = threadIdx.x;
    for (int i = tid; i < DX * L_DIM; i += 256) Cs[i] = C_W[i];
    if (tid < L_DIM)
        rowY[tid] = phisum[((size_t)(b * T_DIM + t + 1)) * L_DIM + tid];
    else {
        int l = tid - L_DIM;
        rowP[l] = predsum2[(size_t)bt * L_DIM + l]
                + predsum2[((size_t)N_B * TM1 + bt) * L_DIM + l];
    }
    __syncthreads();
    if (tid < 2 * DX) {
        int sel = tid >> 4, d = tid & 15;
        const float* row = sel ? rowP : rowY;
        float s = 0.f;
        for (int l = 0; l < L_DIM; l++) s += row[l] * Cs[d * L_DIM + l];
        out[(size_t)sel * N_B * TM1 * DX + (size_t)bt * DX + d] = s;
    }
}

// ---------------- launcher ----------------
extern "C" void kernel_launch(void* const* d_in, const int* in_sizes, int n_in,
                              void* d_out, int out_size) {
    const float* xs      = (const float*)d_in[0];
    const float* us      = (const float*)d_in[1];
    const float* x_gamma = (const float*)d_in[2];
    const float* x_beta  = (const float*)d_in[3];
    const float* xW1     = (const float*)d_in[4];
    const float* xb1     = (const float*)d_in[5];
    const float* xW2     = (const float*)d_in[6];
    const float* xb2     = (const float*)d_in[7];
    const float* xW3     = (const float*)d_in[8];
    const float* x_scale = (const float*)d_in[9];
    const float* u_gamma = (const float*)d_in[10];
    const float* u_beta  = (const float*)d_in[11];
    const float* uW1     = (const float*)d_in[12];
    const float* ub1     = (const float*)d_in[13];
    const float* uW2     = (const float*)d_in[14];
    const float* ub2     = (const float*)d_in[15];
    const float* uW3     = (const float*)d_in[16];
    const float* u_scale = (const float*)d_in[17];
    const float* reL     = (const float*)d_in[18];
    const float* imL     = (const float*)d_in[19];
    const float* C_W     = (const float*)d_in[20];
    float* out = (float*)d_out;

    float *b1ex, *b1eu, *psi, *psi0, *phisum, *predsum2;
    __half *xnhi, *xnlo, *unhi, *unlo, *w1xh, *w1xl, *w1uh, *w1ul;
    __half *h1, *h2, *phi_h;
    __half *w2x, *w3x, *w2u, *w3u;
    cudaGetSymbolAddress((void**)&xnhi, g_xnhi);
    cudaGetSymbolAddress((void**)&xnlo, g_xnlo);
    cudaGetSymbolAddress((void**)&unhi, g_unhi);
    cudaGetSymbolAddress((void**)&unlo, g_unlo);
    cudaGetSymbolAddress((void**)&b1ex, g_b1ex);
    cudaGetSymbolAddress((void**)&b1eu, g_b1eu);
    cudaGetSymbolAddress((void**)&w1xh, g_w1xh);
    cudaGetSymbolAddress((void**)&w1xl, g_w1xl);
    cudaGetSymbolAddress((void**)&w1uh, g_w1uh);
    cudaGetSymbolAddress((void**)&w1ul, g_w1ul);
    cudaGetSymbolAddress((void**)&h1, g_h1);
    cudaGetSymbolAddress((void**)&h2, g_h2);
    cudaGetSymbolAddress((void**)&phi_h, g_phi_h);
    cudaGetSymbolAddress((void**)&w2x, g_w2xt);
    cudaGetSymbolAddress((void**)&w3x, g_w3xt);
    cudaGetSymbolAddress((void**)&w2u, g_w2ut);
    cudaGetSymbolAddress((void**)&w3u, g_w3ut);
    cudaGetSymbolAddress((void**)&psi, g_psi);
    cudaGetSymbolAddress((void**)&psi0, g_psi0);
    cudaGetSymbolAddress((void**)&phisum, g_phisum);
    cudaGetSymbolAddress((void**)&predsum2, g_predsum2);

    cudaFuncSetAttribute((const void*)hmma_l1_kernel,
                         cudaFuncAttributeMaxDynamicSharedMemorySize, SMEM_L1);
    cudaFuncSetAttribute((const void*)hmma_gemm_kernel<64>,
                         cudaFuncAttributeMaxDynamicSharedMemorySize, SMEM_F);

    dim3 tb(32, 8);
    // ---- x path ----
    bn_split_kernel<<<KP1, 256>>>(xs, xnhi, xnlo, MX, DX);                          // 0
    prep_w1_split_kernel<<<K_NETS, H_DIM>>>(x_gamma, x_beta, xW1, xb1,
                                            w1xh, w1xl, b1ex, DX);                  // 1
    transpose_split2_kernel<<<dim3(96, K_NETS), tb>>>(xW2, w2x, xW3, w3x, x_scale); // 2
    hmma_l1_kernel<<<dim3(MX / 128 / L1_MT, 2, K_NETS), 256, SMEM_L1>>>(
        xnhi, xnlo, w1xh, w1xl, b1ex, h1, (size_t)MX * H_DIM, MX);                  // 3: L1x
    bn_split_kernel<<<KP1, 256>>>(us, unhi, unlo, MU, DU);                          // 4
    hmma_gemm_kernel<64><<<dim3(MX / 128, 2, K_NETS), 256, SMEM_F>>>(
        h1, (size_t)MX * H_DIM, H_DIM, H_DIM,
        w2x, (size_t)H_DIM * H_DIM, H_DIM,
        xb2, nullptr, h2, (size_t)MX * H_DIM, MX, H_DIM, 1, 0);                     // 5: L2x
    hmma_gemm_kernel<64><<<dim3(MX / 128, 1, K_NETS), 256, SMEM_F>>>(
        h2, (size_t)MX * H_DIM, H_DIM, H_DIM,
        w3x, (size_t)L_DIM * H_DIM, H_DIM,
        nullptr, nullptr, phi_h, 0, MX, L_DIM, 0, 1);                               // 6: L3x -> fp16 [m][net][L]
    sum_nets_kernel<<<MX, 64>>>(reinterpret_cast<const __half2*>(phi_h), phisum);   // 7

    // ---- u path ----
    prep_w1_split_kernel<<<K_NETS, H_DIM>>>(u_gamma, u_beta, uW1, ub1,
                                            w1uh, w1ul, b1eu, DU);                  // 8
    transpose_split2_kernel<<<dim3(96, K_NETS), tb>>>(uW2, w2u, uW3, w3u, u_scale); // 9
    hmma_l1_kernel<<<dim3(8, 2, K_NETS), 256, SMEM_L1>>>(
        unhi, unlo, w1uh, w1ul, b1eu, h1, (size_t)MU * H_DIM, MU);                  // 10: L1u
    hmma_gemm_kernel<64><<<dim3(32, 2, K_NETS), 256, SMEM_F>>>(
        h1, (size_t)MU * H_DIM, H_DIM, H_DIM,
        w2u, (size_t)H_DIM * H_DIM, H_DIM,
        ub2, nullptr, h2, (size_t)MU * H_DIM, MU, H_DIM, 1, 0);                     // 11: L2u
    hmma_gemm_kernel<64><<<dim3(32, 1, K_NETS), 256, SMEM_F>>>(
        h2, (size_t)MU * H_DIM, H_DIM, H_DIM,
        w3u, (size_t)L_DIM * H_DIM, H_DIM,
        nullptr, psi, nullptr, 0, MU, L_DIM, 0, 1);                                 // 12: psi fp32 [bt][net][L]

    psi0_kernel<<<K_NETS, H_DIM>>>(b1eu, w2u, ub2, w3u, psi0);                      // 13
    scan_kernel<<<2 * N_B, 256>>>(reinterpret_cast<const __half2*>(phi_h),
                                  psi, psi0, reL, imL, predsum2);                   // 14
    decode_kernel<<<N_B * TM1, 256>>>(phisum, predsum2, C_W, out);                  // 15
}

// round 16
// speedup vs baseline: 2.4880x; 1.0696x over previous
#include <cuda_runtime.h>
#include <cuda_fp16.h>
#include <cstdint>
#include <cstddef>

// ---------------- problem dims (fixed) ----------------
#define N_B    64
#define T_DIM  64
#define TM1    63
#define DX     16
#define DU     8
#define H_DIM  256
#define L_DIM  128
#define K_NETS 64
#define MX     (N_B * T_DIM)   // 4096
#define MU     (N_B * TM1)     // 4032
#define KP1    32
#define L1_MT  4               // m-tiles per L1 block

// ---------------- scratch (device globals) ----------------
__device__ __half g_xn[MX * KP1];
__device__ __half g_un[MU * KP1];
__device__ float g_b1ex[K_NETS * H_DIM];
__device__ float g_b1eu[K_NETS * H_DIM];
__device__ __half g_w1x[K_NETS * H_DIM * KP1];
__device__ __half g_w1u[K_NETS * H_DIM * KP1];
__device__ __half g_h1[(size_t)K_NETS * MX * H_DIM];
__device__ __half g_h2[(size_t)K_NETS * MX * H_DIM];
__device__ __half g_w2xt[(size_t)K_NETS * H_DIM * H_DIM];   // [net][n][d] fp16
__device__ __half g_w3xt[(size_t)K_NETS * L_DIM * H_DIM];   // [net][n][d], scale folded
__device__ __half g_w2ut[(size_t)K_NETS * H_DIM * H_DIM];
__device__ __half g_w3ut[(size_t)K_NETS * L_DIM * H_DIM];
__device__ __half g_phi_h[(size_t)MX * K_NETS * L_DIM];     // fp16 [m][net][L]
__device__ __half g_psi_h[(size_t)MU * K_NETS * L_DIM];     // fp16 [bt][net][L]
__device__ float g_psi0[K_NETS * L_DIM];
__device__ float g_phisum[MX * L_DIM];
__device__ float g_predsum2[2 * N_B * TM1 * L_DIM];

// ---------------- BN -> single fp16 plane, K padded to 32 ----------------
__global__ void bn_kernel(const float* __restrict__ x,
                          __half* __restrict__ A, int M, int D) {
    int d = blockIdx.x;
    int tid = threadIdx.x;
    if (d >= D) {
        for (int m = tid; m < M; m += 256)
            A[(size_t)m * KP1 + d] = __float2half(0.f);
        return;
    }
    __shared__ float r1[256], r2[256];
    float s = 0.f, s2 = 0.f;
    for (int m = tid; m < M; m += 256) {
        float v = x[(size_t)m * D + d];
        s += v; s2 += v * v;
    }
    r1[tid] = s; r2[tid] = s2;
    __syncthreads();
    for (int o = 128; o > 0; o >>= 1) {
        if (tid < o) { r1[tid] += r1[tid + o]; r2[tid] += r2[tid + o]; }
        __syncthreads();
    }
    float mu = r1[0] / M;
    float var = r2[0] / M - mu * mu;
    float rstd = rsqrtf(var + 1e-5f);
    for (int m = tid; m < M; m += 256)
        A[(size_t)m * KP1 + d] = __float2half((x[(size_t)m * D + d] - mu) * rstd);
}

// ---------------- fold BN affine into layer-1, transpose, fp16 ----------------
__global__ void prep_w1_kernel(const float* __restrict__ g, const float* __restrict__ be,
                               const float* __restrict__ W1, const float* __restrict__ b1,
                               __half* __restrict__ T, float* __restrict__ beff, int D) {
    int k = blockIdx.x;
    int h = threadIdx.x;
    float bacc = b1[k * H_DIM + h];
    for (int d = 0; d < KP1; d++) {
        float v = 0.f;
        if (d < D) {
            float w = W1[((size_t)k * D + d) * H_DIM + h];
            v = g[k * D + d] * w;
            bacc += be[k * D + d] * w;
        }
        T[((size_t)k * H_DIM + h) * KP1 + d] = __float2half(v);
    }
    beff[k * H_DIM + h] = bacc;
}

// ---------------- W2 + W3 transpose (fp16); W3 scale folded ----------------
__global__ void transpose_split2_kernel(const float* __restrict__ W2,
                                        __half* __restrict__ T2,
                                        const float* __restrict__ W3,
                                        __half* __restrict__ T3,
                                        const float* __restrict__ scale3) {
    __shared__ float tile[32][33];
    int k = blockIdx.y;
    int idx = blockIdx.x;
    if (idx < 64) {
        const float* W = W2 + (size_t)k * H_DIM * H_DIM;
        int kk0 = (idx >> 3) * 32, n0 = (idx & 7) * 32;
        for (int r = threadIdx.y; r < 32; r += 8)
            tile[r][threadIdx.x] = W[(size_t)(kk0 + r) * H_DIM + n0 + threadIdx.x];
        __syncthreads();
        for (int r = threadIdx.y; r < 32; r += 8) {
            int n = n0 + r, kk = kk0 + threadIdx.x;
            T2[((size_t)k * H_DIM + n) * H_DIM + kk] = __float2half(tile[threadIdx.x][r]);
        }
    } else {
        idx -= 64;
        const float* W = W3 + (size_t)k * H_DIM * L_DIM;
        int kk0 = (idx >> 2) * 32, n0 = (idx & 3) * 32;
        for (int r = threadIdx.y; r < 32; r += 8)
            tile[r][threadIdx.x] = W[(size_t)(kk0 + r) * L_DIM + n0 + threadIdx.x];
        __syncthreads();
        for (int r = threadIdx.y; r < 32; r += 8) {
            int n = n0 + r, kk = kk0 + threadIdx.x;
            float v = tile[threadIdx.x][r] * scale3[k * L_DIM + n];
            T3[((size_t)k * L_DIM + n) * H_DIM + kk] = __float2half(v);
        }
    }
}

// ================= common GEMM helpers =================
__device__ __forceinline__ void cp16(void* dst, const void* src, bool pred) {
    uint32_t d = (uint32_t)__cvta_generic_to_shared(dst);
    int n = pred ? 16 : 0;
    asm volatile("cp.async.cg.shared.global [%0], [%1], 16, %2;" :: "r"(d), "l"(src), "r"(n));
}
#define CP_COMMIT() asm volatile("cp.async.commit_group;")
#define CP_WAIT(N)  asm volatile("cp.async.wait_group %0;" :: "n"(N))

__device__ __forceinline__ void ldsm_x4(uint32_t* r, const void* p) {
    uint32_t a = (uint32_t)__cvta_generic_to_shared(p);
    asm volatile("ldmatrix.sync.aligned.m8n8.x4.shared.b16 {%0,%1,%2,%3}, [%4];"
                 : "=r"(r[0]), "=r"(r[1]), "=r"(r[2]), "=r"(r[3]) : "r"(a));
}
#define MMA16816(d, a, b0, b1) \
    asm volatile("mma.sync.aligned.m16n8k16.row.col.f32.f16.f16.f32 " \
                 "{%0,%1,%2,%3},{%4,%5,%6,%7},{%8,%9},{%0,%1,%2,%3};" \
                 : "+f"((d)[0]), "+f"((d)[1]), "+f"((d)[2]), "+f"((d)[3]) \
                 : "r"((a)[0]), "r"((a)[1]), "r"((a)[2]), "r"((a)[3]), \
                   "r"(b0), "r"(b1))

// ================= L1 kernel: plain fp16, B-resident, 4 m-tiles per block =================
#define L1_STR 40
#define L1_PLH (128 * L1_STR)
// planes: [0]=B, [1]=A stage0, [2]=A stage1
#define SMEM_L1 (3 * L1_PLH * 2)  // 30720

__global__ void __launch_bounds__(256, 2)
hmma_l1_kernel(const __half* __restrict__ A,
               const __half* __restrict__ B,
               const float* __restrict__ bias,
               __half* __restrict__ Ch, size_t strideC, int Mrows) {
    extern __shared__ char smem[];
    auto plane = [&](int p) -> __half* {
        return reinterpret_cast<__half*>(smem) + p * L1_PLH;
    };
    int tid = threadIdx.x;
    int lane = tid & 31, wid = tid >> 5;
    int wm = wid >> 1, wn = wid & 1;
    int z = blockIdx.z;
    int n0 = blockIdx.y * 128;
    int mg = blockIdx.x;

    const __half* Bb = B + ((size_t)z * H_DIM + n0) * KP1;

    int rowL = tid >> 1;
    int kkL = (tid & 1) * 16;
    int soff = rowL * L1_STR + kkL;

    cp16(plane(0) + soff,     Bb + (size_t)rowL * KP1 + kkL, true);
    cp16(plane(0) + soff + 8, Bb + (size_t)rowL * KP1 + kkL + 8, true);
    CP_COMMIT();

    auto load_A = [&](int s, int mt) {
        int gm = (mg * L1_MT + mt) * 128 + rowL;
        bool aOk = gm < Mrows;
        const __half* pa = A + (size_t)gm * KP1 + kkL;
        cp16(plane(1 + s) + soff,     pa,     aOk);
        cp16(plane(1 + s) + soff + 8, pa + 8, aOk);
        CP_COMMIT();
    };
    load_A(0, 0);

    int aRow = wm * 32 + (lane & 15);
    int aCol = (lane >> 4) * 8;
    int bRow = wn * 64 + (lane >> 4) * 8 + (lane & 7);
    int bCol = ((lane >> 3) & 1) * 8;
    int g = lane >> 2, t = lane & 3;

    for (int mt = 0; mt < L1_MT; mt++) {
        int s = mt & 1;
        if (mt + 1 < L1_MT) {
            load_A(s ^ 1, mt + 1);
            CP_WAIT(1);
        } else {
            CP_WAIT(0);
        }
        __syncthreads();

        float acc[2][8][4];
#pragma unroll
        for (int mi = 0; mi < 2; mi++)
#pragma unroll
            for (int ni = 0; ni < 8; ni++)
#pragma unroll
                for (int i = 0; i < 4; i++) acc[mi][ni][i] = 0.f;

        const __half* pA = plane(1 + s);
        const __half* pB = plane(0);

#pragma unroll
        for (int ks = 0; ks < 2; ks++) {
            uint32_t ah[2][4];
#pragma unroll
            for (int mi = 0; mi < 2; mi++)
                ldsm_x4(ah[mi], pA + (aRow + mi * 16) * L1_STR + ks * 16 + aCol);
#pragma unroll
            for (int q = 0; q < 4; q++) {
                uint32_t rh[4];
                ldsm_x4(rh, pB + (bRow + q * 16) * L1_STR + ks * 16 + bCol);
#pragma unroll
                for (int p = 0; p < 2; p++) {
                    int ni = 2 * q + p;
#pragma unroll
                    for (int mi = 0; mi < 2; mi++)
                        MMA16816(acc[mi][ni], ah[mi], rh[2 * p], rh[2 * p + 1]);
                }
            }
        }

        int mbase = (mg * L1_MT + mt) * 128;
#pragma unroll
        for (int mi = 0; mi < 2; mi++) {
#pragma unroll
            for (int ni = 0; ni < 8; ni++) {
                int col = n0 + wn * 64 + ni * 8 + 2 * t;
                float b0 = bias[(size_t)z * H_DIM + col];
                float b1v = bias[(size_t)z * H_DIM + col + 1];
#pragma unroll
                for (int h = 0; h < 2; h++) {
                    int row = mbase + wm * 32 + mi * 16 + g + h * 8;
                    if (row >= Mrows) continue;
                    float v0 = acc[mi][ni][2 * h] + b0;
                    float v1 = acc[mi][ni][2 * h + 1] + b1v;
                    v0 = v0 > 0.f ? v0 : 0.01f * v0;
                    v1 = v1 > 0.f ? v1 : 0.01f * v1;
                    size_t o = strideC * z + (size_t)row * H_DIM + col;
                    *reinterpret_cast<__half2*>(&Ch[o]) = __floats2half2_rn(v0, v1);
                }
            }
        }
        __syncthreads();
    }
}

// ================= BK=64 streaming kernel, single-plane A and B =================
template <int BK>
__global__ void __launch_bounds__(256, 2)
hmma_gemm_kernel(const __half* __restrict__ A, size_t strideA, int lda, int KdPad,
                 const __half* __restrict__ B, size_t strideB, int ldb,
                 const float* __restrict__ bias,
                 float* __restrict__ Cf, __half* __restrict__ Ch, size_t strideC,
                 int Mrows, int Nfull, int leaky, int tposeF) {
    extern __shared__ char smem[];
    constexpr int STR = BK + 8;
    constexpr int PLANE_H = 128 * STR;

    int tid = threadIdx.x;
    int lane = tid & 31, wid = tid >> 5;
    int wm = wid >> 1, wn = wid & 1;
    int z = blockIdx.z;
    int m0 = blockIdx.x * 128, n0 = blockIdx.y * 128;

    const __half* Ab = A + strideA * z;
    const __half* Bb = B + strideB * z + (size_t)n0 * ldb;

    auto plane = [&](int p, int s) -> __half* {
        return reinterpret_cast<__half*>(smem) + (p * 2 + s) * PLANE_H;
    };

    int rowL = tid >> 1;
    int kkL = (tid & 1) * 16;
    bool aOk = (m0 + rowL) < Mrows;
    const __half* gA = Ab + (size_t)(m0 + rowL) * lda + kkL;
    const __half* gB = Bb + (size_t)rowL * ldb + kkL;
    int soff = rowL * STR + kkL;

    int nk = KdPad / BK;

    auto load_stage = [&](int s, int c) {
#pragma unroll
        for (int seg = 0; seg < BK / 32; seg++) {
            int k0 = c * BK + seg * 32;
            int so = soff + seg * 32;
            cp16(plane(0, s) + so,     gA + k0,     aOk);
            cp16(plane(0, s) + so + 8, gA + k0 + 8, aOk);
            cp16(plane(1, s) + so,     gB + k0,     true);
            cp16(plane(1, s) + so + 8, gB + k0 + 8, true);
        }
        CP_COMMIT();
    };

    float acc[2][8][4];
#pragma unroll
    for (int mi = 0; mi < 2; mi++)
#pragma unroll
        for (int ni = 0; ni < 8; ni++)
#pragma unroll
            for (int i = 0; i < 4; i++) acc[mi][ni][i] = 0.f;

    int aRow = wm * 32 + (lane & 15);
    int aCol = (lane >> 4) * 8;
    int bRow = wn * 64 + (lane >> 4) * 8 + (lane & 7);
    int bCol = ((lane >> 3) & 1) * 8;
    int g = lane >> 2, t = lane & 3;

    load_stage(0, 0);

    for (int c = 0; c < nk; c++) {
        int s = c & 1;
        if (c + 1 < nk) {
            load_stage(s ^ 1, c + 1);
            CP_WAIT(1);
        } else {
            CP_WAIT(0);
        }
        __syncthreads();

        const __half* pA = plane(0, s);
        const __half* pB = plane(1, s);

#pragma unroll
        for (int ks = 0; ks < BK / 16; ks++) {
            uint32_t ah[2][4];
#pragma unroll
            for (int mi = 0; mi < 2; mi++)
                ldsm_x4(ah[mi], pA + (aRow + mi * 16) * STR + ks * 16 + aCol);
#pragma unroll
            for (int q = 0; q < 4; q++) {
                uint32_t rh[4];
                ldsm_x4(rh, pB + (bRow + q * 16) * STR + ks * 16 + bCol);
#pragma unroll
                for (int p = 0; p < 2; p++) {
                    int ni = 2 * q + p;
#pragma unroll
                    for (int mi = 0; mi < 2; mi++)
                        MMA16816(acc[mi][ni], ah[mi], rh[2 * p], rh[2 * p + 1]);
                }
            }
        }
        __syncthreads();
    }

    // ---- epilogue ----
#pragma unroll
    for (int mi = 0; mi < 2; mi++) {
#pragma unroll
        for (int ni = 0; ni < 8; ni++) {
            int col = n0 + wn * 64 + ni * 8 + 2 * t;
            float b0 = 0.f, b1v = 0.f;
            if (bias) {
                b0 = bias[(size_t)z * Nfull + col];
                b1v = bias[(size_t)z * Nfull + col + 1];
            }
#pragma unroll
            for (int h = 0; h < 2; h++) {
                int row = m0 + wm * 32 + mi * 16 + g + h * 8;
                if (row >= Mrows) continue;
                float v0 = acc[mi][ni][2 * h] + b0;
                float v1 = acc[mi][ni][2 * h + 1] + b1v;
                if (leaky) {
                    v0 = v0 > 0.f ? v0 : 0.01f * v0;
                    v1 = v1 > 0.f ? v1 : 0.01f * v1;
                }
                size_t o = tposeF
                    ? ((size_t)row * K_NETS + z) * Nfull + col
                    : strideC * z + (size_t)row * Nfull + col;
                if (Cf) {
                    *reinterpret_cast<float2*>(&Cf[o]) = make_float2(v0, v1);
                } else {
                    *reinterpret_cast<__half2*>(&Ch[o]) = __floats2half2_rn(v0, v1);
                }
            }
        }
    }
}

#define SMEM_F (2 * 2 * 128 * (64 + 8) * 2)   // BK=64, 2 planes x 2 stages: 73728

// ---------------- sum over net axis (phi fp16) ----------------
__global__ void sum_nets_kernel(const __half2* __restrict__ phi2, float* __restrict__ out) {
    int m = blockIdx.x;
    int t = threadIdx.x;   // 64 half2 lanes
    const __half2* base = phi2 + (size_t)m * K_NETS * 64 + t;
    float sx = 0.f, sy = 0.f;
#pragma unroll 8
    for (int j = 0; j < K_NETS; j++) {
        float2 v = __half22float2(base[j * 64]);
        sx += v.x; sy += v.y;
    }
    *reinterpret_cast<float2*>(&out[(size_t)m * L_DIM + 2 * t]) = make_float2(sx, sy);
}

// ---------------- psi(0): mirrors the GEMM numerics ----------------
__global__ void psi0_kernel(const float* __restrict__ b1eff,
                            const __half* __restrict__ w2t,
                            const float* __restrict__ b2,
                            const __half* __restrict__ w3t,
                            float* __restrict__ psi0) {
    int k = blockIdx.x;
    int t = threadIdx.x;
    __shared__ float h1[H_DIM], h2[H_DIM];
    float v = b1eff[k * H_DIM + t];
    v = v > 0.f ? v : 0.01f * v;
    h1[t] = __half2float(__float2half(v));
    __syncthreads();
    float a = b2[k * H_DIM + t];
    const __half* w2row = w2t + ((size_t)k * H_DIM + t) * H_DIM;
    for (int d = 0; d < H_DIM; d++)
        a += h1[d] * __half2float(w2row[d]);
    a = a > 0.f ? a : 0.01f * a;
    h2[t] = __half2float(__float2half(a));
    __syncthreads();
    if (t < L_DIM) {
        float s = 0.f;
        const __half* w3row = w3t + ((size_t)k * L_DIM + t) * H_DIM;
        for (int d = 0; d < H_DIM; d++)
            s += h2[d] * __half2float(w3row[d]);
        psi0[k * L_DIM + t] = s;
    }
}

// ---------------- scan: 2 blocks per batch; phi fp16, psi fp16 ----------------
__global__ void __launch_bounds__(256)
scan_kernel(const __half2* __restrict__ phi2,
            const __half2* __restrict__ psi2,
            const float* __restrict__ psi0,
            const float* __restrict__ reL, const float* __restrict__ imL,
            float* __restrict__ predsum2) {
    int bid = blockIdx.x;
    int b = bid >> 1;
    int sel = bid & 1;
    int j0 = sel * 32;
    int tid = threadIdx.x;
    __shared__ float ps[32 * L_DIM];
    __shared__ float rsh[K_NETS], ish[K_NETS];
    if (tid < K_NETS) { rsh[tid] = reL[tid]; ish[tid] = imL[tid]; }

    float px[8], py[8], rj[8], ij[8], u0x[8], u0y[8];
    const __half2* phiB = phi2 + ((size_t)(b * T_DIM) * K_NETS + j0) * 64;
    const float* psi0B = psi0 + (size_t)j0 * L_DIM;
#pragma unroll
    for (int q = 0; q < 8; q++) {
        int e = q * 256 + tid;
        float2 v = __half22float2(phiB[e]);
        px[q] = v.x; py[q] = v.y;
        float2 zz = *reinterpret_cast<const float2*>(&psi0B[e * 2]);
        u0x[q] = zz.x; u0y[q] = zz.y;
    }
    __syncthreads();
#pragma unroll
    for (int q = 0; q < 8; q++) {
        int j = j0 + ((q * 256 + tid) >> 6);
        rj[q] = rsh[j]; ij[q] = ish[j];
    }

    for (int t = 0; t < TM1; t++) {
        const __half2* psiT = psi2 + ((size_t)(b * TM1 + t) * K_NETS + j0) * 64;
#pragma unroll
        for (int q = 0; q < 8; q++) {
            int e = q * 256 + tid;
            float2 u = __half22float2(psiT[e]);
            float vx = px[q] + u.x - u0x[q];
            float vy = py[q] + u.y - u0y[q];
            px[q] = vx * rj[q] - vy * ij[q];
            py[q] = vx * ij[q] + vy * rj[q];
            ps[e * 2]     = px[q];
            ps[e * 2 + 1] = py[q];
        }
        __syncthreads();
        if (tid < L_DIM) {
            float s = 0.f;
#pragma unroll 8
            for (int j = 0; j < 32; j++) s += ps[j * L_DIM + tid];
            predsum2[(((size_t)sel * N_B + b) * TM1 + t) * L_DIM + tid] = s;
        }
        __syncthreads();
    }
}

// ---------------- decode ----------------
__global__ void decode_kernel(const float* __restrict__ phisum,
                              const float* __restrict__ predsum2,
                              const float* __restrict__ C_W,
                              float* __restrict__ out) {
    __shared__ float Cs[DX * L_DIM];
    __shared__ float rowY[L_DIM], rowP[L_DIM];
    int bt = blockIdx.x;
    int b = bt / TM1, t = bt % TM1;
    int tid = threadIdx.x;
    for (int i = tid; i < DX * L_DIM; i += 256) Cs[i] = C_W[i];
    if (tid < L_DIM)
        rowY[tid] = phisum[((size_t)(b * T_DIM + t + 1)) * L_DIM + tid];
    else {
        int l = tid - L_DIM;
        rowP[l] = predsum2[(size_t)bt * L_DIM + l]
                + predsum2[((size_t)N_B * TM1 + bt) * L_DIM + l];
    }
    __syncthreads();
    if (tid < 2 * DX) {
        int sel = tid >> 4, d = tid & 15;
        const float* row = sel ? rowP : rowY;
        float s = 0.f;
        for (int l = 0; l < L_DIM; l++) s += row[l] * Cs[d * L_DIM + l];
        out[(size_t)sel * N_B * TM1 * DX + (size_t)bt * DX + d] = s;
    }
}

// ---------------- launcher ----------------
extern "C" void kernel_launch(void* const* d_in, const int* in_sizes, int n_in,
                              void* d_out, int out_size) {
    const float* xs      = (const float*)d_in[0];
    const float* us      = (const float*)d_in[1];
    const float* x_gamma = (const float*)d_in[2];
    const float* x_beta  = (const float*)d_in[3];
    const float* xW1     = (const float*)d_in[4];
    const float* xb1     = (const float*)d_in[5];
    const float* xW2     = (const float*)d_in[6];
    const float* xb2     = (const float*)d_in[7];
    const float* xW3     = (const float*)d_in[8];
    const float* x_scale = (const float*)d_in[9];
    const float* u_gamma = (const float*)d_in[10];
    const float* u_beta  = (const float*)d_in[11];
    const float* uW1     = (const float*)d_in[12];
    const float* ub1     = (const float*)d_in[13];
    const float* uW2     = (const float*)d_in[14];
    const float* ub2     = (const float*)d_in[15];
    const float* uW3     = (const float*)d_in[16];
    const float* u_scale = (const float*)d_in[17];
    const float* reL     = (const float*)d_in[18];
    const float* imL     = (const float*)d_in[19];
    const float* C_W     = (const float*)d_in[20];
    float* out = (float*)d_out;

    float *b1ex, *b1eu, *psi0, *phisum, *predsum2;
    __half *xn, *un, *w1x, *w1u, *h1, *h2, *phi_h, *psi_h;
    __half *w2x, *w3x, *w2u, *w3u;
    cudaGetSymbolAddress((void**)&xn, g_xn);
    cudaGetSymbolAddress((void**)&un, g_un);
    cudaGetSymbolAddress((void**)&b1ex, g_b1ex);
    cudaGetSymbolAddress((void**)&b1eu, g_b1eu);
    cudaGetSymbolAddress((void**)&w1x, g_w1x);
    cudaGetSymbolAddress((void**)&w1u, g_w1u);
    cudaGetSymbolAddress((void**)&h1, g_h1);
    cudaGetSymbolAddress((void**)&h2, g_h2);
    cudaGetSymbolAddress((void**)&phi_h, g_phi_h);
    cudaGetSymbolAddress((void**)&psi_h, g_psi_h);
    cudaGetSymbolAddress((void**)&w2x, g_w2xt);
    cudaGetSymbolAddress((void**)&w3x, g_w3xt);
    cudaGetSymbolAddress((void**)&w2u, g_w2ut);
    cudaGetSymbolAddress((void**)&w3u, g_w3ut);
    cudaGetSymbolAddress((void**)&psi0, g_psi0);
    cudaGetSymbolAddress((void**)&phisum, g_phisum);
    cudaGetSymbolAddress((void**)&predsum2, g_predsum2);

    cudaFuncSetAttribute((const void*)hmma_l1_kernel,
                         cudaFuncAttributeMaxDynamicSharedMemorySize, SMEM_L1);
    cudaFuncSetAttribute((const void*)hmma_gemm_kernel<64>,
                         cudaFuncAttributeMaxDynamicSharedMemorySize, SMEM_F);

    dim3 tb(32, 8);
    // ---- x path ----
    bn_kernel<<<KP1, 256>>>(xs, xn, MX, DX);                                        // 0
    prep_w1_kernel<<<K_NETS, H_DIM>>>(x_gamma, x_beta, xW1, xb1, w1x, b1ex, DX);    // 1
    transpose_split2_kernel<<<dim3(96, K_NETS), tb>>>(xW2, w2x, xW3, w3x, x_scale); // 2
    hmma_l1_kernel<<<dim3(MX / 128 / L1_MT, 2, K_NETS), 256, SMEM_L1>>>(
        xn, w1x, b1ex, h1, (size_t)MX * H_DIM, MX);                                 // 3: L1x
    bn_kernel<<<KP1, 256>>>(us, un, MU, DU);                                        // 4
    hmma_gemm_kernel<64><<<dim3(MX / 128, 2, K_NETS), 256, SMEM_F>>>(
        h1, (size_t)MX * H_DIM, H_DIM, H_DIM,
        w2x, (size_t)H_DIM * H_DIM, H_DIM,
        xb2, nullptr, h2, (size_t)MX * H_DIM, MX, H_DIM, 1, 0);                     // 5: L2x
    hmma_gemm_kernel<64><<<dim3(MX / 128, 1, K_NETS), 256, SMEM_F>>>(
        h2, (size_t)MX * H_DIM, H_DIM, H_DIM,
        w3x, (size_t)L_DIM * H_DIM, H_DIM,
        nullptr, nullptr, phi_h, 0, MX, L_DIM, 0, 1);                               // 6: L3x -> fp16 [m][net][L]
    sum_nets_kernel<<<MX, 64>>>(reinterpret_cast<const __half2*>(phi_h), phisum);   // 7

    // ---- u path ----
    prep_w1_kernel<<<K_NETS, H_DIM>>>(u_gamma, u_beta, uW1, ub1, w1u, b1eu, DU);    // 8
    transpose_split2_kernel<<<dim3(96, K_NETS), tb>>>(uW2, w2u, uW3, w3u, u_scale); // 9
    hmma_l1_kernel<<<dim3(8, 2, K_NETS), 256, SMEM_L1>>>(
        un, w1u, b1eu, h1, (size_t)MU * H_DIM, MU);                                 // 10: L1u
    hmma_gemm_kernel<64><<<dim3(32, 2, K_NETS), 256, SMEM_F>>>(
        h1, (size_t)MU * H_DIM, H_DIM, H_DIM,
        w2u, (size_t)H_DIM * H_DIM, H_DIM,
        ub2, nullptr, h2, (size_t)MU * H_DIM, MU, H_DIM, 1, 0);                     // 11: L2u
    hmma_gemm_kernel<64><<<dim3(32, 1, K_NETS), 256, SMEM_F>>>(
        h2, (size_t)MU * H_DIM, H_DIM, H_DIM,
        w3u, (size_t)L_DIM * H_DIM, H_DIM,
        nullptr, nullptr, psi_h, 0, MU, L_DIM, 0, 1);                               // 12: psi fp16 [bt][net][L]

    psi0_kernel<<<K_NETS, H_DIM>>>(b1eu, w2u, ub2, w3u, psi0);                      // 13
    scan_kernel<<<2 * N_B, 256>>>(reinterpret_cast<const __half2*>(phi_h),
                                  reinterpret_cast<const __half2*>(psi_h),
                                  psi0, reL, imL, predsum2);                        // 14
    decode_kernel<<<N_B * TM1, 256>>>(phisum, predsum2, C_W, out);                  // 15
}